// round 2
// baseline (speedup 1.0000x reference)
#include <cuda_runtime.h>
#include <math.h>

// Problem constants
#define BATCH 8
#define NCH   384
#define HH    56
#define WW    56
#define HWSZ  3136      // 56*56
#define NKV   784       // 28*28
#define HK    28
#define NG    4
#define GC    96
#define NH    8
#define HC    48

#define YSZ   (BATCH*NCH*HWSZ)     // 9633792
#define PSZ   (BATCH*NG*NKV*2)     // 50176

typedef unsigned long long ull;

// packed fp32x2 helpers (Blackwell FFMA2 path — ptxas won't auto-fuse)
#define FMA2(acc, a, b) asm("fma.rn.f32x2 %0, %1, %2, %0;" : "+l"(acc) : "l"(a), "l"(b))
#define PACK2(out, v)   asm("mov.b64 %0, {%1, %1};" : "=l"(out) : "r"(__float_as_uint(v)))
#define UNPACK2(lo, hi, in) asm("mov.b64 {%0, %1}, %2;" : "=r"(lo), "=r"(hi) : "l"(in))

// Scratch (allocation-free rule: __device__ globals)
static __device__ float g_q  [BATCH*NCH*HWSZ];
static __device__ float g_xs [BATCH*NCH*NKV];
static __device__ float g_k  [BATCH*NCH*NKV];
static __device__ float g_v  [BATCH*NCH*NKV];
static __device__ float g_att[BATCH*NCH*HWSZ];
static __device__ float g_pos[BATCH*NG*NKV*2];

// ---------------------------------------------------------------------------
// Batched GEMM with bias: C[z] = A(MxK) * B[z](KxN) + bias
// 128x128x16 tile, 256 threads, 8x8 microtile, f32x2 packed FMA (pairs over m).
// Requires M % 128 == 0, K % 16 == 0; N guarded (must be % 8 for epilogue).
// ---------------------------------------------------------------------------
__global__ __launch_bounds__(256, 2)
void gemm_bias(const float* __restrict__ A, const float* __restrict__ Bsrc,
               const float* __restrict__ bias, float* __restrict__ C,
               int M, int K, int N)
{
    __shared__ float As[16][128];
    __shared__ float Bs[16][128];
    const float* Bp = Bsrc + (size_t)blockIdx.z * K * N;
    float*       Cp = C    + (size_t)blockIdx.z * M * N;
    int m0 = blockIdx.y * 128, n0 = blockIdx.x * 128;
    int tid = threadIdx.x;

    // loader mappings
    int am = tid >> 1;            // 0..127
    int ak = (tid & 1) * 8;       // 0 or 8
    int bk = tid >> 5;            // 0..7 (rows bk, bk+8)
    int bn = (tid & 31) * 4;      // 0..124

    // compute mapping: 8 rows (as 4 m-pairs) x 8 cols
    int tm8 = (tid >> 4) * 8;     // 0..120
    int tn8 = (tid & 15) * 8;     // 0..120

    ull acc[4][8];
#pragma unroll
    for (int i = 0; i < 4; i++)
#pragma unroll
        for (int j = 0; j < 8; j++) acc[i][j] = 0ull;

    for (int k0 = 0; k0 < K; k0 += 16) {
        // load A tile (transpose into As[k][m])
        float4 a0 = *reinterpret_cast<const float4*>(&A[(size_t)(m0 + am) * K + k0 + ak]);
        float4 a1 = *reinterpret_cast<const float4*>(&A[(size_t)(m0 + am) * K + k0 + ak + 4]);
        As[ak + 0][am] = a0.x; As[ak + 1][am] = a0.y;
        As[ak + 2][am] = a0.z; As[ak + 3][am] = a0.w;
        As[ak + 4][am] = a1.x; As[ak + 5][am] = a1.y;
        As[ak + 6][am] = a1.z; As[ak + 7][am] = a1.w;
        // load B tile
#pragma unroll
        for (int i = 0; i < 2; i++) {
            int kk = bk + i * 8;
            float4 bv = make_float4(0.f, 0.f, 0.f, 0.f);
            if (n0 + bn < N)
                bv = *reinterpret_cast<const float4*>(&Bp[(size_t)(k0 + kk) * N + n0 + bn]);
            *reinterpret_cast<float4*>(&Bs[kk][bn]) = bv;
        }
        __syncthreads();
#pragma unroll
        for (int k = 0; k < 16; k++) {
            const ull* ap = reinterpret_cast<const ull*>(&As[k][tm8]);
            ull a[4];
            a[0] = ap[0]; a[1] = ap[1]; a[2] = ap[2]; a[3] = ap[3];
            float4 b0 = *reinterpret_cast<const float4*>(&Bs[k][tn8]);
            float4 b1 = *reinterpret_cast<const float4*>(&Bs[k][tn8 + 4]);
            ull br[8];
            PACK2(br[0], b0.x); PACK2(br[1], b0.y); PACK2(br[2], b0.z); PACK2(br[3], b0.w);
            PACK2(br[4], b1.x); PACK2(br[5], b1.y); PACK2(br[6], b1.z); PACK2(br[7], b1.w);
#pragma unroll
            for (int i = 0; i < 4; i++)
#pragma unroll
                for (int j = 0; j < 8; j++)
                    FMA2(acc[i][j], a[i], br[j]);
        }
        __syncthreads();
    }

    // epilogue: each m-pair -> two rows
    if (n0 + tn8 < N) {
#pragma unroll
        for (int i = 0; i < 4; i++) {
            int mlo = m0 + tm8 + 2 * i;
            float blo = bias[mlo], bhi = bias[mlo + 1];
            float rlo[8], rhi[8];
#pragma unroll
            for (int j = 0; j < 8; j++) {
                unsigned lo, hi;
                UNPACK2(lo, hi, acc[i][j]);
                rlo[j] = __uint_as_float(lo) + blo;
                rhi[j] = __uint_as_float(hi) + bhi;
            }
            *reinterpret_cast<float4*>(&Cp[(size_t)mlo * N + n0 + tn8]) =
                make_float4(rlo[0], rlo[1], rlo[2], rlo[3]);
            *reinterpret_cast<float4*>(&Cp[(size_t)mlo * N + n0 + tn8 + 4]) =
                make_float4(rlo[4], rlo[5], rlo[6], rlo[7]);
            *reinterpret_cast<float4*>(&Cp[(size_t)(mlo + 1) * N + n0 + tn8]) =
                make_float4(rhi[0], rhi[1], rhi[2], rhi[3]);
            *reinterpret_cast<float4*>(&Cp[(size_t)(mlo + 1) * N + n0 + tn8 + 4]) =
                make_float4(rhi[4], rhi[5], rhi[6], rhi[7]);
        }
    }
}

// ---------------------------------------------------------------------------
// Offset network (unchanged from R1)
// ---------------------------------------------------------------------------
__global__ __launch_bounds__(128)
void offset_net(const float* __restrict__ q,
                const float* __restrict__ dw_w, const float* __restrict__ dw_b,
                const float* __restrict__ ln_g, const float* __restrict__ ln_b,
                const float* __restrict__ pw_w,
                float* __restrict__ pos, float* __restrict__ pos_out,
                float* __restrict__ ref_out)
{
    int blk = blockIdx.x;
    int bg = blk / NKV;
    int ij = blk - bg * NKV;
    int i = ij / HK, j = ij - i * HK;
    int b = bg >> 2, g = bg & 3;
    int c = threadIdx.x;

    __shared__ float red[128];

    float h = 0.f;
    if (c < GC) {
        const float* qc = q + ((size_t)(b * NCH + g * GC + c)) * HWSZ;
        const float* w = dw_w + c * 9;
        int y0 = 2 * i - 1, x0 = 2 * j - 1;
#pragma unroll
        for (int ky = 0; ky < 3; ky++) {
            int y = y0 + ky;
            if (y < 0 || y >= HH) continue;
#pragma unroll
            for (int kx = 0; kx < 3; kx++) {
                int x = x0 + kx;
                if (x < 0 || x >= WW) continue;
                h += w[ky * 3 + kx] * qc[y * WW + x];
            }
        }
        h += dw_b[c];
    }
    red[c] = (c < GC) ? h : 0.f; __syncthreads();
    for (int s = 64; s > 0; s >>= 1) { if (c < s) red[c] += red[c + s]; __syncthreads(); }
    float mu = red[0] * (1.f / GC); __syncthreads();
    float d = (c < GC) ? (h - mu) : 0.f;
    red[c] = d * d; __syncthreads();
    for (int s = 64; s > 0; s >>= 1) { if (c < s) red[c] += red[c + s]; __syncthreads(); }
    float var = red[0] * (1.f / GC); __syncthreads();

    float hn = 0.f;
    if (c < GC) {
        hn = d * rsqrtf(var + 1e-5f) * ln_g[c] + ln_b[c];
        hn = 0.5f * hn * (1.f + erff(hn * 0.70710678118654752f));
    }
    red[c] = (c < GC) ? pw_w[c] * hn : 0.f; __syncthreads();
    for (int s = 64; s > 0; s >>= 1) { if (c < s) red[c] += red[c + s]; __syncthreads(); }
    float offy = red[0]; __syncthreads();
    red[c] = (c < GC) ? pw_w[GC + c] * hn : 0.f; __syncthreads();
    for (int s = 64; s > 0; s >>= 1) { if (c < s) red[c] += red[c + s]; __syncthreads(); }
    float offx = red[0];

    if (c == 0) {
        float ry = (0.5f + (float)i) * (1.f / 27.f) * 2.f - 1.f;
        float rx = (0.5f + (float)j) * (1.f / 27.f) * 2.f - 1.f;
        float py = tanhf(offy) * (1.f / 27.f) + ry;
        float px = tanhf(offx) * (1.f / 27.f) + rx;
        size_t o = ((size_t)bg * NKV + ij) * 2;
        pos[o] = py;     pos[o + 1] = px;
        pos_out[o] = py; pos_out[o + 1] = px;
        ref_out[o] = ry; ref_out[o + 1] = rx;
    }
}

// ---------------------------------------------------------------------------
// Bilinear grid sample (unchanged from R1)
// ---------------------------------------------------------------------------
__global__ __launch_bounds__(256)
void grid_sample_k(const float* __restrict__ x, const float* __restrict__ pos,
                   float* __restrict__ xs)
{
    int bg = blockIdx.y;
    int b = bg >> 2, g = bg & 3;
    int idx = blockIdx.x * 256 + threadIdx.x;
    int c = idx / NKV, p = idx - c * NKV;

    float py = pos[((size_t)bg * NKV + p) * 2];
    float px = pos[((size_t)bg * NKV + p) * 2 + 1];
    float gx = (px + 1.f) * 0.5f * (WW - 1);
    float gy = (py + 1.f) * 0.5f * (HH - 1);
    float x0f = floorf(gx), y0f = floorf(gy);
    int x0 = (int)x0f, y0 = (int)y0f;
    float wx1 = gx - x0f, wx0 = 1.f - wx1;
    float wy1 = gy - y0f, wy0 = 1.f - wy1;

    const float* img = x + ((size_t)(b * NCH + g * GC + c)) * HWSZ;

    float v00 = 0.f, v01 = 0.f, v10 = 0.f, v11 = 0.f;
    bool xv0 = (x0 >= 0) && (x0 < WW);
    bool xv1 = (x0 + 1 >= 0) && (x0 + 1 < WW);
    bool yv0 = (y0 >= 0) && (y0 < HH);
    bool yv1 = (y0 + 1 >= 0) && (y0 + 1 < HH);
    if (xv0 && yv0) v00 = img[y0 * WW + x0];
    if (xv1 && yv0) v01 = img[y0 * WW + x0 + 1];
    if (xv0 && yv1) v10 = img[(y0 + 1) * WW + x0];
    if (xv1 && yv1) v11 = img[(y0 + 1) * WW + x0 + 1];

    float acc = v00 * wx0 * wy0 + v01 * wx1 * wy0 + v10 * wx0 * wy1 + v11 * wx1 * wy1;
    xs[((size_t)(b * NCH + g * GC + c)) * NKV + p] = acc;
}

// ---------------------------------------------------------------------------
// Attention v2: 32 queries per block, key tile 128, f32x2 packed math.
// logits kept in smem (stride 788); two-pass with softmax between.
// ---------------------------------------------------------------------------
#define TM 32
#define TNK 128
#define LSTR 788
#define ATT_SMEM ((TM*LSTR + HC*TM + HC*TNK) * 4)   // 131584 bytes

__global__ __launch_bounds__(256)
void attention_k(const float* __restrict__ q, const float* __restrict__ k,
                 const float* __restrict__ v, float* __restrict__ out)
{
    extern __shared__ float sm[];
    float* logits = sm;                  // TM * LSTR
    float* qs     = sm + TM * LSTR;      // HC * TM   (qs[c][m])
    float* kv     = qs + HC * TM;        // HC * TNK  (kv[c][n])

    int head = blockIdx.y;
    int b = head >> 3, hh = head & 7;
    const float* qp = q + ((size_t)(b * NCH + hh * HC)) * HWSZ;
    const float* kp = k + ((size_t)(b * NCH + hh * HC)) * NKV;
    const float* vp = v + ((size_t)(b * NCH + hh * HC)) * NKV;
    float*       op = out + ((size_t)(b * NCH + hh * HC)) * HWSZ;
    int m0 = blockIdx.x * TM;
    int tid = threadIdx.x;
    const float scale = 0.14433756729740643f;   // 1/sqrt(48)

    // load q tile (48 x 32) + zero logits tail columns [784..787]
    for (int idx = tid; idx < HC * TM; idx += 256) {
        int c = idx >> 5, mi = idx & 31;
        qs[c * TM + mi] = qp[(size_t)c * HWSZ + m0 + mi];
    }
    if (tid < 128) logits[(tid >> 2) * LSTR + NKV + (tid & 3)] = 0.f;
    __syncthreads();

    // ---- Pass 1: logits = scale * q^T k  (4q x 4k per thread, pairs over k)
    {
        int tq = (tid >> 5) * 4;        // 0..28 (warp-uniform)
        int tk = (tid & 31) * 4;        // 0..124
        for (int n0 = 0; n0 < NKV; n0 += TNK) {
            // load k tile (zero-padded)
            for (int idx = tid; idx < HC * TNK; idx += 256) {
                int c = idx >> 7, n = idx & 127;
                kv[c * TNK + n] = (n0 + n < NKV) ? kp[(size_t)c * NKV + n0 + n] : 0.f;
            }
            __syncthreads();
            ull acc[4][2];
#pragma unroll
            for (int i = 0; i < 4; i++) { acc[i][0] = 0ull; acc[i][1] = 0ull; }
#pragma unroll 4
            for (int c = 0; c < HC; c++) {
                float4 qv = *reinterpret_cast<const float4*>(&qs[c * TM + tq]);
                ull aq[4];
                PACK2(aq[0], qv.x); PACK2(aq[1], qv.y); PACK2(aq[2], qv.z); PACK2(aq[3], qv.w);
                const ull* kpair = reinterpret_cast<const ull*>(&kv[c * TNK + tk]);
                ull k0p = kpair[0], k1p = kpair[1];
#pragma unroll
                for (int i = 0; i < 4; i++) {
                    FMA2(acc[i][0], aq[i], k0p);
                    FMA2(acc[i][1], aq[i], k1p);
                }
            }
            if (n0 + tk < NKV) {
#pragma unroll
                for (int i = 0; i < 4; i++) {
                    unsigned l0, l1, l2, l3;
                    UNPACK2(l0, l1, acc[i][0]);
                    UNPACK2(l2, l3, acc[i][1]);
                    *reinterpret_cast<float4*>(&logits[(tq + i) * LSTR + n0 + tk]) =
                        make_float4(__uint_as_float(l0) * scale, __uint_as_float(l1) * scale,
                                    __uint_as_float(l2) * scale, __uint_as_float(l3) * scale);
                }
            }
            __syncthreads();
        }
    }

    // ---- Softmax per row (8 warps x 4 rows)
    {
        int warp = tid >> 5, lane = tid & 31;
        for (int mi = warp; mi < TM; mi += 8) {
            float* lr = &logits[mi * LSTR];
            float mx = -1e30f;
            for (int n = lane; n < NKV; n += 32) mx = fmaxf(mx, lr[n]);
#pragma unroll
            for (int o = 16; o > 0; o >>= 1) mx = fmaxf(mx, __shfl_xor_sync(0xffffffffu, mx, o));
            float sum = 0.f;
            for (int n = lane; n < NKV; n += 32) {
                float e = __expf(lr[n] - mx);
                lr[n] = e; sum += e;
            }
#pragma unroll
            for (int o = 16; o > 0; o >>= 1) sum += __shfl_xor_sync(0xffffffffu, sum, o);
            float inv = 1.f / sum;
            for (int n = lane; n < NKV; n += 32) lr[n] *= inv;
        }
    }
    __syncthreads();

    // ---- Pass 2: out[c][m] = sum_n p[m][n] v[c][n]  (3c x 2q, pairs over n)
    {
        int tc  = (tid >> 4) * 3;       // 0..45
        int tq2 = (tid & 15) * 2;       // 0..30
        ull acc[3][2];
#pragma unroll
        for (int i = 0; i < 3; i++) { acc[i][0] = 0ull; acc[i][1] = 0ull; }

        for (int n0 = 0; n0 < NKV; n0 += TNK) {
            // load v tile (zero-padded)
            for (int idx = tid; idx < HC * TNK; idx += 256) {
                int c = idx >> 7, n = idx & 127;
                kv[c * TNK + n] = (n0 + n < NKV) ? vp[(size_t)c * NKV + n0 + n] : 0.f;
            }
            __syncthreads();
            int lim = min(TNK, LSTR - n0);    // stay inside logits row (incl. zero tail)
#pragma unroll 4
            for (int n = 0; n < lim; n += 4) {
                const ull* p0 = reinterpret_cast<const ull*>(&logits[tq2 * LSTR + n0 + n]);
                const ull* p1 = reinterpret_cast<const ull*>(&logits[(tq2 + 1) * LSTR + n0 + n]);
                ull p0a = p0[0], p0b = p0[1];
                ull p1a = p1[0], p1b = p1[1];
#pragma unroll
                for (int i = 0; i < 3; i++) {
                    const ull* vr = reinterpret_cast<const ull*>(&kv[(tc + i) * TNK + n]);
                    ull va = vr[0], vb = vr[1];
                    FMA2(acc[i][0], va, p0a);
                    FMA2(acc[i][0], vb, p0b);
                    FMA2(acc[i][1], va, p1a);
                    FMA2(acc[i][1], vb, p1b);
                }
            }
            __syncthreads();
        }
#pragma unroll
        for (int i = 0; i < 3; i++) {
#pragma unroll
            for (int qi = 0; qi < 2; qi++) {
                unsigned lo, hi;
                UNPACK2(lo, hi, acc[i][qi]);
                op[(size_t)(tc + i) * HWSZ + m0 + tq2 + qi] =
                    __uint_as_float(lo) + __uint_as_float(hi);
            }
        }
    }
}

// ---------------------------------------------------------------------------
extern "C" void kernel_launch(void* const* d_in, const int* in_sizes, int n_in,
                              void* d_out, int out_size)
{
    const float* x   = (const float*)d_in[0];
    const float* Wq  = (const float*)d_in[1];
    const float* bq  = (const float*)d_in[2];
    const float* Wk  = (const float*)d_in[3];
    const float* bk  = (const float*)d_in[4];
    const float* Wv  = (const float*)d_in[5];
    const float* bv  = (const float*)d_in[6];
    const float* Wo  = (const float*)d_in[7];
    const float* bo  = (const float*)d_in[8];
    const float* dww = (const float*)d_in[9];
    const float* dwb = (const float*)d_in[10];
    const float* lng = (const float*)d_in[11];
    const float* lnb = (const float*)d_in[12];
    const float* pww = (const float*)d_in[13];
    float* out = (float*)d_out;

    float *q, *xs, *k, *v, *att, *pos;
    cudaGetSymbolAddress((void**)&q,   g_q);
    cudaGetSymbolAddress((void**)&xs,  g_xs);
    cudaGetSymbolAddress((void**)&k,   g_k);
    cudaGetSymbolAddress((void**)&v,   g_v);
    cudaGetSymbolAddress((void**)&att, g_att);
    cudaGetSymbolAddress((void**)&pos, g_pos);

    cudaFuncSetAttribute(attention_k, cudaFuncAttributeMaxDynamicSharedMemorySize, ATT_SMEM);

    dim3 gbig((HWSZ + 127) / 128, NCH / 128, BATCH);   // 25 x 3 x 8
    dim3 gsml((NKV + 127) / 128, NCH / 128, BATCH);    // 7 x 3 x 8

    gemm_bias<<<gbig, 256>>>(Wq, x, bq, q, NCH, NCH, HWSZ);
    offset_net<<<BATCH * NG * NKV, 128>>>(q, dww, dwb, lng, lnb, pww,
                                          pos, out + YSZ, out + YSZ + PSZ);
    grid_sample_k<<<dim3((GC * NKV) / 256, BATCH * NG), 256>>>(x, pos, xs);
    gemm_bias<<<gsml, 256>>>(Wk, xs, bk, k, NCH, NCH, NKV);
    gemm_bias<<<gsml, 256>>>(Wv, xs, bv, v, NCH, NCH, NKV);
    attention_k<<<dim3(HWSZ / TM, BATCH * NH), 256, ATT_SMEM>>>(q, k, v, att);
    gemm_bias<<<gbig, 256>>>(Wo, att, bo, out, NCH, NCH, HWSZ);
}

// round 3
// speedup vs baseline: 1.6271x; 1.6271x over previous
#include <cuda_runtime.h>
#include <math.h>

// Problem constants
#define BATCH 8
#define NCH   384
#define HH    56
#define WW    56
#define HWSZ  3136      // 56*56
#define NKV   784       // 28*28
#define HK    28
#define NG    4
#define GC    96
#define NH    8
#define HC    48

#define YSZ   (BATCH*NCH*HWSZ)     // 9633792
#define PSZ   (BATCH*NG*NKV*2)     // 50176

// Scratch (allocation-free rule: __device__ globals)
static __device__ float g_q  [BATCH*NCH*HWSZ];
static __device__ float g_xs [BATCH*NCH*NKV];
static __device__ float g_k  [BATCH*NCH*NKV];
static __device__ float g_v  [BATCH*NCH*NKV];
static __device__ float g_att[BATCH*NCH*HWSZ];
static __device__ float g_pos[BATCH*NG*NKV*2];

// ---------------------------------------------------------------------------
// tf32 mma helpers
// ---------------------------------------------------------------------------
__device__ __forceinline__ unsigned f2tf(float f) {
    unsigned r; asm("cvt.rna.tf32.f32 %0, %1;" : "=r"(r) : "f"(f)); return r;
}
__device__ __forceinline__ float tf2f(float f) {     // cvt, keep as float bits
    return __uint_as_float(f2tf(f));
}
__device__ __forceinline__ void mma8(float* d, const unsigned* a, const unsigned* b) {
    asm("mma.sync.aligned.m16n8k8.row.col.f32.tf32.tf32.f32 "
        "{%0,%1,%2,%3}, {%4,%5,%6,%7}, {%8,%9}, {%0,%1,%2,%3};"
        : "+f"(d[0]), "+f"(d[1]), "+f"(d[2]), "+f"(d[3])
        : "r"(a[0]), "r"(a[1]), "r"(a[2]), "r"(a[3]), "r"(b[0]), "r"(b[1]));
}
#define SB(x) __float_as_uint(x)   // smem value already tf32-converted

// ---------------------------------------------------------------------------
// GEMM (tf32 tensor core): C[z] = W(384x384) * B[z](384xN) + bias
// 128x128x16 block tile, 256 threads = 8 warps (2m x 4n), warp tile 64x32.
// smem strides chosen for conflict-free fragment LDS.
// ---------------------------------------------------------------------------
#define ASTR 20
#define BSTR 136

__global__ __launch_bounds__(256)
void gemm_tf32(const float* __restrict__ A, const float* __restrict__ Bsrc,
               const float* __restrict__ bias, float* __restrict__ C,
               int K, int N)
{
    __shared__ float As[128 * ASTR];   // [m][k], tf32-converted
    __shared__ float Bs[16 * BSTR];    // [k][n], tf32-converted
    const float* Bp = Bsrc + (size_t)blockIdx.z * K * N;
    float*       Cp = C    + (size_t)blockIdx.z * 384 * N;
    int m0 = blockIdx.y * 128, n0 = blockIdx.x * 128;
    int tid = threadIdx.x;
    int wid = tid >> 5, lane = tid & 31;
    int g = lane >> 2, tig = lane & 3;
    int wm = (wid & 1) * 64;
    int wn = (wid >> 1) * 32;

    int ar = tid >> 1, ac = (tid & 1) * 8;      // A stage: 128 rows x 16 cols
    int br = tid >> 4, bc = (tid & 15) * 8;     // B stage: 16 rows x 128 cols

    float acc[4][4][4];
#pragma unroll
    for (int i = 0; i < 4; i++)
#pragma unroll
        for (int j = 0; j < 4; j++)
#pragma unroll
            for (int r = 0; r < 4; r++) acc[i][j][r] = 0.f;

    for (int k0 = 0; k0 < K; k0 += 16) {
        // stage A (convert to tf32 bits)
        {
            const float* ap = A + (size_t)(m0 + ar) * K + k0 + ac;
            float4 a0 = *reinterpret_cast<const float4*>(ap);
            float4 a1 = *reinterpret_cast<const float4*>(ap + 4);
            float* d = &As[ar * ASTR + ac];
            d[0] = tf2f(a0.x); d[1] = tf2f(a0.y); d[2] = tf2f(a0.z); d[3] = tf2f(a0.w);
            d[4] = tf2f(a1.x); d[5] = tf2f(a1.y); d[6] = tf2f(a1.z); d[7] = tf2f(a1.w);
        }
        // stage B
        {
            float4 b0 = make_float4(0.f,0.f,0.f,0.f), b1 = b0;
            if (n0 + bc < N) {
                const float* bp = Bp + (size_t)(k0 + br) * N + n0 + bc;
                b0 = *reinterpret_cast<const float4*>(bp);
                b1 = *reinterpret_cast<const float4*>(bp + 4);
            }
            float4 c0 = make_float4(tf2f(b0.x), tf2f(b0.y), tf2f(b0.z), tf2f(b0.w));
            float4 c1 = make_float4(tf2f(b1.x), tf2f(b1.y), tf2f(b1.z), tf2f(b1.w));
            *reinterpret_cast<float4*>(&Bs[br * BSTR + bc])     = c0;
            *reinterpret_cast<float4*>(&Bs[br * BSTR + bc + 4]) = c1;
        }
        __syncthreads();
#pragma unroll
        for (int kk = 0; kk < 16; kk += 8) {
            unsigned af[4][4], bf[4][2];
#pragma unroll
            for (int mi = 0; mi < 4; mi++) {
                int base = wm + mi * 16;
                af[mi][0] = SB(As[(base + g) * ASTR + kk + tig]);
                af[mi][1] = SB(As[(base + g + 8) * ASTR + kk + tig]);
                af[mi][2] = SB(As[(base + g) * ASTR + kk + tig + 4]);
                af[mi][3] = SB(As[(base + g + 8) * ASTR + kk + tig + 4]);
            }
#pragma unroll
            for (int ni = 0; ni < 4; ni++) {
                int col = wn + ni * 8 + g;
                bf[ni][0] = SB(Bs[(kk + tig) * BSTR + col]);
                bf[ni][1] = SB(Bs[(kk + tig + 4) * BSTR + col]);
            }
#pragma unroll
            for (int mi = 0; mi < 4; mi++)
#pragma unroll
                for (int ni = 0; ni < 4; ni++)
                    mma8(acc[mi][ni], af[mi], bf[ni]);
        }
        __syncthreads();
    }

    // epilogue
#pragma unroll
    for (int mi = 0; mi < 4; mi++) {
        int r0 = m0 + wm + mi * 16 + g;
        int r1 = r0 + 8;
        float bv0 = bias[r0], bv1 = bias[r1];
#pragma unroll
        for (int ni = 0; ni < 4; ni++) {
            int cn = n0 + wn + ni * 8 + 2 * tig;
            if (cn < N) {
                float2 lo = make_float2(acc[mi][ni][0] + bv0, acc[mi][ni][1] + bv0);
                float2 hi = make_float2(acc[mi][ni][2] + bv1, acc[mi][ni][3] + bv1);
                *reinterpret_cast<float2*>(&Cp[(size_t)r0 * N + cn]) = lo;
                *reinterpret_cast<float2*>(&Cp[(size_t)r1 * N + cn]) = hi;
            }
        }
    }
}

// ---------------------------------------------------------------------------
// Offset network (unchanged)
// ---------------------------------------------------------------------------
__global__ __launch_bounds__(128)
void offset_net(const float* __restrict__ q,
                const float* __restrict__ dw_w, const float* __restrict__ dw_b,
                const float* __restrict__ ln_g, const float* __restrict__ ln_b,
                const float* __restrict__ pw_w,
                float* __restrict__ pos, float* __restrict__ pos_out,
                float* __restrict__ ref_out)
{
    int blk = blockIdx.x;
    int bg = blk / NKV;
    int ij = blk - bg * NKV;
    int i = ij / HK, j = ij - i * HK;
    int b = bg >> 2, g = bg & 3;
    int c = threadIdx.x;

    __shared__ float red[128];

    float h = 0.f;
    if (c < GC) {
        const float* qc = q + ((size_t)(b * NCH + g * GC + c)) * HWSZ;
        const float* w = dw_w + c * 9;
        int y0 = 2 * i - 1, x0 = 2 * j - 1;
#pragma unroll
        for (int ky = 0; ky < 3; ky++) {
            int y = y0 + ky;
            if (y < 0 || y >= HH) continue;
#pragma unroll
            for (int kx = 0; kx < 3; kx++) {
                int x = x0 + kx;
                if (x < 0 || x >= WW) continue;
                h += w[ky * 3 + kx] * qc[y * WW + x];
            }
        }
        h += dw_b[c];
    }
    red[c] = (c < GC) ? h : 0.f; __syncthreads();
    for (int s = 64; s > 0; s >>= 1) { if (c < s) red[c] += red[c + s]; __syncthreads(); }
    float mu = red[0] * (1.f / GC); __syncthreads();
    float d = (c < GC) ? (h - mu) : 0.f;
    red[c] = d * d; __syncthreads();
    for (int s = 64; s > 0; s >>= 1) { if (c < s) red[c] += red[c + s]; __syncthreads(); }
    float var = red[0] * (1.f / GC); __syncthreads();

    float hn = 0.f;
    if (c < GC) {
        hn = d * rsqrtf(var + 1e-5f) * ln_g[c] + ln_b[c];
        hn = 0.5f * hn * (1.f + erff(hn * 0.70710678118654752f));
    }
    red[c] = (c < GC) ? pw_w[c] * hn : 0.f; __syncthreads();
    for (int s = 64; s > 0; s >>= 1) { if (c < s) red[c] += red[c + s]; __syncthreads(); }
    float offy = red[0]; __syncthreads();
    red[c] = (c < GC) ? pw_w[GC + c] * hn : 0.f; __syncthreads();
    for (int s = 64; s > 0; s >>= 1) { if (c < s) red[c] += red[c + s]; __syncthreads(); }
    float offx = red[0];

    if (c == 0) {
        float ry = (0.5f + (float)i) * (1.f / 27.f) * 2.f - 1.f;
        float rx = (0.5f + (float)j) * (1.f / 27.f) * 2.f - 1.f;
        float py = tanhf(offy) * (1.f / 27.f) + ry;
        float px = tanhf(offx) * (1.f / 27.f) + rx;
        size_t o = ((size_t)bg * NKV + ij) * 2;
        pos[o] = py;     pos[o + 1] = px;
        pos_out[o] = py; pos_out[o + 1] = px;
        ref_out[o] = ry; ref_out[o + 1] = rx;
    }
}

// ---------------------------------------------------------------------------
// Bilinear grid sample (unchanged)
// ---------------------------------------------------------------------------
__global__ __launch_bounds__(256)
void grid_sample_k(const float* __restrict__ x, const float* __restrict__ pos,
                   float* __restrict__ xs)
{
    int bg = blockIdx.y;
    int b = bg >> 2, g = bg & 3;
    int idx = blockIdx.x * 256 + threadIdx.x;
    int c = idx / NKV, p = idx - c * NKV;

    float py = pos[((size_t)bg * NKV + p) * 2];
    float px = pos[((size_t)bg * NKV + p) * 2 + 1];
    float gx = (px + 1.f) * 0.5f * (WW - 1);
    float gy = (py + 1.f) * 0.5f * (HH - 1);
    float x0f = floorf(gx), y0f = floorf(gy);
    int x0 = (int)x0f, y0 = (int)y0f;
    float wx1 = gx - x0f, wx0 = 1.f - wx1;
    float wy1 = gy - y0f, wy0 = 1.f - wy1;

    const float* img = x + ((size_t)(b * NCH + g * GC + c)) * HWSZ;

    float v00 = 0.f, v01 = 0.f, v10 = 0.f, v11 = 0.f;
    bool xv0 = (x0 >= 0) && (x0 < WW);
    bool xv1 = (x0 + 1 >= 0) && (x0 + 1 < WW);
    bool yv0 = (y0 >= 0) && (y0 < HH);
    bool yv1 = (y0 + 1 >= 0) && (y0 + 1 < HH);
    if (xv0 && yv0) v00 = img[y0 * WW + x0];
    if (xv1 && yv0) v01 = img[y0 * WW + x0 + 1];
    if (xv0 && yv1) v10 = img[(y0 + 1) * WW + x0];
    if (xv1 && yv1) v11 = img[(y0 + 1) * WW + x0 + 1];

    float acc = v00 * wx0 * wy0 + v01 * wx1 * wy0 + v10 * wx0 * wy1 + v11 * wx1 * wy1;
    xs[((size_t)(b * NCH + g * GC + c)) * NKV + p] = acc;
}

// ---------------------------------------------------------------------------
// Attention (tf32 tensor core), 32 queries per block, two-pass.
// Pass1: S = Q^T K via mma (m=query, n=key, k=channel), logits fp32 in smem.
// Softmax writes probs pre-converted to tf32 bits.
// Pass2: out = P V^T via mma (m=query, n=channel, k=key).
// ---------------------------------------------------------------------------
#define TM 32
#define TNK 128
#define LSTR 788
#define QSTR 52
#define KVSTR 148
#define ATT_SMEM ((TM*LSTR + TM*QSTR + HC*KVSTR) * 4)   // 135,936 bytes

__global__ __launch_bounds__(256)
void attention_tf32(const float* __restrict__ q, const float* __restrict__ k,
                    const float* __restrict__ v, float* __restrict__ out)
{
    extern __shared__ float sm[];
    float* logits = sm;                       // TM x LSTR (fp32 / tf32 bits)
    float* qs     = sm + TM * LSTR;           // [m][c] stride QSTR, tf32 bits
    float* kv     = qs + TM * QSTR;           // [c][n] stride KVSTR, tf32 bits

    int head = blockIdx.y;
    int b = head >> 3, hh = head & 7;
    const float* qp = q + ((size_t)(b * NCH + hh * HC)) * HWSZ;
    const float* kp = k + ((size_t)(b * NCH + hh * HC)) * NKV;
    const float* vp = v + ((size_t)(b * NCH + hh * HC)) * NKV;
    float*       op = out + ((size_t)(b * NCH + hh * HC)) * HWSZ;
    int m0 = blockIdx.x * TM;
    int tid = threadIdx.x;
    int wid = tid >> 5, lane = tid & 31;
    int g = lane >> 2, tig = lane & 3;
    const float scale = 0.14433756729740643f;   // 1/sqrt(48)

    // stage q tile [m][c], tf32-converted
    for (int idx = tid; idx < HC * TM; idx += 256) {
        int c = idx >> 5, m = idx & 31;
        qs[m * QSTR + c] = tf2f(qp[(size_t)c * HWSZ + m0 + m]);
    }
    __syncthreads();

    // ---- Pass 1 ----
    for (int n0 = 0; n0 < NKV; n0 += TNK) {
        // stage K tile (zero-padded, tf32)
        for (int idx = tid; idx < HC * (TNK / 4); idx += 256) {
            int c = idx >> 5, n4 = (idx & 31) * 4;
            float4 val = make_float4(0.f,0.f,0.f,0.f);
            if (n0 + n4 < NKV)
                val = *reinterpret_cast<const float4*>(&kp[(size_t)c * NKV + n0 + n4]);
            float4 cv = make_float4(tf2f(val.x), tf2f(val.y), tf2f(val.z), tf2f(val.w));
            *reinterpret_cast<float4*>(&kv[c * KVSTR + n4]) = cv;
        }
        __syncthreads();

        int nb = n0 + wid * 16;
        if (nb < LSTR) {
            float acc[2][2][4];
#pragma unroll
            for (int mi = 0; mi < 2; mi++)
#pragma unroll
                for (int ni = 0; ni < 2; ni++)
#pragma unroll
                    for (int r = 0; r < 4; r++) acc[mi][ni][r] = 0.f;
#pragma unroll
            for (int kk = 0; kk < HC; kk += 8) {
                unsigned af[2][4], bf[2][2];
#pragma unroll
                for (int mi = 0; mi < 2; mi++) {
                    int mb = mi * 16;
                    af[mi][0] = SB(qs[(mb + g) * QSTR + kk + tig]);
                    af[mi][1] = SB(qs[(mb + g + 8) * QSTR + kk + tig]);
                    af[mi][2] = SB(qs[(mb + g) * QSTR + kk + tig + 4]);
                    af[mi][3] = SB(qs[(mb + g + 8) * QSTR + kk + tig + 4]);
                }
#pragma unroll
                for (int ni = 0; ni < 2; ni++) {
                    int colL = wid * 16 + ni * 8 + g;
                    bf[ni][0] = SB(kv[(kk + tig) * KVSTR + colL]);
                    bf[ni][1] = SB(kv[(kk + tig + 4) * KVSTR + colL]);
                }
#pragma unroll
                for (int mi = 0; mi < 2; mi++)
#pragma unroll
                    for (int ni = 0; ni < 2; ni++)
                        mma8(acc[mi][ni], af[mi], bf[ni]);
            }
#pragma unroll
            for (int mi = 0; mi < 2; mi++) {
                int q0 = mi * 16 + g;
#pragma unroll
                for (int ni = 0; ni < 2; ni++) {
                    int col = nb + ni * 8 + 2 * tig;
                    if (col < LSTR) {
                        logits[q0 * LSTR + col]           = acc[mi][ni][0] * scale;
                        logits[q0 * LSTR + col + 1]       = acc[mi][ni][1] * scale;
                        logits[(q0 + 8) * LSTR + col]     = acc[mi][ni][2] * scale;
                        logits[(q0 + 8) * LSTR + col + 1] = acc[mi][ni][3] * scale;
                    }
                }
            }
        }
        __syncthreads();
    }

    // ---- Softmax (writes tf32-converted probs) ----
    {
        for (int mi = wid; mi < TM; mi += 8) {
            float* lr = &logits[mi * LSTR];
            float mx = -1e30f;
            for (int n = lane; n < NKV; n += 32) mx = fmaxf(mx, lr[n]);
#pragma unroll
            for (int o = 16; o > 0; o >>= 1) mx = fmaxf(mx, __shfl_xor_sync(0xffffffffu, mx, o));
            float sum = 0.f;
            for (int n = lane; n < NKV; n += 32) {
                float e = __expf(lr[n] - mx);
                lr[n] = e; sum += e;
            }
#pragma unroll
            for (int o = 16; o > 0; o >>= 1) sum += __shfl_xor_sync(0xffffffffu, sum, o);
            float inv = 1.f / sum;
            for (int n = lane; n < NKV; n += 32) lr[n] = tf2f(lr[n] * inv);
        }
    }
    __syncthreads();

    // ---- Pass 2 ----
    float acc2[2][4];
#pragma unroll
    for (int i = 0; i < 2; i++)
#pragma unroll
        for (int r = 0; r < 4; r++) acc2[i][r] = 0.f;

    for (int n0 = 0; n0 < NKV; n0 += TNK) {
        // stage V tile (zero-padded, tf32)
        for (int idx = tid; idx < HC * (TNK / 4); idx += 256) {
            int c = idx >> 5, n4 = (idx & 31) * 4;
            float4 val = make_float4(0.f,0.f,0.f,0.f);
            if (n0 + n4 < NKV)
                val = *reinterpret_cast<const float4*>(&vp[(size_t)c * NKV + n0 + n4]);
            float4 cv = make_float4(tf2f(val.x), tf2f(val.y), tf2f(val.z), tf2f(val.w));
            *reinterpret_cast<float4*>(&kv[c * KVSTR + n4]) = cv;
        }
        __syncthreads();

        int kmax = min(TNK, NKV - n0);
        for (int p = wid; p < 12; p += 8) {
            int pi = (p >= 8) ? 1 : 0;
            int mi = p & 1, ci = p >> 1;
            int q0 = mi * 16;
#pragma unroll 4
            for (int kk = 0; kk < kmax; kk += 8) {
                unsigned af[4], bf[2];
                af[0] = SB(logits[(q0 + g) * LSTR + n0 + kk + tig]);
                af[1] = SB(logits[(q0 + g + 8) * LSTR + n0 + kk + tig]);
                af[2] = SB(logits[(q0 + g) * LSTR + n0 + kk + tig + 4]);
                af[3] = SB(logits[(q0 + g + 8) * LSTR + n0 + kk + tig + 4]);
                bf[0] = SB(kv[(ci * 8 + g) * KVSTR + kk + tig]);
                bf[1] = SB(kv[(ci * 8 + g) * KVSTR + kk + tig + 4]);
                mma8(acc2[pi], af, bf);
            }
        }
        __syncthreads();
    }

    // epilogue: D (m=query, n=channel)
    for (int p = wid; p < 12; p += 8) {
        int pi = (p >= 8) ? 1 : 0;
        int mi = p & 1, ci = p >> 1;
        int qg = m0 + mi * 16 + g;
        int cc = ci * 8 + 2 * tig;
        op[(size_t)cc * HWSZ + qg]           = acc2[pi][0];
        op[(size_t)(cc + 1) * HWSZ + qg]     = acc2[pi][1];
        op[(size_t)cc * HWSZ + qg + 8]       = acc2[pi][2];
        op[(size_t)(cc + 1) * HWSZ + qg + 8] = acc2[pi][3];
    }
}

// ---------------------------------------------------------------------------
extern "C" void kernel_launch(void* const* d_in, const int* in_sizes, int n_in,
                              void* d_out, int out_size)
{
    const float* x   = (const float*)d_in[0];
    const float* Wq  = (const float*)d_in[1];
    const float* bq  = (const float*)d_in[2];
    const float* Wk  = (const float*)d_in[3];
    const float* bk  = (const float*)d_in[4];
    const float* Wv  = (const float*)d_in[5];
    const float* bv  = (const float*)d_in[6];
    const float* Wo  = (const float*)d_in[7];
    const float* bo  = (const float*)d_in[8];
    const float* dww = (const float*)d_in[9];
    const float* dwb = (const float*)d_in[10];
    const float* lng = (const float*)d_in[11];
    const float* lnb = (const float*)d_in[12];
    const float* pww = (const float*)d_in[13];
    float* out = (float*)d_out;

    float *q, *xs, *k, *v, *att, *pos;
    cudaGetSymbolAddress((void**)&q,   g_q);
    cudaGetSymbolAddress((void**)&xs,  g_xs);
    cudaGetSymbolAddress((void**)&k,   g_k);
    cudaGetSymbolAddress((void**)&v,   g_v);
    cudaGetSymbolAddress((void**)&att, g_att);
    cudaGetSymbolAddress((void**)&pos, g_pos);

    cudaFuncSetAttribute(attention_tf32, cudaFuncAttributeMaxDynamicSharedMemorySize, ATT_SMEM);

    dim3 gbig((HWSZ + 127) / 128, 3, BATCH);   // 25 x 3 x 8
    dim3 gsml((NKV + 127) / 128, 3, BATCH);    // 7 x 3 x 8

    gemm_tf32<<<gbig, 256>>>(Wq, x, bq, q, NCH, HWSZ);
    offset_net<<<BATCH * NG * NKV, 128>>>(q, dww, dwb, lng, lnb, pww,
                                          pos, out + YSZ, out + YSZ + PSZ);
    grid_sample_k<<<dim3((GC * NKV) / 256, BATCH * NG), 256>>>(x, pos, xs);
    gemm_tf32<<<gsml, 256>>>(Wk, xs, bk, k, NCH, NKV);
    gemm_tf32<<<gsml, 256>>>(Wv, xs, bv, v, NCH, NKV);
    attention_tf32<<<dim3(HWSZ / TM, BATCH * NH), 256, ATT_SMEM>>>(q, k, v, att);
    gemm_tf32<<<gbig, 256>>>(Wo, att, bo, out, NCH, HWSZ);
}

// round 4
// speedup vs baseline: 4.2541x; 2.6145x over previous
#include <cuda_runtime.h>
#include <math.h>

// Problem constants
#define BATCH 8
#define NCH   384
#define HH    56
#define WW    56
#define HWSZ  3136      // 56*56
#define NKV   784       // 28*28
#define HK    28
#define NG    4
#define GC    96
#define NH    8
#define HC    48

#define YSZ   (BATCH*NCH*HWSZ)     // 9633792
#define PSZ   (BATCH*NG*NKV*2)     // 50176

// Scratch (allocation-free rule: __device__ globals)
static __device__ float g_q  [BATCH*NCH*HWSZ];
static __device__ float g_xs [BATCH*NCH*NKV];
static __device__ float g_k  [BATCH*NCH*NKV];
static __device__ float g_v  [BATCH*NCH*NKV];
static __device__ float g_att[BATCH*NCH*HWSZ];
static __device__ float g_pos[BATCH*NG*NKV*2];

// ---------------------------------------------------------------------------
// tf32 mma helpers
// ---------------------------------------------------------------------------
__device__ __forceinline__ unsigned f2tf(float f) {
    unsigned r; asm("cvt.rna.tf32.f32 %0, %1;" : "=r"(r) : "f"(f)); return r;
}
__device__ __forceinline__ void mma8(float* d, const unsigned* a, const unsigned* b) {
    asm("mma.sync.aligned.m16n8k8.row.col.f32.tf32.tf32.f32 "
        "{%0,%1,%2,%3}, {%4,%5,%6,%7}, {%8,%9}, {%0,%1,%2,%3};"
        : "+f"(d[0]), "+f"(d[1]), "+f"(d[2]), "+f"(d[3])
        : "r"(a[0]), "r"(a[1]), "r"(a[2]), "r"(a[3]), "r"(b[0]), "r"(b[1]));
}
__device__ __forceinline__ void cpa16(unsigned dst, const void* src, bool pred) {
    int sz = pred ? 16 : 0;
    asm volatile("cp.async.cg.shared.global [%0], [%1], 16, %2;"
                 :: "r"(dst), "l"(src), "r"(sz));
}
#define CPA_COMMIT() asm volatile("cp.async.commit_group;")
#define CPA_WAIT1()  asm volatile("cp.async.wait_group 1;")

// ---------------------------------------------------------------------------
// GEMM (tf32, cp.async double-buffered): C[z] = W(384x384)*B[z](384xN)+bias
// 128x128x16 block tile, 8 warps (2m x 4n), warp tile 64x32.
// Raw fp32 staged; tf32 conversion at fragment read (fma pipe idle).
// ---------------------------------------------------------------------------
#define ASTR 20
#define BSTR 136

__global__ __launch_bounds__(256)
void gemm_tf32(const float* __restrict__ A, const float* __restrict__ Bsrc,
               const float* __restrict__ bias, float* __restrict__ C,
               int K, int N)
{
    __shared__ float As[2][128 * ASTR];
    __shared__ float Bs[2][16 * BSTR];
    const float* Bp = Bsrc + (size_t)blockIdx.z * K * N;
    float*       Cp = C    + (size_t)blockIdx.z * 384 * N;
    int m0 = blockIdx.y * 128, n0 = blockIdx.x * 128;
    int tid = threadIdx.x;
    int wid = tid >> 5, lane = tid & 31;
    int g = lane >> 2, tig = lane & 3;
    int wm = (wid & 1) * 64;
    int wn = (wid >> 1) * 32;

    // stage mappings (float4 granules)
    int a_r0 = tid >> 2, a_c0 = (tid & 3) * 4;                 // +64 rows for i=1
    int b_r0 = tid >> 5, b_c0 = (tid & 31) * 4;                // +8 rows for i=1

    float acc[4][4][4];
#pragma unroll
    for (int i = 0; i < 4; i++)
#pragma unroll
        for (int j = 0; j < 4; j++)
#pragma unroll
            for (int r = 0; r < 4; r++) acc[i][j][r] = 0.f;

    // issue stage for k0 into buffer s
    auto issue = [&](int s, int k0) {
#pragma unroll
        for (int i = 0; i < 2; i++) {
            int r = a_r0 + i * 64;
            unsigned dst = (unsigned)__cvta_generic_to_shared(&As[s][r * ASTR + a_c0]);
            cpa16(dst, A + (size_t)(m0 + r) * K + k0 + a_c0, true);
        }
#pragma unroll
        for (int i = 0; i < 2; i++) {
            int r = b_r0 + i * 8;
            unsigned dst = (unsigned)__cvta_generic_to_shared(&Bs[s][r * BSTR + b_c0]);
            cpa16(dst, Bp + (size_t)(k0 + r) * N + n0 + b_c0, n0 + b_c0 < N);
        }
    };

    issue(0, 0);
    CPA_COMMIT();

    int s = 0;
    for (int k0 = 0; k0 < K; k0 += 16, s ^= 1) {
        if (k0 + 16 < K) issue(s ^ 1, k0 + 16);
        CPA_COMMIT();
        CPA_WAIT1();
        __syncthreads();
#pragma unroll
        for (int kk = 0; kk < 16; kk += 8) {
            unsigned af[4][4], bf[4][2];
#pragma unroll
            for (int mi = 0; mi < 4; mi++) {
                int base = wm + mi * 16;
                af[mi][0] = f2tf(As[s][(base + g) * ASTR + kk + tig]);
                af[mi][1] = f2tf(As[s][(base + g + 8) * ASTR + kk + tig]);
                af[mi][2] = f2tf(As[s][(base + g) * ASTR + kk + tig + 4]);
                af[mi][3] = f2tf(As[s][(base + g + 8) * ASTR + kk + tig + 4]);
            }
#pragma unroll
            for (int ni = 0; ni < 4; ni++) {
                int col = wn + ni * 8 + g;
                bf[ni][0] = f2tf(Bs[s][(kk + tig) * BSTR + col]);
                bf[ni][1] = f2tf(Bs[s][(kk + tig + 4) * BSTR + col]);
            }
#pragma unroll
            for (int mi = 0; mi < 4; mi++)
#pragma unroll
                for (int ni = 0; ni < 4; ni++)
                    mma8(acc[mi][ni], af[mi], bf[ni]);
        }
        __syncthreads();
    }

    // epilogue
#pragma unroll
    for (int mi = 0; mi < 4; mi++) {
        int r0 = m0 + wm + mi * 16 + g;
        int r1 = r0 + 8;
        float bv0 = bias[r0], bv1 = bias[r1];
#pragma unroll
        for (int ni = 0; ni < 4; ni++) {
            int cn = n0 + wn + ni * 8 + 2 * tig;
            if (cn < N) {
                float2 lo = make_float2(acc[mi][ni][0] + bv0, acc[mi][ni][1] + bv0);
                float2 hi = make_float2(acc[mi][ni][2] + bv1, acc[mi][ni][3] + bv1);
                *reinterpret_cast<float2*>(&Cp[(size_t)r0 * N + cn]) = lo;
                *reinterpret_cast<float2*>(&Cp[(size_t)r1 * N + cn]) = hi;
            }
        }
    }
}

// ---------------------------------------------------------------------------
// Offset network (unchanged)
// ---------------------------------------------------------------------------
__global__ __launch_bounds__(128)
void offset_net(const float* __restrict__ q,
                const float* __restrict__ dw_w, const float* __restrict__ dw_b,
                const float* __restrict__ ln_g, const float* __restrict__ ln_b,
                const float* __restrict__ pw_w,
                float* __restrict__ pos, float* __restrict__ pos_out,
                float* __restrict__ ref_out)
{
    int blk = blockIdx.x;
    int bg = blk / NKV;
    int ij = blk - bg * NKV;
    int i = ij / HK, j = ij - i * HK;
    int b = bg >> 2, g = bg & 3;
    int c = threadIdx.x;

    __shared__ float red[128];

    float h = 0.f;
    if (c < GC) {
        const float* qc = q + ((size_t)(b * NCH + g * GC + c)) * HWSZ;
        const float* w = dw_w + c * 9;
        int y0 = 2 * i - 1, x0 = 2 * j - 1;
#pragma unroll
        for (int ky = 0; ky < 3; ky++) {
            int y = y0 + ky;
            if (y < 0 || y >= HH) continue;
#pragma unroll
            for (int kx = 0; kx < 3; kx++) {
                int x = x0 + kx;
                if (x < 0 || x >= WW) continue;
                h += w[ky * 3 + kx] * qc[y * WW + x];
            }
        }
        h += dw_b[c];
    }
    red[c] = (c < GC) ? h : 0.f; __syncthreads();
    for (int s = 64; s > 0; s >>= 1) { if (c < s) red[c] += red[c + s]; __syncthreads(); }
    float mu = red[0] * (1.f / GC); __syncthreads();
    float d = (c < GC) ? (h - mu) : 0.f;
    red[c] = d * d; __syncthreads();
    for (int s = 64; s > 0; s >>= 1) { if (c < s) red[c] += red[c + s]; __syncthreads(); }
    float var = red[0] * (1.f / GC); __syncthreads();

    float hn = 0.f;
    if (c < GC) {
        hn = d * rsqrtf(var + 1e-5f) * ln_g[c] + ln_b[c];
        hn = 0.5f * hn * (1.f + erff(hn * 0.70710678118654752f));
    }
    red[c] = (c < GC) ? pw_w[c] * hn : 0.f; __syncthreads();
    for (int s = 64; s > 0; s >>= 1) { if (c < s) red[c] += red[c + s]; __syncthreads(); }
    float offy = red[0]; __syncthreads();
    red[c] = (c < GC) ? pw_w[GC + c] * hn : 0.f; __syncthreads();
    for (int s = 64; s > 0; s >>= 1) { if (c < s) red[c] += red[c + s]; __syncthreads(); }
    float offx = red[0];

    if (c == 0) {
        float ry = (0.5f + (float)i) * (1.f / 27.f) * 2.f - 1.f;
        float rx = (0.5f + (float)j) * (1.f / 27.f) * 2.f - 1.f;
        float py = tanhf(offy) * (1.f / 27.f) + ry;
        float px = tanhf(offx) * (1.f / 27.f) + rx;
        size_t o = ((size_t)bg * NKV + ij) * 2;
        pos[o] = py;     pos[o + 1] = px;
        pos_out[o] = py; pos_out[o + 1] = px;
        ref_out[o] = ry; ref_out[o + 1] = rx;
    }
}

// ---------------------------------------------------------------------------
// Bilinear grid sample (unchanged)
// ---------------------------------------------------------------------------
__global__ __launch_bounds__(256)
void grid_sample_k(const float* __restrict__ x, const float* __restrict__ pos,
                   float* __restrict__ xs)
{
    int bg = blockIdx.y;
    int b = bg >> 2, g = bg & 3;
    int idx = blockIdx.x * 256 + threadIdx.x;
    int c = idx / NKV, p = idx - c * NKV;

    float py = pos[((size_t)bg * NKV + p) * 2];
    float px = pos[((size_t)bg * NKV + p) * 2 + 1];
    float gx = (px + 1.f) * 0.5f * (WW - 1);
    float gy = (py + 1.f) * 0.5f * (HH - 1);
    float x0f = floorf(gx), y0f = floorf(gy);
    int x0 = (int)x0f, y0 = (int)y0f;
    float wx1 = gx - x0f, wx0 = 1.f - wx1;
    float wy1 = gy - y0f, wy0 = 1.f - wy1;

    const float* img = x + ((size_t)(b * NCH + g * GC + c)) * HWSZ;

    float v00 = 0.f, v01 = 0.f, v10 = 0.f, v11 = 0.f;
    bool xv0 = (x0 >= 0) && (x0 < WW);
    bool xv1 = (x0 + 1 >= 0) && (x0 + 1 < WW);
    bool yv0 = (y0 >= 0) && (y0 < HH);
    bool yv1 = (y0 + 1 >= 0) && (y0 + 1 < HH);
    if (xv0 && yv0) v00 = img[y0 * WW + x0];
    if (xv1 && yv0) v01 = img[y0 * WW + x0 + 1];
    if (xv0 && yv1) v10 = img[(y0 + 1) * WW + x0];
    if (xv1 && yv1) v11 = img[(y0 + 1) * WW + x0 + 1];

    float acc = v00 * wx0 * wy0 + v01 * wx1 * wy0 + v10 * wx0 * wy1 + v11 * wx1 * wy1;
    xs[((size_t)(b * NCH + g * GC + c)) * NKV + p] = acc;
}

// ---------------------------------------------------------------------------
// Flash attention (tf32 mma): 64 queries/block, key tile 112 (7 exact tiles).
// Online softmax; P via smem round-trip; 8 warps as 4m x 2n.
// ---------------------------------------------------------------------------
#define FTM 64
#define FTN 112
#define QSTR 52
#define KSTR 116
#define F_SMEM ((FTM*QSTR + 2*HC*KSTR + FTM*KSTR + 128 + 64 + 64) * 4)

__global__ __launch_bounds__(256, 2)
void attention_flash(const float* __restrict__ q, const float* __restrict__ k,
                     const float* __restrict__ v, float* __restrict__ out)
{
    extern __shared__ float sm[];
    float* qs  = sm;                          // [m][c]  FTM x QSTR
    float* kt  = qs + FTM * QSTR;             // [c][n]  HC x KSTR
    float* vt  = kt + HC * KSTR;              // [c][n]  HC x KSTR
    float* pt  = vt + HC * KSTR;              // [m][n]  FTM x KSTR
    float* red = pt + FTM * KSTR;             // [2][64]
    float* mst = red + 128;                   // [64]
    float* lst = mst + 64;                    // [64]

    int head = blockIdx.y;
    int b = head >> 3, hh = head & 7;
    const float* qp = q + ((size_t)(b * NCH + hh * HC)) * HWSZ;
    const float* kp = k + ((size_t)(b * NCH + hh * HC)) * NKV;
    const float* vp = v + ((size_t)(b * NCH + hh * HC)) * NKV;
    float*       op = out + ((size_t)(b * NCH + hh * HC)) * HWSZ;
    int m0 = blockIdx.x * FTM;
    int tid = threadIdx.x;
    int wid = tid >> 5, lane = tid & 31;
    int g = lane >> 2, tig = lane & 3;
    int wm = (wid & 3) * 16;                  // m tile base
    int wn = wid >> 2;                        // 0 or 1 (n half)
    const float scale = 0.14433756729740643f; // 1/sqrt(48)

    int row_lo = wm + g, row_hi = wm + g + 8;
    bool writer = (tig == 0) && (wn == 0);

    // stage Q [m][c]; init state
    for (int idx = tid; idx < HC * FTM; idx += 256) {
        int c = idx >> 6, m = idx & 63;
        qs[m * QSTR + c] = qp[(size_t)c * HWSZ + m0 + m];
    }
    if (tid < 64) { mst[tid] = -1e30f; lst[tid] = 0.f; }

    float o_acc[3][4];
#pragma unroll
    for (int i = 0; i < 3; i++)
#pragma unroll
        for (int r = 0; r < 4; r++) o_acc[i][r] = 0.f;

    for (int t = 0; t < 7; t++) {
        int n0 = t * FTN;
        // ---- stage K and V tiles (48 x 112 each, float4) ----
        __syncthreads();   // protect pt/kt/vt/red from previous tile readers
        for (int idx = tid; idx < HC * (FTN / 4); idx += 256) {
            int c = idx / 28, n4 = (idx % 28) * 4;
            *reinterpret_cast<float4*>(&kt[c * KSTR + n4]) =
                *reinterpret_cast<const float4*>(&kp[(size_t)c * NKV + n0 + n4]);
            *reinterpret_cast<float4*>(&vt[c * KSTR + n4]) =
                *reinterpret_cast<const float4*>(&vp[(size_t)c * NKV + n0 + n4]);
        }
        __syncthreads();

        // ---- S = scale * Q^T K : per warp 16 x 56 (7 n-tiles) ----
        float s[7][4];
#pragma unroll
        for (int j = 0; j < 7; j++)
#pragma unroll
            for (int r = 0; r < 4; r++) s[j][r] = 0.f;
        int ncol = wn * 56;
#pragma unroll
        for (int kk = 0; kk < HC; kk += 8) {
            unsigned af[4];
            af[0] = f2tf(qs[(wm + g) * QSTR + kk + tig]);
            af[1] = f2tf(qs[(wm + g + 8) * QSTR + kk + tig]);
            af[2] = f2tf(qs[(wm + g) * QSTR + kk + tig + 4]);
            af[3] = f2tf(qs[(wm + g + 8) * QSTR + kk + tig + 4]);
#pragma unroll
            for (int j = 0; j < 7; j++) {
                unsigned bf[2];
                int col = ncol + j * 8 + g;
                bf[0] = f2tf(kt[(kk + tig) * KSTR + col]);
                bf[1] = f2tf(kt[(kk + tig + 4) * KSTR + col]);
                mma8(s[j], af, bf);
            }
        }
#pragma unroll
        for (int j = 0; j < 7; j++)
#pragma unroll
            for (int r = 0; r < 4; r++) s[j][r] *= scale;

        // ---- row max: thread-local -> quad shuffle -> smem partials ----
        float mx_lo = -1e30f, mx_hi = -1e30f;
#pragma unroll
        for (int j = 0; j < 7; j++) {
            mx_lo = fmaxf(mx_lo, fmaxf(s[j][0], s[j][1]));
            mx_hi = fmaxf(mx_hi, fmaxf(s[j][2], s[j][3]));
        }
#pragma unroll
        for (int o = 1; o < 4; o <<= 1) {
            mx_lo = fmaxf(mx_lo, __shfl_xor_sync(0xffffffffu, mx_lo, o));
            mx_hi = fmaxf(mx_hi, __shfl_xor_sync(0xffffffffu, mx_hi, o));
        }
        if (tig == 0) { red[wn * 64 + row_lo] = mx_lo; red[wn * 64 + row_hi] = mx_hi; }
        __syncthreads();

        // ---- m_new, alpha (all threads, identical per row) ----
        float mo_lo = mst[row_lo], mo_hi = mst[row_hi];
        float mn_lo = fmaxf(mo_lo, fmaxf(red[row_lo], red[64 + row_lo]));
        float mn_hi = fmaxf(mo_hi, fmaxf(red[row_hi], red[64 + row_hi]));
        float al_lo = __expf(mo_lo - mn_lo);
        float al_hi = __expf(mo_hi - mn_hi);
        __syncthreads();
        if (writer) { mst[row_lo] = mn_lo; mst[row_hi] = mn_hi; }

        // ---- p = exp(s - m_new); write to pt; rowsum partials ----
        float sm_lo = 0.f, sm_hi = 0.f;
#pragma unroll
        for (int j = 0; j < 7; j++) {
            float p0 = __expf(s[j][0] - mn_lo);
            float p1 = __expf(s[j][1] - mn_lo);
            float p2 = __expf(s[j][2] - mn_hi);
            float p3 = __expf(s[j][3] - mn_hi);
            sm_lo += p0 + p1; sm_hi += p2 + p3;
            int col = ncol + j * 8 + 2 * tig;
            pt[row_lo * KSTR + col]     = p0;
            pt[row_lo * KSTR + col + 1] = p1;
            pt[row_hi * KSTR + col]     = p2;
            pt[row_hi * KSTR + col + 1] = p3;
        }
#pragma unroll
        for (int o = 1; o < 4; o <<= 1) {
            sm_lo += __shfl_xor_sync(0xffffffffu, sm_lo, o);
            sm_hi += __shfl_xor_sync(0xffffffffu, sm_hi, o);
        }
        if (tig == 0) { red[wn * 64 + row_lo] = sm_lo; red[wn * 64 + row_hi] = sm_hi; }
        __syncthreads();

        // ---- l update (writer), rescale out, PV mma ----
        if (writer) {
            lst[row_lo] = lst[row_lo] * al_lo + red[row_lo] + red[64 + row_lo];
            lst[row_hi] = lst[row_hi] * al_hi + red[row_hi] + red[64 + row_hi];
        }
#pragma unroll
        for (int i = 0; i < 3; i++) {
            o_acc[i][0] *= al_lo; o_acc[i][1] *= al_lo;
            o_acc[i][2] *= al_hi; o_acc[i][3] *= al_hi;
        }
        int cn = wn * 24;
#pragma unroll
        for (int kk = 0; kk < FTN; kk += 8) {
            unsigned af[4];
            af[0] = f2tf(pt[(wm + g) * KSTR + kk + tig]);
            af[1] = f2tf(pt[(wm + g + 8) * KSTR + kk + tig]);
            af[2] = f2tf(pt[(wm + g) * KSTR + kk + tig + 4]);
            af[3] = f2tf(pt[(wm + g + 8) * KSTR + kk + tig + 4]);
#pragma unroll
            for (int ni = 0; ni < 3; ni++) {
                unsigned bf[2];
                int cc = cn + ni * 8 + g;
                bf[0] = f2tf(vt[cc * KSTR + kk + tig]);
                bf[1] = f2tf(vt[cc * KSTR + kk + tig + 4]);
                mma8(o_acc[ni], af, bf);
            }
        }
    }
    __syncthreads();

    // ---- epilogue: out = acc / l ----
    float il_lo = 1.f / lst[row_lo];
    float il_hi = 1.f / lst[row_hi];
    int cn = wn * 24;
#pragma unroll
    for (int ni = 0; ni < 3; ni++) {
        int cc = cn + ni * 8 + 2 * tig;
        op[(size_t)cc * HWSZ + m0 + row_lo]       = o_acc[ni][0] * il_lo;
        op[(size_t)(cc + 1) * HWSZ + m0 + row_lo] = o_acc[ni][1] * il_lo;
        op[(size_t)cc * HWSZ + m0 + row_hi]       = o_acc[ni][2] * il_hi;
        op[(size_t)(cc + 1) * HWSZ + m0 + row_hi] = o_acc[ni][3] * il_hi;
    }
}

// ---------------------------------------------------------------------------
extern "C" void kernel_launch(void* const* d_in, const int* in_sizes, int n_in,
                              void* d_out, int out_size)
{
    const float* x   = (const float*)d_in[0];
    const float* Wq  = (const float*)d_in[1];
    const float* bq  = (const float*)d_in[2];
    const float* Wk  = (const float*)d_in[3];
    const float* bk  = (const float*)d_in[4];
    const float* Wv  = (const float*)d_in[5];
    const float* bv  = (const float*)d_in[6];
    const float* Wo  = (const float*)d_in[7];
    const float* bo  = (const float*)d_in[8];
    const float* dww = (const float*)d_in[9];
    const float* dwb = (const float*)d_in[10];
    const float* lng = (const float*)d_in[11];
    const float* lnb = (const float*)d_in[12];
    const float* pww = (const float*)d_in[13];
    float* out = (float*)d_out;

    float *q, *xs, *k, *v, *att, *pos;
    cudaGetSymbolAddress((void**)&q,   g_q);
    cudaGetSymbolAddress((void**)&xs,  g_xs);
    cudaGetSymbolAddress((void**)&k,   g_k);
    cudaGetSymbolAddress((void**)&v,   g_v);
    cudaGetSymbolAddress((void**)&att, g_att);
    cudaGetSymbolAddress((void**)&pos, g_pos);

    cudaFuncSetAttribute(attention_flash, cudaFuncAttributeMaxDynamicSharedMemorySize, F_SMEM);

    dim3 gbig((HWSZ + 127) / 128, 3, BATCH);   // 25 x 3 x 8
    dim3 gsml((NKV + 127) / 128, 3, BATCH);    // 7 x 3 x 8

    gemm_tf32<<<gbig, 256>>>(Wq, x, bq, q, NCH, HWSZ);
    offset_net<<<BATCH * NG * NKV, 128>>>(q, dww, dwb, lng, lnb, pww,
                                          pos, out + YSZ, out + YSZ + PSZ);
    grid_sample_k<<<dim3((GC * NKV) / 256, BATCH * NG), 256>>>(x, pos, xs);
    gemm_tf32<<<gsml, 256>>>(Wk, xs, bk, k, NCH, NKV);
    gemm_tf32<<<gsml, 256>>>(Wv, xs, bv, v, NCH, NKV);
    attention_flash<<<dim3(HWSZ / FTM, BATCH * NH), 256, F_SMEM>>>(q, k, v, att);
    gemm_tf32<<<gbig, 256>>>(Wo, att, bo, out, NCH, HWSZ);
}

// round 7
// speedup vs baseline: 7.6502x; 1.7983x over previous
#include <cuda_runtime.h>
#include <cuda_fp16.h>
#include <math.h>

// Problem constants
#define BATCH 8
#define NCH   384
#define HH    56
#define WW    56
#define HWSZ  3136      // 56*56
#define NKV   784       // 28*28
#define HK    28
#define NG    4
#define GC    96
#define NH    8
#define HC    48

#define YSZ   (BATCH*NCH*HWSZ)     // 9633792
#define PSZ   (BATCH*NG*NKV*2)     // 50176

// Scratch (allocation-free rule: __device__ globals)
static __device__ float  g_q   [BATCH*NCH*HWSZ];
static __device__ __half g_xh  [BATCH*NCH*HWSZ];
static __device__ __half g_atth[BATCH*NCH*HWSZ];
static __device__ __half g_xsh [BATCH*NCH*NKV];
static __device__ __half g_kh  [BATCH*NCH*NKV];
static __device__ __half g_vh  [BATCH*NCH*NKV];
static __device__ __half g_wh  [4*NCH*NCH];     // Wq, Wk, Wv, Wo fp16
static __device__ float  g_pos [BATCH*NG*NKV*2];

// ---------------------------------------------------------------------------
// mma / ldmatrix / cp.async helpers
// ---------------------------------------------------------------------------
__device__ __forceinline__ void mma16(float* d, const unsigned* a, const unsigned* b) {
    asm("mma.sync.aligned.m16n8k16.row.col.f32.f16.f16.f32 "
        "{%0,%1,%2,%3}, {%4,%5,%6,%7}, {%8,%9}, {%0,%1,%2,%3};"
        : "+f"(d[0]), "+f"(d[1]), "+f"(d[2]), "+f"(d[3])
        : "r"(a[0]), "r"(a[1]), "r"(a[2]), "r"(a[3]), "r"(b[0]), "r"(b[1]));
}
__device__ __forceinline__ void ldsm4(unsigned* r, const __half* p) {
    unsigned addr = (unsigned)__cvta_generic_to_shared(p);
    asm volatile("ldmatrix.sync.aligned.m8n8.x4.shared.b16 {%0,%1,%2,%3}, [%4];"
                 : "=r"(r[0]), "=r"(r[1]), "=r"(r[2]), "=r"(r[3]) : "r"(addr));
}
__device__ __forceinline__ void ldsm4t(unsigned* r, const __half* p) {
    unsigned addr = (unsigned)__cvta_generic_to_shared(p);
    asm volatile("ldmatrix.sync.aligned.m8n8.x4.trans.shared.b16 {%0,%1,%2,%3}, [%4];"
                 : "=r"(r[0]), "=r"(r[1]), "=r"(r[2]), "=r"(r[3]) : "r"(addr));
}
__device__ __forceinline__ void ldsm2t(unsigned* r, const __half* p) {
    unsigned addr = (unsigned)__cvta_generic_to_shared(p);
    asm volatile("ldmatrix.sync.aligned.m8n8.x2.trans.shared.b16 {%0,%1}, [%2];"
                 : "=r"(r[0]), "=r"(r[1]) : "r"(addr));
}
__device__ __forceinline__ void cpa16(const __half* dst, const __half* src, bool pred) {
    unsigned d = (unsigned)__cvta_generic_to_shared(dst);
    int sz = pred ? 16 : 0;
    asm volatile("cp.async.cg.shared.global [%0], [%1], 16, %2;"
                 :: "r"(d), "l"(src), "r"(sz));
}
#define CPA_COMMIT() asm volatile("cp.async.commit_group;")
#define CPA_WAIT1()  asm volatile("cp.async.wait_group 1;")
#define CPA_WAIT0()  asm volatile("cp.async.wait_group 0;")

// ---------------------------------------------------------------------------
// fp32 -> fp16 conversion (vectorized)
// ---------------------------------------------------------------------------
__global__ __launch_bounds__(256)
void to_half4(const float* __restrict__ src, __half* __restrict__ dst, int n4)
{
    int i = blockIdx.x * 256 + threadIdx.x;
    if (i < n4) {
        float4 f = reinterpret_cast<const float4*>(src)[i];
        half2 h0 = __floats2half2_rn(f.x, f.y);
        half2 h1 = __floats2half2_rn(f.z, f.w);
        reinterpret_cast<half2*>(dst)[2*i]   = h0;
        reinterpret_cast<half2*>(dst)[2*i+1] = h1;
    }
}

// ---------------------------------------------------------------------------
// fp16 GEMM: C[z] = A(384xK) * B[z](KxN) + bias
// 128x128x32 block tile, 8 warps (2m x 4n), warp 64x32. cp.async double-buffer.
// If A1 != null: blocks with blockIdx.y >= 3 use (A1, bias1, C1) (fused k/v).
// OUTH: write __half output, else float.
// ---------------------------------------------------------------------------
#define ASTRH 40     // halves per A row (32 + 8 pad)
#define BSTRH 136    // halves per B row (128 + 8 pad)

template<bool OUTH>
__global__ __launch_bounds__(256)
void gemm_h(const __half* __restrict__ A0, const __half* __restrict__ A1,
            const float* __restrict__ bias0, const float* __restrict__ bias1,
            const __half* __restrict__ Bsrc,
            void* __restrict__ C0, void* __restrict__ C1,
            int K, int N)
{
    __shared__ __half As[2][128 * ASTRH];
    __shared__ __half Bs[2][32 * BSTRH];

    bool sel = (A1 != nullptr) && (blockIdx.y >= 3);
    const __half* A    = sel ? A1 : A0;
    const float*  bias = sel ? bias1 : bias0;
    void*         Cv   = sel ? C1 : C0;

    const __half* Bp = Bsrc + (size_t)blockIdx.z * K * N;
    int m0 = (blockIdx.y % 3) * 128, n0 = blockIdx.x * 128;
    int tid = threadIdx.x;
    int wid = tid >> 5, lane = tid & 31;
    int g = lane >> 2, tig = lane & 3;
    int wm = (wid & 1) * 64;
    int wn = (wid >> 1) * 32;
    int l16 = lane & 15, lh = (lane >> 4) * 8;

    // stage mappings
    int ar = tid >> 1, ac = (tid & 1) * 16;   // A: 128 rows x 2 granule-pairs
    int br = tid >> 3, bc = (tid & 7) * 16;   // B: 32 rows x 8 granule-pairs

    float acc[4][4][4];
#pragma unroll
    for (int i = 0; i < 4; i++)
#pragma unroll
        for (int j = 0; j < 4; j++)
#pragma unroll
            for (int r = 0; r < 4; r++) acc[i][j][r] = 0.f;

    auto issue = [&](int s, int k0) {
        const __half* asrc = A + (size_t)(m0 + ar) * K + k0 + ac;
        cpa16(&As[s][ar * ASTRH + ac], asrc, true);
        cpa16(&As[s][ar * ASTRH + ac + 8], asrc + 8, true);
        const __half* bsrc = Bp + (size_t)(k0 + br) * N + n0 + bc;
        cpa16(&Bs[s][br * BSTRH + bc], bsrc, n0 + bc < N);
        cpa16(&Bs[s][br * BSTRH + bc + 8], bsrc + 8, n0 + bc + 8 < N);
    };

    issue(0, 0);
    CPA_COMMIT();

    int s = 0;
    for (int k0 = 0; k0 < K; k0 += 32, s ^= 1) {
        if (k0 + 32 < K) issue(s ^ 1, k0 + 32);
        CPA_COMMIT();
        CPA_WAIT1();
        __syncthreads();
#pragma unroll
        for (int kk = 0; kk < 32; kk += 16) {
            unsigned af[4][4], bf[4][2];
#pragma unroll
            for (int mf = 0; mf < 4; mf++)
                ldsm4(af[mf], &As[s][(wm + mf * 16 + l16) * ASTRH + kk + lh]);
#pragma unroll
            for (int nf = 0; nf < 4; nf += 2) {
                unsigned t4[4];
                ldsm4t(t4, &Bs[s][(kk + l16) * BSTRH + wn + nf * 8 + lh]);
                bf[nf][0] = t4[0]; bf[nf][1] = t4[1];
                bf[nf+1][0] = t4[2]; bf[nf+1][1] = t4[3];
            }
#pragma unroll
            for (int mf = 0; mf < 4; mf++)
#pragma unroll
                for (int nf = 0; nf < 4; nf++)
                    mma16(acc[mf][nf], af[mf], bf[nf]);
        }
        __syncthreads();
    }

    // epilogue
#pragma unroll
    for (int mf = 0; mf < 4; mf++) {
        int r0 = m0 + wm + mf * 16 + g;
        int r1 = r0 + 8;
        float bv0 = bias[r0], bv1 = bias[r1];
#pragma unroll
        for (int nf = 0; nf < 4; nf++) {
            int cn = n0 + wn + nf * 8 + 2 * tig;
            if (cn < N) {
                if (OUTH) {
                    __half* Ch = (__half*)Cv + (size_t)blockIdx.z * 384 * N;
                    *reinterpret_cast<half2*>(&Ch[(size_t)r0 * N + cn]) =
                        __floats2half2_rn(acc[mf][nf][0] + bv0, acc[mf][nf][1] + bv0);
                    *reinterpret_cast<half2*>(&Ch[(size_t)r1 * N + cn]) =
                        __floats2half2_rn(acc[mf][nf][2] + bv1, acc[mf][nf][3] + bv1);
                } else {
                    float* Cf = (float*)Cv + (size_t)blockIdx.z * 384 * N;
                    *reinterpret_cast<float2*>(&Cf[(size_t)r0 * N + cn]) =
                        make_float2(acc[mf][nf][0] + bv0, acc[mf][nf][1] + bv0);
                    *reinterpret_cast<float2*>(&Cf[(size_t)r1 * N + cn]) =
                        make_float2(acc[mf][nf][2] + bv1, acc[mf][nf][3] + bv1);
                }
            }
        }
    }
}

// ---------------------------------------------------------------------------
// Offset network (unchanged)
// ---------------------------------------------------------------------------
__global__ __launch_bounds__(128)
void offset_net(const float* __restrict__ q,
                const float* __restrict__ dw_w, const float* __restrict__ dw_b,
                const float* __restrict__ ln_g, const float* __restrict__ ln_b,
                const float* __restrict__ pw_w,
                float* __restrict__ pos, float* __restrict__ pos_out,
                float* __restrict__ ref_out)
{
    int blk = blockIdx.x;
    int bg = blk / NKV;
    int ij = blk - bg * NKV;
    int i = ij / HK, j = ij - i * HK;
    int b = bg >> 2, g = bg & 3;
    int c = threadIdx.x;

    __shared__ float red[128];

    float h = 0.f;
    if (c < GC) {
        const float* qc = q + ((size_t)(b * NCH + g * GC + c)) * HWSZ;
        const float* w = dw_w + c * 9;
        int y0 = 2 * i - 1, x0 = 2 * j - 1;
#pragma unroll
        for (int ky = 0; ky < 3; ky++) {
            int y = y0 + ky;
            if (y < 0 || y >= HH) continue;
#pragma unroll
            for (int kx = 0; kx < 3; kx++) {
                int x = x0 + kx;
                if (x < 0 || x >= WW) continue;
                h += w[ky * 3 + kx] * qc[y * WW + x];
            }
        }
        h += dw_b[c];
    }
    red[c] = (c < GC) ? h : 0.f; __syncthreads();
    for (int s = 64; s > 0; s >>= 1) { if (c < s) red[c] += red[c + s]; __syncthreads(); }
    float mu = red[0] * (1.f / GC); __syncthreads();
    float d = (c < GC) ? (h - mu) : 0.f;
    red[c] = d * d; __syncthreads();
    for (int s = 64; s > 0; s >>= 1) { if (c < s) red[c] += red[c + s]; __syncthreads(); }
    float var = red[0] * (1.f / GC); __syncthreads();

    float hn = 0.f;
    if (c < GC) {
        hn = d * rsqrtf(var + 1e-5f) * ln_g[c] + ln_b[c];
        hn = 0.5f * hn * (1.f + erff(hn * 0.70710678118654752f));
    }
    red[c] = (c < GC) ? pw_w[c] * hn : 0.f; __syncthreads();
    for (int s = 64; s > 0; s >>= 1) { if (c < s) red[c] += red[c + s]; __syncthreads(); }
    float offy = red[0]; __syncthreads();
    red[c] = (c < GC) ? pw_w[GC + c] * hn : 0.f; __syncthreads();
    for (int s = 64; s > 0; s >>= 1) { if (c < s) red[c] += red[c + s]; __syncthreads(); }
    float offx = red[0];

    if (c == 0) {
        float ry = (0.5f + (float)i) * (1.f / 27.f) * 2.f - 1.f;
        float rx = (0.5f + (float)j) * (1.f / 27.f) * 2.f - 1.f;
        float py = tanhf(offy) * (1.f / 27.f) + ry;
        float px = tanhf(offx) * (1.f / 27.f) + rx;
        size_t o = ((size_t)bg * NKV + ij) * 2;
        pos[o] = py;     pos[o + 1] = px;
        pos_out[o] = py; pos_out[o + 1] = px;
        ref_out[o] = ry; ref_out[o + 1] = rx;
    }
}

// ---------------------------------------------------------------------------
// Bilinear grid sample -> fp16 xs
// ---------------------------------------------------------------------------
__global__ __launch_bounds__(256)
void grid_sample_k(const float* __restrict__ x, const float* __restrict__ pos,
                   __half* __restrict__ xs)
{
    int bg = blockIdx.y;
    int b = bg >> 2, g = bg & 3;
    int idx = blockIdx.x * 256 + threadIdx.x;
    int c = idx / NKV, p = idx - c * NKV;

    float py = pos[((size_t)bg * NKV + p) * 2];
    float px = pos[((size_t)bg * NKV + p) * 2 + 1];
    float gx = (px + 1.f) * 0.5f * (WW - 1);
    float gy = (py + 1.f) * 0.5f * (HH - 1);
    float x0f = floorf(gx), y0f = floorf(gy);
    int x0 = (int)x0f, y0 = (int)y0f;
    float wx1 = gx - x0f, wx0 = 1.f - wx1;
    float wy1 = gy - y0f, wy0 = 1.f - wy1;

    const float* img = x + ((size_t)(b * NCH + g * GC + c)) * HWSZ;

    float v00 = 0.f, v01 = 0.f, v10 = 0.f, v11 = 0.f;
    bool xv0 = (x0 >= 0) && (x0 < WW);
    bool xv1 = (x0 + 1 >= 0) && (x0 + 1 < WW);
    bool yv0 = (y0 >= 0) && (y0 < HH);
    bool yv1 = (y0 + 1 >= 0) && (y0 + 1 < HH);
    if (xv0 && yv0) v00 = img[y0 * WW + x0];
    if (xv1 && yv0) v01 = img[y0 * WW + x0 + 1];
    if (xv0 && yv1) v10 = img[(y0 + 1) * WW + x0];
    if (xv1 && yv1) v11 = img[(y0 + 1) * WW + x0 + 1];

    float acc = v00 * wx0 * wy0 + v01 * wx1 * wy0 + v10 * wx0 * wy1 + v11 * wx1 * wy1;
    xs[((size_t)(b * NCH + g * GC + c)) * NKV + p] = __float2half_rn(acc);
}

// ---------------------------------------------------------------------------
// Flash attention (fp16 mma m16n8k16): 64 queries/block, key tile 112,
// double-buffered cp.async K/V, online softmax, fp16 output.
// ---------------------------------------------------------------------------
#define FTM 64
#define FTN 112
#define QSTRH 56     // 48 + 8 pad
#define KSTRH 120    // 112 + 8 pad
// halves: qs 64*56 + kt 2*48*120 + vt 2*48*120 + pt 64*120 = 34304 -> 68608 B
// floats: red 128 + mst 64 + lst 64 = 256 -> 1024 B
#define F_SMEM (34304 * 2 + 256 * 4)

__global__ __launch_bounds__(256)
void attention_h(const float* __restrict__ q, const __half* __restrict__ k,
                 const __half* __restrict__ v, __half* __restrict__ out)
{
    extern __shared__ char smraw[];
    __half* qs = (__half*)smraw;                    // [m][c]   64 x QSTRH
    __half* kt = qs + FTM * QSTRH;                  // [2][c][n] 48 x KSTRH
    __half* vt = kt + 2 * HC * KSTRH;
    __half* pt = vt + 2 * HC * KSTRH;               // [m][n]   64 x KSTRH
    float* red = (float*)(smraw + 34304 * 2);       // [2][64]
    float* mst = red + 128;
    float* lst = mst + 64;

    int head = blockIdx.y;
    int b = head >> 3, hh = head & 7;
    const float*  qp = q + ((size_t)(b * NCH + hh * HC)) * HWSZ;
    const __half* kp = k + ((size_t)(b * NCH + hh * HC)) * NKV;
    const __half* vp = v + ((size_t)(b * NCH + hh * HC)) * NKV;
    __half*       op = out + ((size_t)(b * NCH + hh * HC)) * HWSZ;
    int m0 = blockIdx.x * FTM;
    int tid = threadIdx.x;
    int wid = tid >> 5, lane = tid & 31;
    int g = lane >> 2, tig = lane & 3;
    int l16 = lane & 15, lh = (lane >> 4) * 8;
    int wm = (wid & 3) * 16;
    int wn = wid >> 2;                              // 0/1: key half
    const float scale = 0.14433756729740643f;

    int row_lo = wm + g, row_hi = wm + g + 8;
    bool writer = (tig == 0) && (wn == 0);

    // stage Q (fp32 -> fp16), init state
    for (int idx = tid; idx < HC * FTM; idx += 256) {
        int c = idx >> 6, m = idx & 63;
        qs[m * QSTRH + c] = __float2half_rn(qp[(size_t)c * HWSZ + m0 + m]);
    }
    if (tid < 64) { mst[tid] = -1e30f; lst[tid] = 0.f; }

    // stage K/V tile into buffer s (cp.async)
    auto stage_kv = [&](int s, int n0) {
        __half* kd = kt + s * HC * KSTRH;
        __half* vd = vt + s * HC * KSTRH;
        for (int it = tid; it < 1344; it += 256) {
            int tsel = it / 672;
            int rid = it - tsel * 672;
            int c = rid / 14, gc = (rid - c * 14) * 8;
            const __half* src = (tsel ? vp : kp) + (size_t)c * NKV + n0 + gc;
            cpa16((tsel ? vd : kd) + c * KSTRH + gc, src, true);
        }
    };

    stage_kv(0, 0);
    CPA_COMMIT();

    float o_acc[3][4];
#pragma unroll
    for (int i = 0; i < 3; i++)
#pragma unroll
        for (int r = 0; r < 4; r++) o_acc[i][r] = 0.f;

    int s = 0;
    for (int t = 0; t < 7; t++) {
        CPA_WAIT0();
        __syncthreads();
        const __half* kts = kt + s * HC * KSTRH;
        const __half* vts = vt + s * HC * KSTRH;
        int ncol = wn * 56;

        // ---- S = scale * Q^T K : warp tile 16 x 56 ----
        float sv[7][4];
#pragma unroll
        for (int j = 0; j < 7; j++)
#pragma unroll
            for (int r = 0; r < 4; r++) sv[j][r] = 0.f;
#pragma unroll
        for (int kk = 0; kk < HC; kk += 16) {
            unsigned af[4], bf[7][2];
            ldsm4(af, &qs[(wm + l16) * QSTRH + kk + lh]);
#pragma unroll
            for (int j = 0; j < 6; j += 2) {
                unsigned t4[4];
                ldsm4t(t4, &kts[(kk + l16) * KSTRH + ncol + j * 8 + lh]);
                bf[j][0] = t4[0]; bf[j][1] = t4[1];
                bf[j+1][0] = t4[2]; bf[j+1][1] = t4[3];
            }
            ldsm2t(bf[6], &kts[(kk + l16) * KSTRH + ncol + 48]);
#pragma unroll
            for (int j = 0; j < 7; j++) mma16(sv[j], af, bf[j]);
        }
#pragma unroll
        for (int j = 0; j < 7; j++)
#pragma unroll
            for (int r = 0; r < 4; r++) sv[j][r] *= scale;

        // prefetch next K/V tile (overlaps softmax + PV)
        if (t < 6) stage_kv(s ^ 1, (t + 1) * FTN);
        CPA_COMMIT();

        // ---- row max ----
        float mx_lo = -1e30f, mx_hi = -1e30f;
#pragma unroll
        for (int j = 0; j < 7; j++) {
            mx_lo = fmaxf(mx_lo, fmaxf(sv[j][0], sv[j][1]));
            mx_hi = fmaxf(mx_hi, fmaxf(sv[j][2], sv[j][3]));
        }
#pragma unroll
        for (int o = 1; o < 4; o <<= 1) {
            mx_lo = fmaxf(mx_lo, __shfl_xor_sync(0xffffffffu, mx_lo, o));
            mx_hi = fmaxf(mx_hi, __shfl_xor_sync(0xffffffffu, mx_hi, o));
        }
        if (tig == 0) { red[wn * 64 + row_lo] = mx_lo; red[wn * 64 + row_hi] = mx_hi; }
        __syncthreads();

        float mo_lo = mst[row_lo], mo_hi = mst[row_hi];
        float mn_lo = fmaxf(mo_lo, fmaxf(red[row_lo], red[64 + row_lo]));
        float mn_hi = fmaxf(mo_hi, fmaxf(red[row_hi], red[64 + row_hi]));
        float al_lo = __expf(mo_lo - mn_lo);
        float al_hi = __expf(mo_hi - mn_hi);
        __syncthreads();
        if (writer) { mst[row_lo] = mn_lo; mst[row_hi] = mn_hi; }

        // ---- p = exp(s - m_new) -> pt (fp16); rowsum ----
        float sm_lo = 0.f, sm_hi = 0.f;
#pragma unroll
        for (int j = 0; j < 7; j++) {
            float p0 = __expf(sv[j][0] - mn_lo);
            float p1 = __expf(sv[j][1] - mn_lo);
            float p2 = __expf(sv[j][2] - mn_hi);
            float p3 = __expf(sv[j][3] - mn_hi);
            sm_lo += p0 + p1; sm_hi += p2 + p3;
            int col = ncol + j * 8 + 2 * tig;
            *reinterpret_cast<half2*>(&pt[row_lo * KSTRH + col]) = __floats2half2_rn(p0, p1);
            *reinterpret_cast<half2*>(&pt[row_hi * KSTRH + col]) = __floats2half2_rn(p2, p3);
        }
#pragma unroll
        for (int o = 1; o < 4; o <<= 1) {
            sm_lo += __shfl_xor_sync(0xffffffffu, sm_lo, o);
            sm_hi += __shfl_xor_sync(0xffffffffu, sm_hi, o);
        }
        if (tig == 0) { red[wn * 64 + row_lo] = sm_lo; red[wn * 64 + row_hi] = sm_hi; }
        __syncthreads();

        if (writer) {
            lst[row_lo] = lst[row_lo] * al_lo + red[row_lo] + red[64 + row_lo];
            lst[row_hi] = lst[row_hi] * al_hi + red[row_hi] + red[64 + row_hi];
        }
#pragma unroll
        for (int i = 0; i < 3; i++) {
            o_acc[i][0] *= al_lo; o_acc[i][1] *= al_lo;
            o_acc[i][2] *= al_hi; o_acc[i][3] *= al_hi;
        }

        // ---- PV: warp tile 16m x 24c, k = 112 keys ----
        int cn = wn * 24;
#pragma unroll
        for (int kk = 0; kk < FTN; kk += 16) {
            unsigned af[4];
            ldsm4(af, &pt[(wm + l16) * KSTRH + kk + lh]);
#pragma unroll
            for (int ni = 0; ni < 3; ni++) {
                unsigned bf[2];
                bf[0] = *reinterpret_cast<const unsigned*>(&vts[(cn + ni * 8 + g) * KSTRH + kk + 2 * tig]);
                bf[1] = *reinterpret_cast<const unsigned*>(&vts[(cn + ni * 8 + g) * KSTRH + kk + 8 + 2 * tig]);
                mma16(o_acc[ni], af, bf);
            }
        }
        s ^= 1;
    }
    __syncthreads();

    // ---- epilogue: out = acc / l  (fp16) ----
    float il_lo = 1.f / lst[row_lo];
    float il_hi = 1.f / lst[row_hi];
    int cn = wn * 24;
#pragma unroll
    for (int ni = 0; ni < 3; ni++) {
        int cc = cn + ni * 8 + 2 * tig;
        op[(size_t)cc * HWSZ + m0 + row_lo]       = __float2half_rn(o_acc[ni][0] * il_lo);
        op[(size_t)(cc + 1) * HWSZ + m0 + row_lo] = __float2half_rn(o_acc[ni][1] * il_lo);
        op[(size_t)cc * HWSZ + m0 + row_hi]       = __float2half_rn(o_acc[ni][2] * il_hi);
        op[(size_t)(cc + 1) * HWSZ + m0 + row_hi] = __float2half_rn(o_acc[ni][3] * il_hi);
    }
}

// ---------------------------------------------------------------------------
extern "C" void kernel_launch(void* const* d_in, const int* in_sizes, int n_in,
                              void* d_out, int out_size)
{
    const float* x   = (const float*)d_in[0];
    const float* Wq  = (const float*)d_in[1];
    const float* bq  = (const float*)d_in[2];
    const float* Wk  = (const float*)d_in[3];
    const float* bk  = (const float*)d_in[4];
    const float* Wv  = (const float*)d_in[5];
    const float* bv  = (const float*)d_in[6];
    const float* Wo  = (const float*)d_in[7];
    const float* bo  = (const float*)d_in[8];
    const float* dww = (const float*)d_in[9];
    const float* dwb = (const float*)d_in[10];
    const float* lng = (const float*)d_in[11];
    const float* lnb = (const float*)d_in[12];
    const float* pww = (const float*)d_in[13];
    float* out = (float*)d_out;

    float *q, *pos;
    __half *xh, *atth, *xsh, *kh, *vh, *wh;
    cudaGetSymbolAddress((void**)&q,    g_q);
    cudaGetSymbolAddress((void**)&pos,  g_pos);
    cudaGetSymbolAddress((void**)&xh,   g_xh);
    cudaGetSymbolAddress((void**)&atth, g_atth);
    cudaGetSymbolAddress((void**)&xsh,  g_xsh);
    cudaGetSymbolAddress((void**)&kh,   g_kh);
    cudaGetSymbolAddress((void**)&vh,   g_vh);
    cudaGetSymbolAddress((void**)&wh,   g_wh);

    __half* whq = wh;
    __half* whk = wh + NCH * NCH;
    __half* whv = wh + 2 * NCH * NCH;
    __half* who = wh + 3 * NCH * NCH;

    cudaFuncSetAttribute(attention_h, cudaFuncAttributeMaxDynamicSharedMemorySize, F_SMEM);

    // 0) fp16 conversions
    to_half4<<<(YSZ / 4 + 255) / 256, 256>>>(x, xh, YSZ / 4);
    to_half4<<<(NCH*NCH/4 + 255) / 256, 256>>>(Wq, whq, NCH*NCH/4);
    to_half4<<<(NCH*NCH/4 + 255) / 256, 256>>>(Wk, whk, NCH*NCH/4);
    to_half4<<<(NCH*NCH/4 + 255) / 256, 256>>>(Wv, whv, NCH*NCH/4);
    to_half4<<<(NCH*NCH/4 + 255) / 256, 256>>>(Wo, who, NCH*NCH/4);

    dim3 gbig((HWSZ + 127) / 128, 3, BATCH);   // 25 x 3 x 8
    dim3 gkv((NKV + 127) / 128, 6, BATCH);     // 7 x 6 x 8 (k + v fused)

    // 1) q = Wq x + bq (fp32 out, needed by offset net)
    gemm_h<false><<<gbig, 256>>>(whq, nullptr, bq, nullptr, xh, q, nullptr, NCH, HWSZ);
    // 2) offset net -> pos
    offset_net<<<BATCH * NG * NKV, 128>>>(q, dww, dwb, lng, lnb, pww,
                                          pos, out + YSZ, out + YSZ + PSZ);
    // 3) grid sample -> xs (fp16)
    grid_sample_k<<<dim3((GC * NKV) / 256, BATCH * NG), 256>>>(x, pos, xsh);
    // 4) k and v in one launch (fp16 out)
    gemm_h<true><<<gkv, 256>>>(whk, whv, bk, bv, xsh, kh, vh, NCH, NKV);
    // 5) flash attention -> atth (fp16)
    attention_h<<<dim3(HWSZ / FTM, BATCH * NH), 256, F_SMEM>>>(q, kh, vh, atth);
    // 6) y = Wo att + bo (fp32 -> d_out)
    gemm_h<false><<<gbig, 256>>>(who, nullptr, bo, nullptr, atth, out, nullptr, NCH, HWSZ);
}

// round 8
// speedup vs baseline: 9.3032x; 1.2161x over previous
#include <cuda_runtime.h>
#include <cuda_fp16.h>
#include <math.h>

// Problem constants
#define BATCH 8
#define NCH   384
#define HH    56
#define WW    56
#define HWSZ  3136      // 56*56
#define NKV   784       // 28*28
#define HK    28
#define NG    4
#define GC    96
#define NH    8
#define HC    48

#define YSZ   (BATCH*NCH*HWSZ)     // 9633792
#define PSZ   (BATCH*NG*NKV*2)     // 50176

// Scratch (allocation-free rule: __device__ globals)
static __device__ float  g_q   [BATCH*NCH*HWSZ];
static __device__ __half g_xh  [BATCH*NCH*HWSZ];
static __device__ __half g_atth[BATCH*NCH*HWSZ];
static __device__ __half g_xsh [BATCH*NCH*NKV];
static __device__ __half g_kh  [BATCH*NCH*NKV];
static __device__ __half g_vh  [BATCH*NCH*NKV];
static __device__ __half g_wh  [4*NCH*NCH];     // Wq, Wk, Wv, Wo fp16
static __device__ float  g_pos [BATCH*NG*NKV*2];

// ---------------------------------------------------------------------------
// mma / ldmatrix / cp.async helpers
// ---------------------------------------------------------------------------
__device__ __forceinline__ void mma16(float* d, const unsigned* a, const unsigned* b) {
    asm("mma.sync.aligned.m16n8k16.row.col.f32.f16.f16.f32 "
        "{%0,%1,%2,%3}, {%4,%5,%6,%7}, {%8,%9}, {%0,%1,%2,%3};"
        : "+f"(d[0]), "+f"(d[1]), "+f"(d[2]), "+f"(d[3])
        : "r"(a[0]), "r"(a[1]), "r"(a[2]), "r"(a[3]), "r"(b[0]), "r"(b[1]));
}
__device__ __forceinline__ void ldsm4(unsigned* r, const __half* p) {
    unsigned addr = (unsigned)__cvta_generic_to_shared(p);
    asm volatile("ldmatrix.sync.aligned.m8n8.x4.shared.b16 {%0,%1,%2,%3}, [%4];"
                 : "=r"(r[0]), "=r"(r[1]), "=r"(r[2]), "=r"(r[3]) : "r"(addr));
}
__device__ __forceinline__ void ldsm4t(unsigned* r, const __half* p) {
    unsigned addr = (unsigned)__cvta_generic_to_shared(p);
    asm volatile("ldmatrix.sync.aligned.m8n8.x4.trans.shared.b16 {%0,%1,%2,%3}, [%4];"
                 : "=r"(r[0]), "=r"(r[1]), "=r"(r[2]), "=r"(r[3]) : "r"(addr));
}
__device__ __forceinline__ void cpa16(const __half* dst, const __half* src, bool pred) {
    unsigned d = (unsigned)__cvta_generic_to_shared(dst);
    int sz = pred ? 16 : 0;
    asm volatile("cp.async.cg.shared.global [%0], [%1], 16, %2;"
                 :: "r"(d), "l"(src), "r"(sz));
}
#define CPA_COMMIT() asm volatile("cp.async.commit_group;")
#define CPA_WAIT1()  asm volatile("cp.async.wait_group 1;")
#define CPA_WAIT0()  asm volatile("cp.async.wait_group 0;")

// ---------------------------------------------------------------------------
// fp32 -> fp16 conversions
// ---------------------------------------------------------------------------
__global__ __launch_bounds__(256)
void to_half4(const float* __restrict__ src, __half* __restrict__ dst, int n4)
{
    int i = blockIdx.x * 256 + threadIdx.x;
    if (i < n4) {
        float4 f = reinterpret_cast<const float4*>(src)[i];
        reinterpret_cast<half2*>(dst)[2*i]   = __floats2half2_rn(f.x, f.y);
        reinterpret_cast<half2*>(dst)[2*i+1] = __floats2half2_rn(f.z, f.w);
    }
}

// all 4 weight matrices in one launch
#define WN4 (NCH*NCH/4)   // 36864
__global__ __launch_bounds__(256)
void w_to_half(const float* __restrict__ Wq, const float* __restrict__ Wk,
               const float* __restrict__ Wv, const float* __restrict__ Wo,
               __half* __restrict__ wh)
{
    int i = blockIdx.x * 256 + threadIdx.x;      // < 4*WN4
    int m = i / WN4, r = i - m * WN4;
    const float* src = (m == 0) ? Wq : (m == 1) ? Wk : (m == 2) ? Wv : Wo;
    float4 f = reinterpret_cast<const float4*>(src)[r];
    half2* dst = reinterpret_cast<half2*>(wh + (size_t)m * NCH * NCH);
    dst[2*r]   = __floats2half2_rn(f.x, f.y);
    dst[2*r+1] = __floats2half2_rn(f.z, f.w);
}

// ---------------------------------------------------------------------------
// fp16 GEMM: C[z] = A(384xK) * B[z](KxN) + bias  (unchanged from R7)
// ---------------------------------------------------------------------------
#define ASTRH 40     // halves per A row (32 + 8 pad)
#define BSTRH 136    // halves per B row (128 + 8 pad)

template<bool OUTH>
__global__ __launch_bounds__(256)
void gemm_h(const __half* __restrict__ A0, const __half* __restrict__ A1,
            const float* __restrict__ bias0, const float* __restrict__ bias1,
            const __half* __restrict__ Bsrc,
            void* __restrict__ C0, void* __restrict__ C1,
            int K, int N)
{
    __shared__ __half As[2][128 * ASTRH];
    __shared__ __half Bs[2][32 * BSTRH];

    bool sel = (A1 != nullptr) && (blockIdx.y >= 3);
    const __half* A    = sel ? A1 : A0;
    const float*  bias = sel ? bias1 : bias0;
    void*         Cv   = sel ? C1 : C0;

    const __half* Bp = Bsrc + (size_t)blockIdx.z * K * N;
    int m0 = (blockIdx.y % 3) * 128, n0 = blockIdx.x * 128;
    int tid = threadIdx.x;
    int wid = tid >> 5, lane = tid & 31;
    int g = lane >> 2, tig = lane & 3;
    int wm = (wid & 1) * 64;
    int wn = (wid >> 1) * 32;
    int l16 = lane & 15, lh = (lane >> 4) * 8;

    int ar = tid >> 1, ac = (tid & 1) * 16;
    int br = tid >> 3, bc = (tid & 7) * 16;

    float acc[4][4][4];
#pragma unroll
    for (int i = 0; i < 4; i++)
#pragma unroll
        for (int j = 0; j < 4; j++)
#pragma unroll
            for (int r = 0; r < 4; r++) acc[i][j][r] = 0.f;

    auto issue = [&](int s, int k0) {
        const __half* asrc = A + (size_t)(m0 + ar) * K + k0 + ac;
        cpa16(&As[s][ar * ASTRH + ac], asrc, true);
        cpa16(&As[s][ar * ASTRH + ac + 8], asrc + 8, true);
        const __half* bsrc = Bp + (size_t)(k0 + br) * N + n0 + bc;
        cpa16(&Bs[s][br * BSTRH + bc], bsrc, n0 + bc < N);
        cpa16(&Bs[s][br * BSTRH + bc + 8], bsrc + 8, n0 + bc + 8 < N);
    };

    issue(0, 0);
    CPA_COMMIT();

    int s = 0;
    for (int k0 = 0; k0 < K; k0 += 32, s ^= 1) {
        if (k0 + 32 < K) issue(s ^ 1, k0 + 32);
        CPA_COMMIT();
        CPA_WAIT1();
        __syncthreads();
#pragma unroll
        for (int kk = 0; kk < 32; kk += 16) {
            unsigned af[4][4], bf[4][2];
#pragma unroll
            for (int mf = 0; mf < 4; mf++)
                ldsm4(af[mf], &As[s][(wm + mf * 16 + l16) * ASTRH + kk + lh]);
#pragma unroll
            for (int nf = 0; nf < 4; nf += 2) {
                unsigned t4[4];
                ldsm4t(t4, &Bs[s][(kk + l16) * BSTRH + wn + nf * 8 + lh]);
                bf[nf][0] = t4[0]; bf[nf][1] = t4[1];
                bf[nf+1][0] = t4[2]; bf[nf+1][1] = t4[3];
            }
#pragma unroll
            for (int mf = 0; mf < 4; mf++)
#pragma unroll
                for (int nf = 0; nf < 4; nf++)
                    mma16(acc[mf][nf], af[mf], bf[nf]);
        }
        __syncthreads();
    }

#pragma unroll
    for (int mf = 0; mf < 4; mf++) {
        int r0 = m0 + wm + mf * 16 + g;
        int r1 = r0 + 8;
        float bv0 = bias[r0], bv1 = bias[r1];
#pragma unroll
        for (int nf = 0; nf < 4; nf++) {
            int cn = n0 + wn + nf * 8 + 2 * tig;
            if (cn < N) {
                if (OUTH) {
                    __half* Ch = (__half*)Cv + (size_t)blockIdx.z * 384 * N;
                    *reinterpret_cast<half2*>(&Ch[(size_t)r0 * N + cn]) =
                        __floats2half2_rn(acc[mf][nf][0] + bv0, acc[mf][nf][1] + bv0);
                    *reinterpret_cast<half2*>(&Ch[(size_t)r1 * N + cn]) =
                        __floats2half2_rn(acc[mf][nf][2] + bv1, acc[mf][nf][3] + bv1);
                } else {
                    float* Cf = (float*)Cv + (size_t)blockIdx.z * 384 * N;
                    *reinterpret_cast<float2*>(&Cf[(size_t)r0 * N + cn]) =
                        make_float2(acc[mf][nf][0] + bv0, acc[mf][nf][1] + bv0);
                    *reinterpret_cast<float2*>(&Cf[(size_t)r1 * N + cn]) =
                        make_float2(acc[mf][nf][2] + bv1, acc[mf][nf][3] + bv1);
                }
            }
        }
    }
}

// ---------------------------------------------------------------------------
// Offset network v2: one warp per output position, 3 channels per lane,
// all reductions via shuffles (zero __syncthreads).
// ---------------------------------------------------------------------------
__device__ __forceinline__ float wsum(float v) {
#pragma unroll
    for (int o = 16; o > 0; o >>= 1) v += __shfl_xor_sync(0xffffffffu, v, o);
    return v;
}

__global__ __launch_bounds__(256)
void offset_net(const float* __restrict__ q,
                const float* __restrict__ dw_w, const float* __restrict__ dw_b,
                const float* __restrict__ ln_g, const float* __restrict__ ln_b,
                const float* __restrict__ pw_w,
                float* __restrict__ pos, float* __restrict__ pos_out,
                float* __restrict__ ref_out)
{
    int warp = threadIdx.x >> 5, lane = threadIdx.x & 31;
    int p = blockIdx.x * 8 + warp;          // 0 .. 25087
    int bg = p / NKV;
    int ij = p - bg * NKV;
    int i = ij / HK, j = ij - i * HK;
    int b = bg >> 2, g = bg & 3;

    float h[3];
    int y0 = 2 * i - 1, x0 = 2 * j - 1;
#pragma unroll
    for (int e = 0; e < 3; e++) {
        int c = lane * 3 + e;
        const float* qc = q + ((size_t)(b * NCH + g * GC + c)) * HWSZ;
        const float* w = dw_w + c * 9;
        float acc = dw_b[c];
#pragma unroll
        for (int ky = 0; ky < 3; ky++) {
            int y = y0 + ky;
            if (y < 0 || y >= HH) continue;
#pragma unroll
            for (int kx = 0; kx < 3; kx++) {
                int x = x0 + kx;
                if (x < 0 || x >= WW) continue;
                acc += w[ky * 3 + kx] * qc[y * WW + x];
            }
        }
        h[e] = acc;
    }
    float mu = wsum(h[0] + h[1] + h[2]) * (1.f / GC);
    float d0 = h[0] - mu, d1 = h[1] - mu, d2 = h[2] - mu;
    float var = wsum(d0 * d0 + d1 * d1 + d2 * d2) * (1.f / GC);
    float inv = rsqrtf(var + 1e-5f);

    float hn[3] = {d0 * inv, d1 * inv, d2 * inv};
    float py_p = 0.f, px_p = 0.f;
#pragma unroll
    for (int e = 0; e < 3; e++) {
        int c = lane * 3 + e;
        float v = hn[e] * ln_g[c] + ln_b[c];
        v = 0.5f * v * (1.f + erff(v * 0.70710678118654752f));   // exact GELU
        py_p += pw_w[c] * v;
        px_p += pw_w[GC + c] * v;
    }
    float offy = wsum(py_p);
    float offx = wsum(px_p);

    if (lane == 0) {
        float ry = (0.5f + (float)i) * (1.f / 27.f) * 2.f - 1.f;
        float rx = (0.5f + (float)j) * (1.f / 27.f) * 2.f - 1.f;
        float py = tanhf(offy) * (1.f / 27.f) + ry;
        float px = tanhf(offx) * (1.f / 27.f) + rx;
        size_t o = ((size_t)bg * NKV + ij) * 2;
        pos[o] = py;     pos[o + 1] = px;
        pos_out[o] = py; pos_out[o + 1] = px;
        ref_out[o] = ry; ref_out[o + 1] = rx;
    }
}

// ---------------------------------------------------------------------------
// Bilinear grid sample -> fp16 xs (unchanged)
// ---------------------------------------------------------------------------
__global__ __launch_bounds__(256)
void grid_sample_k(const float* __restrict__ x, const float* __restrict__ pos,
                   __half* __restrict__ xs)
{
    int bg = blockIdx.y;
    int b = bg >> 2, g = bg & 3;
    int idx = blockIdx.x * 256 + threadIdx.x;
    int c = idx / NKV, p = idx - c * NKV;

    float py = pos[((size_t)bg * NKV + p) * 2];
    float px = pos[((size_t)bg * NKV + p) * 2 + 1];
    float gx = (px + 1.f) * 0.5f * (WW - 1);
    float gy = (py + 1.f) * 0.5f * (HH - 1);
    float x0f = floorf(gx), y0f = floorf(gy);
    int x0 = (int)x0f, y0 = (int)y0f;
    float wx1 = gx - x0f, wx0 = 1.f - wx1;
    float wy1 = gy - y0f, wy0 = 1.f - wy1;

    const float* img = x + ((size_t)(b * NCH + g * GC + c)) * HWSZ;

    float v00 = 0.f, v01 = 0.f, v10 = 0.f, v11 = 0.f;
    bool xv0 = (x0 >= 0) && (x0 < WW);
    bool xv1 = (x0 + 1 >= 0) && (x0 + 1 < WW);
    bool yv0 = (y0 >= 0) && (y0 < HH);
    bool yv1 = (y0 + 1 >= 0) && (y0 + 1 < HH);
    if (xv0 && yv0) v00 = img[y0 * WW + x0];
    if (xv1 && yv0) v01 = img[y0 * WW + x0 + 1];
    if (xv0 && yv1) v10 = img[(y0 + 1) * WW + x0];
    if (xv1 && yv1) v11 = img[(y0 + 1) * WW + x0 + 1];

    float acc = v00 * wx0 * wy0 + v01 * wx1 * wy0 + v10 * wx0 * wy1 + v11 * wx1 * wy1;
    xs[((size_t)(b * NCH + g * GC + c)) * NKV + p] = __float2half_rn(acc);
}

// ---------------------------------------------------------------------------
// Flash attention v2: 4 warps/block, each warp owns 16 query rows x ALL keys.
// m/l state in registers, pt warp-private, quad-shuffle softmax, no
// inter-warp softmax barriers. Double-buffered cp.async K/V.
// ---------------------------------------------------------------------------
#define FTM 64
#define FTN 112
#define QSTRH 56     // 48 + 8 pad
#define KSTRH 120    // 112 + 8 pad
// halves: qs 64*56=3584 + kt 2*48*120=11520 + vt 11520 + pt 64*120=7680 = 34304
#define F_SMEM (34304 * 2)

__global__ __launch_bounds__(128)
void attention_h(const float* __restrict__ q, const __half* __restrict__ k,
                 const __half* __restrict__ v, __half* __restrict__ out)
{
    extern __shared__ char smraw[];
    __half* qs = (__half*)smraw;                    // [m][c]    64 x QSTRH
    __half* kt = qs + FTM * QSTRH;                  // [2][c][n] 48 x KSTRH
    __half* vt = kt + 2 * HC * KSTRH;
    __half* pt = vt + 2 * HC * KSTRH;               // [m][n]    64 x KSTRH

    int head = blockIdx.y;
    int b = head >> 3, hh = head & 7;
    const float*  qp = q + ((size_t)(b * NCH + hh * HC)) * HWSZ;
    const __half* kp = k + ((size_t)(b * NCH + hh * HC)) * NKV;
    const __half* vp = v + ((size_t)(b * NCH + hh * HC)) * NKV;
    __half*       op = out + ((size_t)(b * NCH + hh * HC)) * HWSZ;
    int m0 = blockIdx.x * FTM;
    int tid = threadIdx.x;
    int wid = tid >> 5, lane = tid & 31;
    int g = lane >> 2, tig = lane & 3;
    int l16 = lane & 15, lh = (lane >> 4) * 8;
    int wm = wid * 16;
    const float scale = 0.14433756729740643f;       // 1/sqrt(48)

    int row_lo = wm + g, row_hi = wm + g + 8;

    // stage Q (fp32 -> fp16)
    for (int idx = tid; idx < HC * FTM; idx += 128) {
        int c = idx >> 6, m = idx & 63;
        qs[m * QSTRH + c] = __float2half_rn(qp[(size_t)c * HWSZ + m0 + m]);
    }

    // stage K/V tile into buffer s (cp.async)
    auto stage_kv = [&](int s, int n0) {
        __half* kd = kt + s * HC * KSTRH;
        __half* vd = vt + s * HC * KSTRH;
        for (int it = tid; it < 1344; it += 128) {
            int tsel = it / 672;
            int rid = it - tsel * 672;
            int c = rid / 14, gc = (rid - c * 14) * 8;
            const __half* src = (tsel ? vp : kp) + (size_t)c * NKV + n0 + gc;
            cpa16((tsel ? vd : kd) + c * KSTRH + gc, src, true);
        }
    };

    stage_kv(0, 0);
    CPA_COMMIT();

    float m_lo = -1e30f, m_hi = -1e30f, l_lo = 0.f, l_hi = 0.f;
    float o_acc[6][4];
#pragma unroll
    for (int i = 0; i < 6; i++)
#pragma unroll
        for (int r = 0; r < 4; r++) o_acc[i][r] = 0.f;

    int s = 0;
    for (int t = 0; t < 7; t++) {
        CPA_WAIT0();
        __syncthreads();
        const __half* kts = kt + s * HC * KSTRH;
        const __half* vts = vt + s * HC * KSTRH;

        // ---- S = Q^T K : warp tile 16 x 112 (raw, scale folded into exp) ----
        float sv[14][4];
#pragma unroll
        for (int j = 0; j < 14; j++)
#pragma unroll
            for (int r = 0; r < 4; r++) sv[j][r] = 0.f;
#pragma unroll
        for (int kk = 0; kk < HC; kk += 16) {
            unsigned af[4];
            ldsm4(af, &qs[(wm + l16) * QSTRH + kk + lh]);
#pragma unroll
            for (int j16 = 0; j16 < 7; j16++) {
                unsigned t4[4];
                ldsm4t(t4, &kts[(kk + l16) * KSTRH + j16 * 16 + lh]);
                mma16(sv[2 * j16],     af, t4);
                mma16(sv[2 * j16 + 1], af, t4 + 2);
            }
        }

        // prefetch next K/V tile (overlaps softmax + PV)
        if (t < 6) stage_kv(s ^ 1, (t + 1) * FTN);
        CPA_COMMIT();

        // ---- row max (raw), quad shuffle ----
        float mx_lo = -1e30f, mx_hi = -1e30f;
#pragma unroll
        for (int j = 0; j < 14; j++) {
            mx_lo = fmaxf(mx_lo, fmaxf(sv[j][0], sv[j][1]));
            mx_hi = fmaxf(mx_hi, fmaxf(sv[j][2], sv[j][3]));
        }
#pragma unroll
        for (int o = 1; o < 4; o <<= 1) {
            mx_lo = fmaxf(mx_lo, __shfl_xor_sync(0xffffffffu, mx_lo, o));
            mx_hi = fmaxf(mx_hi, __shfl_xor_sync(0xffffffffu, mx_hi, o));
        }
        float mn_lo = fmaxf(m_lo, mx_lo * scale);
        float mn_hi = fmaxf(m_hi, mx_hi * scale);
        float al_lo = __expf(m_lo - mn_lo);
        float al_hi = __expf(m_hi - mn_hi);
        m_lo = mn_lo; m_hi = mn_hi;

        // ---- p = exp(scale*s - m) -> pt (warp-private); rowsum ----
        float sm_lo = 0.f, sm_hi = 0.f;
#pragma unroll
        for (int j = 0; j < 14; j++) {
            float p0 = __expf(fmaf(sv[j][0], scale, -mn_lo));
            float p1 = __expf(fmaf(sv[j][1], scale, -mn_lo));
            float p2 = __expf(fmaf(sv[j][2], scale, -mn_hi));
            float p3 = __expf(fmaf(sv[j][3], scale, -mn_hi));
            sm_lo += p0 + p1; sm_hi += p2 + p3;
            int col = j * 8 + 2 * tig;
            *reinterpret_cast<half2*>(&pt[row_lo * KSTRH + col]) = __floats2half2_rn(p0, p1);
            *reinterpret_cast<half2*>(&pt[row_hi * KSTRH + col]) = __floats2half2_rn(p2, p3);
        }
#pragma unroll
        for (int o = 1; o < 4; o <<= 1) {
            sm_lo += __shfl_xor_sync(0xffffffffu, sm_lo, o);
            sm_hi += __shfl_xor_sync(0xffffffffu, sm_hi, o);
        }
        l_lo = l_lo * al_lo + sm_lo;
        l_hi = l_hi * al_hi + sm_hi;
#pragma unroll
        for (int i = 0; i < 6; i++) {
            o_acc[i][0] *= al_lo; o_acc[i][1] *= al_lo;
            o_acc[i][2] *= al_hi; o_acc[i][3] *= al_hi;
        }
        __syncwarp();

        // ---- PV: warp tile 16m x 48c, k = 112 keys ----
#pragma unroll
        for (int kk = 0; kk < 7; kk++) {
            unsigned af[4];
            ldsm4(af, &pt[(wm + l16) * KSTRH + kk * 16 + lh]);
#pragma unroll
            for (int ci = 0; ci < 6; ci++) {
                unsigned bf[2];
                bf[0] = *reinterpret_cast<const unsigned*>(&vts[(ci * 8 + g) * KSTRH + kk * 16 + 2 * tig]);
                bf[1] = *reinterpret_cast<const unsigned*>(&vts[(ci * 8 + g) * KSTRH + kk * 16 + 8 + 2 * tig]);
                mma16(o_acc[ci], af, bf);
            }
        }
        s ^= 1;
    }

    // ---- epilogue: out = acc / l  (fp16) ----
    float il_lo = 1.f / l_lo;
    float il_hi = 1.f / l_hi;
#pragma unroll
    for (int ci = 0; ci < 6; ci++) {
        int cc = ci * 8 + 2 * tig;
        op[(size_t)cc * HWSZ + m0 + row_lo]       = __float2half_rn(o_acc[ci][0] * il_lo);
        op[(size_t)(cc + 1) * HWSZ + m0 + row_lo] = __float2half_rn(o_acc[ci][1] * il_lo);
        op[(size_t)cc * HWSZ + m0 + row_hi]       = __float2half_rn(o_acc[ci][2] * il_hi);
        op[(size_t)(cc + 1) * HWSZ + m0 + row_hi] = __float2half_rn(o_acc[ci][3] * il_hi);
    }
}

// ---------------------------------------------------------------------------
extern "C" void kernel_launch(void* const* d_in, const int* in_sizes, int n_in,
                              void* d_out, int out_size)
{
    const float* x   = (const float*)d_in[0];
    const float* Wq  = (const float*)d_in[1];
    const float* bq  = (const float*)d_in[2];
    const float* Wk  = (const float*)d_in[3];
    const float* bk  = (const float*)d_in[4];
    const float* Wv  = (const float*)d_in[5];
    const float* bv  = (const float*)d_in[6];
    const float* Wo  = (const float*)d_in[7];
    const float* bo  = (const float*)d_in[8];
    const float* dww = (const float*)d_in[9];
    const float* dwb = (const float*)d_in[10];
    const float* lng = (const float*)d_in[11];
    const float* lnb = (const float*)d_in[12];
    const float* pww = (const float*)d_in[13];
    float* out = (float*)d_out;

    float *q, *pos;
    __half *xh, *atth, *xsh, *kh, *vh, *wh;
    cudaGetSymbolAddress((void**)&q,    g_q);
    cudaGetSymbolAddress((void**)&pos,  g_pos);
    cudaGetSymbolAddress((void**)&xh,   g_xh);
    cudaGetSymbolAddress((void**)&atth, g_atth);
    cudaGetSymbolAddress((void**)&xsh,  g_xsh);
    cudaGetSymbolAddress((void**)&kh,   g_kh);
    cudaGetSymbolAddress((void**)&vh,   g_vh);
    cudaGetSymbolAddress((void**)&wh,   g_wh);

    __half* whq = wh;
    __half* whk = wh + NCH * NCH;
    __half* whv = wh + 2 * NCH * NCH;
    __half* who = wh + 3 * NCH * NCH;

    cudaFuncSetAttribute(attention_h, cudaFuncAttributeMaxDynamicSharedMemorySize, F_SMEM);

    // 0) fp16 conversions (x + all 4 weights fused)
    to_half4<<<(YSZ / 4 + 255) / 256, 256>>>(x, xh, YSZ / 4);
    w_to_half<<<(4 * WN4) / 256, 256>>>(Wq, Wk, Wv, Wo, wh);

    dim3 gbig((HWSZ + 127) / 128, 3, BATCH);   // 25 x 3 x 8
    dim3 gkv((NKV + 127) / 128, 6, BATCH);     // 7 x 6 x 8 (k + v fused)

    // 1) q = Wq x + bq (fp32 out, needed by offset net + attention)
    gemm_h<false><<<gbig, 256>>>(whq, nullptr, bq, nullptr, xh, q, nullptr, NCH, HWSZ);
    // 2) offset net -> pos (warp per position)
    offset_net<<<BATCH * NG * NKV / 8, 256>>>(q, dww, dwb, lng, lnb, pww,
                                              pos, out + YSZ, out + YSZ + PSZ);
    // 3) grid sample -> xs (fp16)
    grid_sample_k<<<dim3((GC * NKV) / 256, BATCH * NG), 256>>>(x, pos, xsh);
    // 4) k and v in one launch (fp16 out)
    gemm_h<true><<<gkv, 256>>>(whk, whv, bk, bv, xsh, kh, vh, NCH, NKV);
    // 5) flash attention -> atth (fp16)
    attention_h<<<dim3(HWSZ / FTM, BATCH * NH), 128, F_SMEM>>>(q, kh, vh, atth);
    // 6) y = Wo att + bo (fp32 -> d_out)
    gemm_h<false><<<gbig, 256>>>(who, nullptr, bo, nullptr, atth, out, nullptr, NCH, HWSZ);
}

// round 9
// speedup vs baseline: 11.5857x; 1.2453x over previous
#include <cuda_runtime.h>
#include <cuda_fp16.h>
#include <math.h>

// Problem constants
#define BATCH 8
#define NCH   384
#define HH    56
#define WW    56
#define HWSZ  3136      // 56*56
#define NKV   784       // 28*28
#define HK    28
#define NG    4
#define GC    96
#define NH    8
#define HC    48

#define YSZ   (BATCH*NCH*HWSZ)     // 9633792
#define PSZ   (BATCH*NG*NKV*2)     // 50176

// Scratch (allocation-free rule: __device__ globals)
static __device__ float  g_q   [BATCH*NCH*HWSZ];
static __device__ __half g_xh  [BATCH*NCH*HWSZ];
static __device__ __half g_atth[BATCH*NCH*HWSZ];
static __device__ __half g_xsh [BATCH*NCH*NKV];
static __device__ __half g_kh  [BATCH*NCH*NKV];
static __device__ __half g_vh  [BATCH*NCH*NKV];
static __device__ __half g_wh  [4*NCH*NCH];     // Wq, Wk, Wv, Wo fp16
static __device__ float  g_pos [BATCH*NG*NKV*2];

// ---------------------------------------------------------------------------
// mma / ldmatrix / cp.async helpers
// ---------------------------------------------------------------------------
__device__ __forceinline__ void mma16(float* d, const unsigned* a, const unsigned* b) {
    asm("mma.sync.aligned.m16n8k16.row.col.f32.f16.f16.f32 "
        "{%0,%1,%2,%3}, {%4,%5,%6,%7}, {%8,%9}, {%0,%1,%2,%3};"
        : "+f"(d[0]), "+f"(d[1]), "+f"(d[2]), "+f"(d[3])
        : "r"(a[0]), "r"(a[1]), "r"(a[2]), "r"(a[3]), "r"(b[0]), "r"(b[1]));
}
__device__ __forceinline__ void ldsm4(unsigned* r, const __half* p) {
    unsigned addr = (unsigned)__cvta_generic_to_shared(p);
    asm volatile("ldmatrix.sync.aligned.m8n8.x4.shared.b16 {%0,%1,%2,%3}, [%4];"
                 : "=r"(r[0]), "=r"(r[1]), "=r"(r[2]), "=r"(r[3]) : "r"(addr));
}
__device__ __forceinline__ void ldsm4t(unsigned* r, const __half* p) {
    unsigned addr = (unsigned)__cvta_generic_to_shared(p);
    asm volatile("ldmatrix.sync.aligned.m8n8.x4.trans.shared.b16 {%0,%1,%2,%3}, [%4];"
                 : "=r"(r[0]), "=r"(r[1]), "=r"(r[2]), "=r"(r[3]) : "r"(addr));
}
__device__ __forceinline__ void cpa16(const __half* dst, const __half* src, bool pred) {
    unsigned d = (unsigned)__cvta_generic_to_shared(dst);
    int sz = pred ? 16 : 0;
    asm volatile("cp.async.cg.shared.global [%0], [%1], 16, %2;"
                 :: "r"(d), "l"(src), "r"(sz));
}
#define CPA_COMMIT() asm volatile("cp.async.commit_group;")
#define CPA_WAIT1()  asm volatile("cp.async.wait_group 1;")
#define CPA_WAIT0()  asm volatile("cp.async.wait_group 0;")

// ---------------------------------------------------------------------------
// fp32 -> fp16 conversions
// ---------------------------------------------------------------------------
__global__ __launch_bounds__(256)
void to_half4(const float* __restrict__ src, __half* __restrict__ dst, int n4)
{
    int i = blockIdx.x * 256 + threadIdx.x;
    if (i < n4) {
        float4 f = reinterpret_cast<const float4*>(src)[i];
        reinterpret_cast<half2*>(dst)[2*i]   = __floats2half2_rn(f.x, f.y);
        reinterpret_cast<half2*>(dst)[2*i+1] = __floats2half2_rn(f.z, f.w);
    }
}

// all 4 weight matrices in one launch
#define WN4 (NCH*NCH/4)   // 36864
__global__ __launch_bounds__(256)
void w_to_half(const float* __restrict__ Wq, const float* __restrict__ Wk,
               const float* __restrict__ Wv, const float* __restrict__ Wo,
               __half* __restrict__ wh)
{
    int i = blockIdx.x * 256 + threadIdx.x;      // < 4*WN4
    int m = i / WN4, r = i - m * WN4;
    const float* src = (m == 0) ? Wq : (m == 1) ? Wk : (m == 2) ? Wv : Wo;
    float4 f = reinterpret_cast<const float4*>(src)[r];
    half2* dst = reinterpret_cast<half2*>(wh + (size_t)m * NCH * NCH);
    dst[2*r]   = __floats2half2_rn(f.x, f.y);
    dst[2*r+1] = __floats2half2_rn(f.z, f.w);
}

// ---------------------------------------------------------------------------
// fp16 GEMM: C[z] = A(384xK) * B[z](KxN) + bias  (unchanged)
// ---------------------------------------------------------------------------
#define ASTRH 40     // halves per A row (32 + 8 pad)
#define BSTRH 136    // halves per B row (128 + 8 pad)

template<bool OUTH>
__global__ __launch_bounds__(256)
void gemm_h(const __half* __restrict__ A0, const __half* __restrict__ A1,
            const float* __restrict__ bias0, const float* __restrict__ bias1,
            const __half* __restrict__ Bsrc,
            void* __restrict__ C0, void* __restrict__ C1,
            int K, int N)
{
    __shared__ __half As[2][128 * ASTRH];
    __shared__ __half Bs[2][32 * BSTRH];

    bool sel = (A1 != nullptr) && (blockIdx.y >= 3);
    const __half* A    = sel ? A1 : A0;
    const float*  bias = sel ? bias1 : bias0;
    void*         Cv   = sel ? C1 : C0;

    const __half* Bp = Bsrc + (size_t)blockIdx.z * K * N;
    int m0 = (blockIdx.y % 3) * 128, n0 = blockIdx.x * 128;
    int tid = threadIdx.x;
    int wid = tid >> 5, lane = tid & 31;
    int g = lane >> 2, tig = lane & 3;
    int wm = (wid & 1) * 64;
    int wn = (wid >> 1) * 32;
    int l16 = lane & 15, lh = (lane >> 4) * 8;

    int ar = tid >> 1, ac = (tid & 1) * 16;
    int br = tid >> 3, bc = (tid & 7) * 16;

    float acc[4][4][4];
#pragma unroll
    for (int i = 0; i < 4; i++)
#pragma unroll
        for (int j = 0; j < 4; j++)
#pragma unroll
            for (int r = 0; r < 4; r++) acc[i][j][r] = 0.f;

    auto issue = [&](int s, int k0) {
        const __half* asrc = A + (size_t)(m0 + ar) * K + k0 + ac;
        cpa16(&As[s][ar * ASTRH + ac], asrc, true);
        cpa16(&As[s][ar * ASTRH + ac + 8], asrc + 8, true);
        const __half* bsrc = Bp + (size_t)(k0 + br) * N + n0 + bc;
        cpa16(&Bs[s][br * BSTRH + bc], bsrc, n0 + bc < N);
        cpa16(&Bs[s][br * BSTRH + bc + 8], bsrc + 8, n0 + bc + 8 < N);
    };

    issue(0, 0);
    CPA_COMMIT();

    int s = 0;
    for (int k0 = 0; k0 < K; k0 += 32, s ^= 1) {
        if (k0 + 32 < K) issue(s ^ 1, k0 + 32);
        CPA_COMMIT();
        CPA_WAIT1();
        __syncthreads();
#pragma unroll
        for (int kk = 0; kk < 32; kk += 16) {
            unsigned af[4][4], bf[4][2];
#pragma unroll
            for (int mf = 0; mf < 4; mf++)
                ldsm4(af[mf], &As[s][(wm + mf * 16 + l16) * ASTRH + kk + lh]);
#pragma unroll
            for (int nf = 0; nf < 4; nf += 2) {
                unsigned t4[4];
                ldsm4t(t4, &Bs[s][(kk + l16) * BSTRH + wn + nf * 8 + lh]);
                bf[nf][0] = t4[0]; bf[nf][1] = t4[1];
                bf[nf+1][0] = t4[2]; bf[nf+1][1] = t4[3];
            }
#pragma unroll
            for (int mf = 0; mf < 4; mf++)
#pragma unroll
                for (int nf = 0; nf < 4; nf++)
                    mma16(acc[mf][nf], af[mf], bf[nf]);
        }
        __syncthreads();
    }

#pragma unroll
    for (int mf = 0; mf < 4; mf++) {
        int r0 = m0 + wm + mf * 16 + g;
        int r1 = r0 + 8;
        float bv0 = bias[r0], bv1 = bias[r1];
#pragma unroll
        for (int nf = 0; nf < 4; nf++) {
            int cn = n0 + wn + nf * 8 + 2 * tig;
            if (cn < N) {
                if (OUTH) {
                    __half* Ch = (__half*)Cv + (size_t)blockIdx.z * 384 * N;
                    *reinterpret_cast<half2*>(&Ch[(size_t)r0 * N + cn]) =
                        __floats2half2_rn(acc[mf][nf][0] + bv0, acc[mf][nf][1] + bv0);
                    *reinterpret_cast<half2*>(&Ch[(size_t)r1 * N + cn]) =
                        __floats2half2_rn(acc[mf][nf][2] + bv1, acc[mf][nf][3] + bv1);
                } else {
                    float* Cf = (float*)Cv + (size_t)blockIdx.z * 384 * N;
                    *reinterpret_cast<float2*>(&Cf[(size_t)r0 * N + cn]) =
                        make_float2(acc[mf][nf][0] + bv0, acc[mf][nf][1] + bv0);
                    *reinterpret_cast<float2*>(&Cf[(size_t)r1 * N + cn]) =
                        make_float2(acc[mf][nf][2] + bv1, acc[mf][nf][3] + bv1);
                }
            }
        }
    }
}

// ---------------------------------------------------------------------------
// Offset network v3: block per (bg, i) output row.
// Phase A: coalesced depthwise conv (work item = (c,j), j fastest) -> smem.
// Phase B: warp-per-position shuffle LN/GELU/1x1 from smem.
// ---------------------------------------------------------------------------
#define HSTR 100   // smem row stride for sh[j][c]

__device__ __forceinline__ float wsum(float v) {
#pragma unroll
    for (int o = 16; o > 0; o >>= 1) v += __shfl_xor_sync(0xffffffffu, v, o);
    return v;
}

__global__ __launch_bounds__(256)
void offset_net(const float* __restrict__ q,
                const float* __restrict__ dw_w, const float* __restrict__ dw_b,
                const float* __restrict__ ln_g, const float* __restrict__ ln_b,
                const float* __restrict__ pw_w,
                float* __restrict__ pos, float* __restrict__ pos_out,
                float* __restrict__ ref_out)
{
    __shared__ float sh[HK * HSTR];     // [j][c]

    int blk = blockIdx.x;               // bg*28 + i
    int bg = blk / HK;
    int i  = blk - bg * HK;
    int b = bg >> 2, gg = bg & 3;
    int tid = threadIdx.x;

    // ---- Phase A: depthwise 3x3 stride-2 conv, coalesced over j ----
    int y0 = 2 * i - 1;
    for (int it = tid; it < GC * HK; it += 256) {
        int c = it / HK, j = it - c * HK;
        const float* qc = q + ((size_t)(b * NCH + gg * GC + c)) * HWSZ;
        const float* w = dw_w + c * 9;
        float acc = dw_b[c];
        int x0 = 2 * j - 1;
#pragma unroll
        for (int ky = 0; ky < 3; ky++) {
            int y = y0 + ky;
            if (y < 0 || y >= HH) continue;
#pragma unroll
            for (int kx = 0; kx < 3; kx++) {
                int x = x0 + kx;
                if (x < 0 || x >= WW) continue;
                acc += w[ky * 3 + kx] * qc[y * WW + x];
            }
        }
        sh[j * HSTR + c] = acc;
    }
    __syncthreads();

    // ---- Phase B: per-position LN + GELU + 1x1 + tanh (warp shuffles) ----
    int warp = tid >> 5, lane = tid & 31;
    for (int j = warp; j < HK; j += 8) {
        const float* hr = &sh[j * HSTR];
        float h0 = hr[lane * 3], h1 = hr[lane * 3 + 1], h2 = hr[lane * 3 + 2];
        float mu = wsum(h0 + h1 + h2) * (1.f / GC);
        float d0 = h0 - mu, d1 = h1 - mu, d2 = h2 - mu;
        float var = wsum(d0 * d0 + d1 * d1 + d2 * d2) * (1.f / GC);
        float inv = rsqrtf(var + 1e-5f);

        float py_p = 0.f, px_p = 0.f;
        float hn[3] = {d0 * inv, d1 * inv, d2 * inv};
#pragma unroll
        for (int e = 0; e < 3; e++) {
            int c = lane * 3 + e;
            float v = hn[e] * ln_g[c] + ln_b[c];
            v = 0.5f * v * (1.f + erff(v * 0.70710678118654752f));   // exact GELU
            py_p += pw_w[c] * v;
            px_p += pw_w[GC + c] * v;
        }
        float offy = wsum(py_p);
        float offx = wsum(px_p);

        if (lane == 0) {
            float ry = (0.5f + (float)i) * (1.f / 27.f) * 2.f - 1.f;
            float rx = (0.5f + (float)j) * (1.f / 27.f) * 2.f - 1.f;
            float py = tanhf(offy) * (1.f / 27.f) + ry;
            float px = tanhf(offx) * (1.f / 27.f) + rx;
            size_t o = ((size_t)bg * NKV + i * HK + j) * 2;
            pos[o] = py;     pos[o + 1] = px;
            pos_out[o] = py; pos_out[o + 1] = px;
            ref_out[o] = ry; ref_out[o + 1] = rx;
        }
    }
}

// ---------------------------------------------------------------------------
// Bilinear grid sample -> fp16 xs (unchanged)
// ---------------------------------------------------------------------------
__global__ __launch_bounds__(256)
void grid_sample_k(const float* __restrict__ x, const float* __restrict__ pos,
                   __half* __restrict__ xs)
{
    int bg = blockIdx.y;
    int b = bg >> 2, g = bg & 3;
    int idx = blockIdx.x * 256 + threadIdx.x;
    int c = idx / NKV, p = idx - c * NKV;

    float py = pos[((size_t)bg * NKV + p) * 2];
    float px = pos[((size_t)bg * NKV + p) * 2 + 1];
    float gx = (px + 1.f) * 0.5f * (WW - 1);
    float gy = (py + 1.f) * 0.5f * (HH - 1);
    float x0f = floorf(gx), y0f = floorf(gy);
    int x0 = (int)x0f, y0 = (int)y0f;
    float wx1 = gx - x0f, wx0 = 1.f - wx1;
    float wy1 = gy - y0f, wy0 = 1.f - wy1;

    const float* img = x + ((size_t)(b * NCH + g * GC + c)) * HWSZ;

    float v00 = 0.f, v01 = 0.f, v10 = 0.f, v11 = 0.f;
    bool xv0 = (x0 >= 0) && (x0 < WW);
    bool xv1 = (x0 + 1 >= 0) && (x0 + 1 < WW);
    bool yv0 = (y0 >= 0) && (y0 < HH);
    bool yv1 = (y0 + 1 >= 0) && (y0 + 1 < HH);
    if (xv0 && yv0) v00 = img[y0 * WW + x0];
    if (xv1 && yv0) v01 = img[y0 * WW + x0 + 1];
    if (xv0 && yv1) v10 = img[(y0 + 1) * WW + x0];
    if (xv1 && yv1) v11 = img[(y0 + 1) * WW + x0 + 1];

    float acc = v00 * wx0 * wy0 + v01 * wx1 * wy0 + v10 * wx0 * wy1 + v11 * wx1 * wy1;
    xs[((size_t)(b * NCH + g * GC + c)) * NKV + p] = __float2half_rn(acc);
}

// ---------------------------------------------------------------------------
// Flash attention (unchanged from R8): 4 warps/block, warp-autonomous.
// ---------------------------------------------------------------------------
#define FTM 64
#define FTN 112
#define QSTRH 56     // 48 + 8 pad
#define KSTRH 120    // 112 + 8 pad
#define F_SMEM (34304 * 2)

__global__ __launch_bounds__(128)
void attention_h(const float* __restrict__ q, const __half* __restrict__ k,
                 const __half* __restrict__ v, __half* __restrict__ out)
{
    extern __shared__ char smraw[];
    __half* qs = (__half*)smraw;                    // [m][c]    64 x QSTRH
    __half* kt = qs + FTM * QSTRH;                  // [2][c][n] 48 x KSTRH
    __half* vt = kt + 2 * HC * KSTRH;
    __half* pt = vt + 2 * HC * KSTRH;               // [m][n]    64 x KSTRH

    int head = blockIdx.y;
    int b = head >> 3, hh = head & 7;
    const float*  qp = q + ((size_t)(b * NCH + hh * HC)) * HWSZ;
    const __half* kp = k + ((size_t)(b * NCH + hh * HC)) * NKV;
    const __half* vp = v + ((size_t)(b * NCH + hh * HC)) * NKV;
    __half*       op = out + ((size_t)(b * NCH + hh * HC)) * HWSZ;
    int m0 = blockIdx.x * FTM;
    int tid = threadIdx.x;
    int wid = tid >> 5, lane = tid & 31;
    int g = lane >> 2, tig = lane & 3;
    int l16 = lane & 15, lh = (lane >> 4) * 8;
    int wm = wid * 16;
    const float scale = 0.14433756729740643f;       // 1/sqrt(48)

    int row_lo = wm + g, row_hi = wm + g + 8;

    for (int idx = tid; idx < HC * FTM; idx += 128) {
        int c = idx >> 6, m = idx & 63;
        qs[m * QSTRH + c] = __float2half_rn(qp[(size_t)c * HWSZ + m0 + m]);
    }

    auto stage_kv = [&](int s, int n0) {
        __half* kd = kt + s * HC * KSTRH;
        __half* vd = vt + s * HC * KSTRH;
        for (int it = tid; it < 1344; it += 128) {
            int tsel = it / 672;
            int rid = it - tsel * 672;
            int c = rid / 14, gc = (rid - c * 14) * 8;
            const __half* src = (tsel ? vp : kp) + (size_t)c * NKV + n0 + gc;
            cpa16((tsel ? vd : kd) + c * KSTRH + gc, src, true);
        }
    };

    stage_kv(0, 0);
    CPA_COMMIT();

    float m_lo = -1e30f, m_hi = -1e30f, l_lo = 0.f, l_hi = 0.f;
    float o_acc[6][4];
#pragma unroll
    for (int i = 0; i < 6; i++)
#pragma unroll
        for (int r = 0; r < 4; r++) o_acc[i][r] = 0.f;

    int s = 0;
    for (int t = 0; t < 7; t++) {
        CPA_WAIT0();
        __syncthreads();
        const __half* kts = kt + s * HC * KSTRH;
        const __half* vts = vt + s * HC * KSTRH;

        float sv[14][4];
#pragma unroll
        for (int j = 0; j < 14; j++)
#pragma unroll
            for (int r = 0; r < 4; r++) sv[j][r] = 0.f;
#pragma unroll
        for (int kk = 0; kk < HC; kk += 16) {
            unsigned af[4];
            ldsm4(af, &qs[(wm + l16) * QSTRH + kk + lh]);
#pragma unroll
            for (int j16 = 0; j16 < 7; j16++) {
                unsigned t4[4];
                ldsm4t(t4, &kts[(kk + l16) * KSTRH + j16 * 16 + lh]);
                mma16(sv[2 * j16],     af, t4);
                mma16(sv[2 * j16 + 1], af, t4 + 2);
            }
        }

        if (t < 6) stage_kv(s ^ 1, (t + 1) * FTN);
        CPA_COMMIT();

        float mx_lo = -1e30f, mx_hi = -1e30f;
#pragma unroll
        for (int j = 0; j < 14; j++) {
            mx_lo = fmaxf(mx_lo, fmaxf(sv[j][0], sv[j][1]));
            mx_hi = fmaxf(mx_hi, fmaxf(sv[j][2], sv[j][3]));
        }
#pragma unroll
        for (int o = 1; o < 4; o <<= 1) {
            mx_lo = fmaxf(mx_lo, __shfl_xor_sync(0xffffffffu, mx_lo, o));
            mx_hi = fmaxf(mx_hi, __shfl_xor_sync(0xffffffffu, mx_hi, o));
        }
        float mn_lo = fmaxf(m_lo, mx_lo * scale);
        float mn_hi = fmaxf(m_hi, mx_hi * scale);
        float al_lo = __expf(m_lo - mn_lo);
        float al_hi = __expf(m_hi - mn_hi);
        m_lo = mn_lo; m_hi = mn_hi;

        float sm_lo = 0.f, sm_hi = 0.f;
#pragma unroll
        for (int j = 0; j < 14; j++) {
            float p0 = __expf(fmaf(sv[j][0], scale, -mn_lo));
            float p1 = __expf(fmaf(sv[j][1], scale, -mn_lo));
            float p2 = __expf(fmaf(sv[j][2], scale, -mn_hi));
            float p3 = __expf(fmaf(sv[j][3], scale, -mn_hi));
            sm_lo += p0 + p1; sm_hi += p2 + p3;
            int col = j * 8 + 2 * tig;
            *reinterpret_cast<half2*>(&pt[row_lo * KSTRH + col]) = __floats2half2_rn(p0, p1);
            *reinterpret_cast<half2*>(&pt[row_hi * KSTRH + col]) = __floats2half2_rn(p2, p3);
        }
#pragma unroll
        for (int o = 1; o < 4; o <<= 1) {
            sm_lo += __shfl_xor_sync(0xffffffffu, sm_lo, o);
            sm_hi += __shfl_xor_sync(0xffffffffu, sm_hi, o);
        }
        l_lo = l_lo * al_lo + sm_lo;
        l_hi = l_hi * al_hi + sm_hi;
#pragma unroll
        for (int i = 0; i < 6; i++) {
            o_acc[i][0] *= al_lo; o_acc[i][1] *= al_lo;
            o_acc[i][2] *= al_hi; o_acc[i][3] *= al_hi;
        }
        __syncwarp();

#pragma unroll
        for (int kk = 0; kk < 7; kk++) {
            unsigned af[4];
            ldsm4(af, &pt[(wm + l16) * KSTRH + kk * 16 + lh]);
#pragma unroll
            for (int ci = 0; ci < 6; ci++) {
                unsigned bf[2];
                bf[0] = *reinterpret_cast<const unsigned*>(&vts[(ci * 8 + g) * KSTRH + kk * 16 + 2 * tig]);
                bf[1] = *reinterpret_cast<const unsigned*>(&vts[(ci * 8 + g) * KSTRH + kk * 16 + 8 + 2 * tig]);
                mma16(o_acc[ci], af, bf);
            }
        }
        s ^= 1;
    }

    float il_lo = 1.f / l_lo;
    float il_hi = 1.f / l_hi;
#pragma unroll
    for (int ci = 0; ci < 6; ci++) {
        int cc = ci * 8 + 2 * tig;
        op[(size_t)cc * HWSZ + m0 + row_lo]       = __float2half_rn(o_acc[ci][0] * il_lo);
        op[(size_t)(cc + 1) * HWSZ + m0 + row_lo] = __float2half_rn(o_acc[ci][1] * il_lo);
        op[(size_t)cc * HWSZ + m0 + row_hi]       = __float2half_rn(o_acc[ci][2] * il_hi);
        op[(size_t)(cc + 1) * HWSZ + m0 + row_hi] = __float2half_rn(o_acc[ci][3] * il_hi);
    }
}

// ---------------------------------------------------------------------------
extern "C" void kernel_launch(void* const* d_in, const int* in_sizes, int n_in,
                              void* d_out, int out_size)
{
    const float* x   = (const float*)d_in[0];
    const float* Wq  = (const float*)d_in[1];
    const float* bq  = (const float*)d_in[2];
    const float* Wk  = (const float*)d_in[3];
    const float* bk  = (const float*)d_in[4];
    const float* Wv  = (const float*)d_in[5];
    const float* bv  = (const float*)d_in[6];
    const float* Wo  = (const float*)d_in[7];
    const float* bo  = (const float*)d_in[8];
    const float* dww = (const float*)d_in[9];
    const float* dwb = (const float*)d_in[10];
    const float* lng = (const float*)d_in[11];
    const float* lnb = (const float*)d_in[12];
    const float* pww = (const float*)d_in[13];
    float* out = (float*)d_out;

    float *q, *pos;
    __half *xh, *atth, *xsh, *kh, *vh, *wh;
    cudaGetSymbolAddress((void**)&q,    g_q);
    cudaGetSymbolAddress((void**)&pos,  g_pos);
    cudaGetSymbolAddress((void**)&xh,   g_xh);
    cudaGetSymbolAddress((void**)&atth, g_atth);
    cudaGetSymbolAddress((void**)&xsh,  g_xsh);
    cudaGetSymbolAddress((void**)&kh,   g_kh);
    cudaGetSymbolAddress((void**)&vh,   g_vh);
    cudaGetSymbolAddress((void**)&wh,   g_wh);

    __half* whq = wh;
    __half* whk = wh + NCH * NCH;
    __half* whv = wh + 2 * NCH * NCH;
    __half* who = wh + 3 * NCH * NCH;

    cudaFuncSetAttribute(attention_h, cudaFuncAttributeMaxDynamicSharedMemorySize, F_SMEM);

    // 0) fp16 conversions (x + all 4 weights fused)
    to_half4<<<(YSZ / 4 + 255) / 256, 256>>>(x, xh, YSZ / 4);
    w_to_half<<<(4 * WN4) / 256, 256>>>(Wq, Wk, Wv, Wo, wh);

    dim3 gbig((HWSZ + 127) / 128, 3, BATCH);   // 25 x 3 x 8
    dim3 gkv((NKV + 127) / 128, 6, BATCH);     // 7 x 6 x 8 (k + v fused)

    // 1) q = Wq x + bq (fp32 out, needed by offset net + attention)
    gemm_h<false><<<gbig, 256>>>(whq, nullptr, bq, nullptr, xh, q, nullptr, NCH, HWSZ);
    // 2) offset net -> pos (block per (bg, i) row; coalesced conv)
    offset_net<<<BATCH * NG * HK, 256>>>(q, dww, dwb, lng, lnb, pww,
                                         pos, out + YSZ, out + YSZ + PSZ);
    // 3) grid sample -> xs (fp16)
    grid_sample_k<<<dim3((GC * NKV) / 256, BATCH * NG), 256>>>(x, pos, xsh);
    // 4) k and v in one launch (fp16 out)
    gemm_h<true><<<gkv, 256>>>(whk, whv, bk, bv, xsh, kh, vh, NCH, NKV);
    // 5) flash attention -> atth (fp16)
    attention_h<<<dim3(HWSZ / FTM, BATCH * NH), 128, F_SMEM>>>(q, kh, vh, atth);
    // 6) y = Wo att + bo (fp32 -> d_out)
    gemm_h<false><<<gbig, 256>>>(who, nullptr, bo, nullptr, atth, out, nullptr, NCH, HWSZ);
}

// round 10
// speedup vs baseline: 11.9749x; 1.0336x over previous
#include <cuda_runtime.h>
#include <cuda_fp16.h>
#include <math.h>

// Problem constants
#define BATCH 8
#define NCH   384
#define HH    56
#define WW    56
#define HWSZ  3136      // 56*56
#define NKV   784       // 28*28
#define HK    28
#define NG    4
#define GC    96
#define NH    8
#define HC    48

#define YSZ   (BATCH*NCH*HWSZ)     // 9633792
#define PSZ   (BATCH*NG*NKV*2)     // 50176

// Scratch (allocation-free rule: __device__ globals)
static __device__ float  g_q   [BATCH*NCH*HWSZ];
static __device__ __half g_xh  [BATCH*NCH*HWSZ];
static __device__ __half g_atth[BATCH*NCH*HWSZ];
static __device__ __half g_xsh [BATCH*NCH*NKV];
static __device__ __half g_kh  [BATCH*NCH*NKV];
static __device__ __half g_vh  [BATCH*NCH*NKV];
static __device__ __half g_wh  [4*NCH*NCH];     // Wq, Wk, Wv, Wo fp16
static __device__ float  g_pos [BATCH*NG*NKV*2];

// ---------------------------------------------------------------------------
// mma / ldmatrix / cp.async helpers
// ---------------------------------------------------------------------------
__device__ __forceinline__ void mma16(float* d, const unsigned* a, const unsigned* b) {
    asm("mma.sync.aligned.m16n8k16.row.col.f32.f16.f16.f32 "
        "{%0,%1,%2,%3}, {%4,%5,%6,%7}, {%8,%9}, {%0,%1,%2,%3};"
        : "+f"(d[0]), "+f"(d[1]), "+f"(d[2]), "+f"(d[3])
        : "r"(a[0]), "r"(a[1]), "r"(a[2]), "r"(a[3]), "r"(b[0]), "r"(b[1]));
}
__device__ __forceinline__ void ldsm4(unsigned* r, const __half* p) {
    unsigned addr = (unsigned)__cvta_generic_to_shared(p);
    asm volatile("ldmatrix.sync.aligned.m8n8.x4.shared.b16 {%0,%1,%2,%3}, [%4];"
                 : "=r"(r[0]), "=r"(r[1]), "=r"(r[2]), "=r"(r[3]) : "r"(addr));
}
__device__ __forceinline__ void ldsm4t(unsigned* r, const __half* p) {
    unsigned addr = (unsigned)__cvta_generic_to_shared(p);
    asm volatile("ldmatrix.sync.aligned.m8n8.x4.trans.shared.b16 {%0,%1,%2,%3}, [%4];"
                 : "=r"(r[0]), "=r"(r[1]), "=r"(r[2]), "=r"(r[3]) : "r"(addr));
}
__device__ __forceinline__ void cpa16(const __half* dst, const __half* src, bool pred) {
    unsigned d = (unsigned)__cvta_generic_to_shared(dst);
    int sz = pred ? 16 : 0;
    asm volatile("cp.async.cg.shared.global [%0], [%1], 16, %2;"
                 :: "r"(d), "l"(src), "r"(sz));
}
#define CPA_COMMIT() asm volatile("cp.async.commit_group;")
#define CPA_WAIT1()  asm volatile("cp.async.wait_group 1;")
#define CPA_WAIT0()  asm volatile("cp.async.wait_group 0;")

__device__ __forceinline__ unsigned packh2(float a, float b) {
    half2 h = __floats2half2_rn(a, b);
    return *reinterpret_cast<unsigned*>(&h);
}

// ---------------------------------------------------------------------------
// fp32 -> fp16 conversions
// ---------------------------------------------------------------------------
__global__ __launch_bounds__(256)
void to_half4(const float* __restrict__ src, __half* __restrict__ dst, int n4)
{
    int i = blockIdx.x * 256 + threadIdx.x;
    if (i < n4) {
        float4 f = reinterpret_cast<const float4*>(src)[i];
        reinterpret_cast<half2*>(dst)[2*i]   = __floats2half2_rn(f.x, f.y);
        reinterpret_cast<half2*>(dst)[2*i+1] = __floats2half2_rn(f.z, f.w);
    }
}

#define WN4 (NCH*NCH/4)   // 36864
__global__ __launch_bounds__(256)
void w_to_half(const float* __restrict__ Wq, const float* __restrict__ Wk,
               const float* __restrict__ Wv, const float* __restrict__ Wo,
               __half* __restrict__ wh)
{
    int i = blockIdx.x * 256 + threadIdx.x;      // < 4*WN4
    int m = i / WN4, r = i - m * WN4;
    const float* src = (m == 0) ? Wq : (m == 1) ? Wk : (m == 2) ? Wv : Wo;
    float4 f = reinterpret_cast<const float4*>(src)[r];
    half2* dst = reinterpret_cast<half2*>(wh + (size_t)m * NCH * NCH);
    dst[2*r]   = __floats2half2_rn(f.x, f.y);
    dst[2*r+1] = __floats2half2_rn(f.z, f.w);
}

// ---------------------------------------------------------------------------
// fp16 GEMM (unchanged)
// ---------------------------------------------------------------------------
#define ASTRH 40
#define BSTRH 136

template<bool OUTH>
__global__ __launch_bounds__(256)
void gemm_h(const __half* __restrict__ A0, const __half* __restrict__ A1,
            const float* __restrict__ bias0, const float* __restrict__ bias1,
            const __half* __restrict__ Bsrc,
            void* __restrict__ C0, void* __restrict__ C1,
            int K, int N)
{
    __shared__ __half As[2][128 * ASTRH];
    __shared__ __half Bs[2][32 * BSTRH];

    bool sel = (A1 != nullptr) && (blockIdx.y >= 3);
    const __half* A    = sel ? A1 : A0;
    const float*  bias = sel ? bias1 : bias0;
    void*         Cv   = sel ? C1 : C0;

    const __half* Bp = Bsrc + (size_t)blockIdx.z * K * N;
    int m0 = (blockIdx.y % 3) * 128, n0 = blockIdx.x * 128;
    int tid = threadIdx.x;
    int wid = tid >> 5, lane = tid & 31;
    int g = lane >> 2, tig = lane & 3;
    int wm = (wid & 1) * 64;
    int wn = (wid >> 1) * 32;
    int l16 = lane & 15, lh = (lane >> 4) * 8;

    int ar = tid >> 1, ac = (tid & 1) * 16;
    int br = tid >> 3, bc = (tid & 7) * 16;

    float acc[4][4][4];
#pragma unroll
    for (int i = 0; i < 4; i++)
#pragma unroll
        for (int j = 0; j < 4; j++)
#pragma unroll
            for (int r = 0; r < 4; r++) acc[i][j][r] = 0.f;

    auto issue = [&](int s, int k0) {
        const __half* asrc = A + (size_t)(m0 + ar) * K + k0 + ac;
        cpa16(&As[s][ar * ASTRH + ac], asrc, true);
        cpa16(&As[s][ar * ASTRH + ac + 8], asrc + 8, true);
        const __half* bsrc = Bp + (size_t)(k0 + br) * N + n0 + bc;
        cpa16(&Bs[s][br * BSTRH + bc], bsrc, n0 + bc < N);
        cpa16(&Bs[s][br * BSTRH + bc + 8], bsrc + 8, n0 + bc + 8 < N);
    };

    issue(0, 0);
    CPA_COMMIT();

    int s = 0;
    for (int k0 = 0; k0 < K; k0 += 32, s ^= 1) {
        if (k0 + 32 < K) issue(s ^ 1, k0 + 32);
        CPA_COMMIT();
        CPA_WAIT1();
        __syncthreads();
#pragma unroll
        for (int kk = 0; kk < 32; kk += 16) {
            unsigned af[4][4], bf[4][2];
#pragma unroll
            for (int mf = 0; mf < 4; mf++)
                ldsm4(af[mf], &As[s][(wm + mf * 16 + l16) * ASTRH + kk + lh]);
#pragma unroll
            for (int nf = 0; nf < 4; nf += 2) {
                unsigned t4[4];
                ldsm4t(t4, &Bs[s][(kk + l16) * BSTRH + wn + nf * 8 + lh]);
                bf[nf][0] = t4[0]; bf[nf][1] = t4[1];
                bf[nf+1][0] = t4[2]; bf[nf+1][1] = t4[3];
            }
#pragma unroll
            for (int mf = 0; mf < 4; mf++)
#pragma unroll
                for (int nf = 0; nf < 4; nf++)
                    mma16(acc[mf][nf], af[mf], bf[nf]);
        }
        __syncthreads();
    }

#pragma unroll
    for (int mf = 0; mf < 4; mf++) {
        int r0 = m0 + wm + mf * 16 + g;
        int r1 = r0 + 8;
        float bv0 = bias[r0], bv1 = bias[r1];
#pragma unroll
        for (int nf = 0; nf < 4; nf++) {
            int cn = n0 + wn + nf * 8 + 2 * tig;
            if (cn < N) {
                if (OUTH) {
                    __half* Ch = (__half*)Cv + (size_t)blockIdx.z * 384 * N;
                    *reinterpret_cast<half2*>(&Ch[(size_t)r0 * N + cn]) =
                        __floats2half2_rn(acc[mf][nf][0] + bv0, acc[mf][nf][1] + bv0);
                    *reinterpret_cast<half2*>(&Ch[(size_t)r1 * N + cn]) =
                        __floats2half2_rn(acc[mf][nf][2] + bv1, acc[mf][nf][3] + bv1);
                } else {
                    float* Cf = (float*)Cv + (size_t)blockIdx.z * 384 * N;
                    *reinterpret_cast<float2*>(&Cf[(size_t)r0 * N + cn]) =
                        make_float2(acc[mf][nf][0] + bv0, acc[mf][nf][1] + bv0);
                    *reinterpret_cast<float2*>(&Cf[(size_t)r1 * N + cn]) =
                        make_float2(acc[mf][nf][2] + bv1, acc[mf][nf][3] + bv1);
                }
            }
        }
    }
}

// ---------------------------------------------------------------------------
// Offset network v3 (unchanged from R9)
// ---------------------------------------------------------------------------
#define HSTR 100

__device__ __forceinline__ float wsum(float v) {
#pragma unroll
    for (int o = 16; o > 0; o >>= 1) v += __shfl_xor_sync(0xffffffffu, v, o);
    return v;
}

__global__ __launch_bounds__(256)
void offset_net(const float* __restrict__ q,
                const float* __restrict__ dw_w, const float* __restrict__ dw_b,
                const float* __restrict__ ln_g, const float* __restrict__ ln_b,
                const float* __restrict__ pw_w,
                float* __restrict__ pos, float* __restrict__ pos_out,
                float* __restrict__ ref_out)
{
    __shared__ float sh[HK * HSTR];     // [j][c]

    int blk = blockIdx.x;               // bg*28 + i
    int bg = blk / HK;
    int i  = blk - bg * HK;
    int b = bg >> 2, gg = bg & 3;
    int tid = threadIdx.x;

    int y0 = 2 * i - 1;
    for (int it = tid; it < GC * HK; it += 256) {
        int c = it / HK, j = it - c * HK;
        const float* qc = q + ((size_t)(b * NCH + gg * GC + c)) * HWSZ;
        const float* w = dw_w + c * 9;
        float acc = dw_b[c];
        int x0 = 2 * j - 1;
#pragma unroll
        for (int ky = 0; ky < 3; ky++) {
            int y = y0 + ky;
            if (y < 0 || y >= HH) continue;
#pragma unroll
            for (int kx = 0; kx < 3; kx++) {
                int x = x0 + kx;
                if (x < 0 || x >= WW) continue;
                acc += w[ky * 3 + kx] * qc[y * WW + x];
            }
        }
        sh[j * HSTR + c] = acc;
    }
    __syncthreads();

    int warp = tid >> 5, lane = tid & 31;
    for (int j = warp; j < HK; j += 8) {
        const float* hr = &sh[j * HSTR];
        float h0 = hr[lane * 3], h1 = hr[lane * 3 + 1], h2 = hr[lane * 3 + 2];
        float mu = wsum(h0 + h1 + h2) * (1.f / GC);
        float d0 = h0 - mu, d1 = h1 - mu, d2 = h2 - mu;
        float var = wsum(d0 * d0 + d1 * d1 + d2 * d2) * (1.f / GC);
        float inv = rsqrtf(var + 1e-5f);

        float py_p = 0.f, px_p = 0.f;
        float hn[3] = {d0 * inv, d1 * inv, d2 * inv};
#pragma unroll
        for (int e = 0; e < 3; e++) {
            int c = lane * 3 + e;
            float v = hn[e] * ln_g[c] + ln_b[c];
            v = 0.5f * v * (1.f + erff(v * 0.70710678118654752f));
            py_p += pw_w[c] * v;
            px_p += pw_w[GC + c] * v;
        }
        float offy = wsum(py_p);
        float offx = wsum(px_p);

        if (lane == 0) {
            float ry = (0.5f + (float)i) * (1.f / 27.f) * 2.f - 1.f;
            float rx = (0.5f + (float)j) * (1.f / 27.f) * 2.f - 1.f;
            float py = tanhf(offy) * (1.f / 27.f) + ry;
            float px = tanhf(offx) * (1.f / 27.f) + rx;
            size_t o = ((size_t)bg * NKV + i * HK + j) * 2;
            pos[o] = py;     pos[o + 1] = px;
            pos_out[o] = py; pos_out[o + 1] = px;
            ref_out[o] = ry; ref_out[o + 1] = rx;
        }
    }
}

// ---------------------------------------------------------------------------
// Bilinear grid sample -> fp16 xs (unchanged)
// ---------------------------------------------------------------------------
__global__ __launch_bounds__(256)
void grid_sample_k(const float* __restrict__ x, const float* __restrict__ pos,
                   __half* __restrict__ xs)
{
    int bg = blockIdx.y;
    int b = bg >> 2, g = bg & 3;
    int idx = blockIdx.x * 256 + threadIdx.x;
    int c = idx / NKV, p = idx - c * NKV;

    float py = pos[((size_t)bg * NKV + p) * 2];
    float px = pos[((size_t)bg * NKV + p) * 2 + 1];
    float gx = (px + 1.f) * 0.5f * (WW - 1);
    float gy = (py + 1.f) * 0.5f * (HH - 1);
    float x0f = floorf(gx), y0f = floorf(gy);
    int x0 = (int)x0f, y0 = (int)y0f;
    float wx1 = gx - x0f, wx0 = 1.f - wx1;
    float wy1 = gy - y0f, wy0 = 1.f - wy1;

    const float* img = x + ((size_t)(b * NCH + g * GC + c)) * HWSZ;

    float v00 = 0.f, v01 = 0.f, v10 = 0.f, v11 = 0.f;
    bool xv0 = (x0 >= 0) && (x0 < WW);
    bool xv1 = (x0 + 1 >= 0) && (x0 + 1 < WW);
    bool yv0 = (y0 >= 0) && (y0 < HH);
    bool yv1 = (y0 + 1 >= 0) && (y0 + 1 < HH);
    if (xv0 && yv0) v00 = img[y0 * WW + x0];
    if (xv1 && yv0) v01 = img[y0 * WW + x0 + 1];
    if (xv0 && yv1) v10 = img[(y0 + 1) * WW + x0];
    if (xv1 && yv1) v11 = img[(y0 + 1) * WW + x0 + 1];

    float acc = v00 * wx0 * wy0 + v01 * wx1 * wy0 + v10 * wx0 * wy1 + v11 * wx1 * wy1;
    xs[((size_t)(b * NCH + g * GC + c)) * NKV + p] = __float2half_rn(acc);
}

// ---------------------------------------------------------------------------
// Flash attention v3: 128 queries/block (8 warps x 16 rows), register-resident
// P (C->A fragment identity, no smem round-trip), double-buffered cp.async K/V.
// ---------------------------------------------------------------------------
#define FTM 128
#define FTN 112
#define QSTRH 56     // 48 + 8 pad
#define KSTRH 120    // 112 + 8 pad
// halves: qs 128*56=7168 + kt 2*48*120=11520 + vt 11520 = 30208 -> 60416 B
#define F_SMEM (30208 * 2)

__global__ __launch_bounds__(256)
void attention_h(const float* __restrict__ q, const __half* __restrict__ k,
                 const __half* __restrict__ v, __half* __restrict__ out)
{
    extern __shared__ char smraw[];
    __half* qs = (__half*)smraw;                    // [m][c]    128 x QSTRH
    __half* kt = qs + FTM * QSTRH;                  // [2][c][n] 48 x KSTRH
    __half* vt = kt + 2 * HC * KSTRH;

    int head = blockIdx.y;
    int b = head >> 3, hh = head & 7;
    const float*  qp = q + ((size_t)(b * NCH + hh * HC)) * HWSZ;
    const __half* kp = k + ((size_t)(b * NCH + hh * HC)) * NKV;
    const __half* vp = v + ((size_t)(b * NCH + hh * HC)) * NKV;
    __half*       op = out + ((size_t)(b * NCH + hh * HC)) * HWSZ;
    int m0 = blockIdx.x * FTM;
    int tid = threadIdx.x;
    int wid = tid >> 5, lane = tid & 31;
    int g = lane >> 2, tig = lane & 3;
    int l16 = lane & 15, lh = (lane >> 4) * 8;
    int wm = wid * 16;
    const float scale = 0.14433756729740643f;       // 1/sqrt(48)

    int row_lo = wm + g, row_hi = wm + g + 8;

    // stage Q (fp32 -> fp16), guarded for tail block
    for (int idx = tid; idx < HC * FTM; idx += 256) {
        int c = idx >> 7, m = idx & 127;
        float qv = (m0 + m < HWSZ) ? qp[(size_t)c * HWSZ + m0 + m] : 0.f;
        qs[m * QSTRH + c] = __float2half_rn(qv);
    }

    auto stage_kv = [&](int s, int n0) {
        __half* kd = kt + s * HC * KSTRH;
        __half* vd = vt + s * HC * KSTRH;
        for (int it = tid; it < 1344; it += 256) {
            int tsel = it / 672;
            int rid = it - tsel * 672;
            int c = rid / 14, gc = (rid - c * 14) * 8;
            const __half* src = (tsel ? vp : kp) + (size_t)c * NKV + n0 + gc;
            cpa16((tsel ? vd : kd) + c * KSTRH + gc, src, true);
        }
    };

    stage_kv(0, 0);
    CPA_COMMIT();

    float m_lo = -1e30f, m_hi = -1e30f, l_lo = 0.f, l_hi = 0.f;
    float o_acc[6][4];
#pragma unroll
    for (int i = 0; i < 6; i++)
#pragma unroll
        for (int r = 0; r < 4; r++) o_acc[i][r] = 0.f;

    int s = 0;
    for (int t = 0; t < 7; t++) {
        CPA_WAIT0();
        __syncthreads();
        const __half* kts = kt + s * HC * KSTRH;
        const __half* vts = vt + s * HC * KSTRH;

        // ---- S = Q^T K : warp tile 16 x 112 ----
        float sv[14][4];
#pragma unroll
        for (int j = 0; j < 14; j++)
#pragma unroll
            for (int r = 0; r < 4; r++) sv[j][r] = 0.f;
#pragma unroll
        for (int kk = 0; kk < HC; kk += 16) {
            unsigned af[4];
            ldsm4(af, &qs[(wm + l16) * QSTRH + kk + lh]);
#pragma unroll
            for (int j16 = 0; j16 < 7; j16++) {
                unsigned t4[4];
                ldsm4t(t4, &kts[(kk + l16) * KSTRH + j16 * 16 + lh]);
                mma16(sv[2 * j16],     af, t4);
                mma16(sv[2 * j16 + 1], af, t4 + 2);
            }
        }

        // prefetch next K/V tile
        if (t < 6) stage_kv(s ^ 1, (t + 1) * FTN);
        CPA_COMMIT();

        // ---- row max ----
        float mx_lo = -1e30f, mx_hi = -1e30f;
#pragma unroll
        for (int j = 0; j < 14; j++) {
            mx_lo = fmaxf(mx_lo, fmaxf(sv[j][0], sv[j][1]));
            mx_hi = fmaxf(mx_hi, fmaxf(sv[j][2], sv[j][3]));
        }
#pragma unroll
        for (int o = 1; o < 4; o <<= 1) {
            mx_lo = fmaxf(mx_lo, __shfl_xor_sync(0xffffffffu, mx_lo, o));
            mx_hi = fmaxf(mx_hi, __shfl_xor_sync(0xffffffffu, mx_hi, o));
        }
        float mn_lo = fmaxf(m_lo, mx_lo * scale);
        float mn_hi = fmaxf(m_hi, mx_hi * scale);
        float al_lo = __expf(m_lo - mn_lo);
        float al_hi = __expf(m_hi - mn_hi);
        m_lo = mn_lo; m_hi = mn_hi;

        // ---- p = exp(scale*s - m) -> packed A fragments (registers only) ----
        unsigned pk[7][4];
        float sm_lo = 0.f, sm_hi = 0.f;
#pragma unroll
        for (int j16 = 0; j16 < 7; j16++) {
#pragma unroll
            for (int h = 0; h < 2; h++) {       // h=0: keys 2tig(+1); h=1: keys 8+2tig(+1)
                float* svp = sv[2 * j16 + h];
                float p0 = __expf(fmaf(svp[0], scale, -mn_lo));
                float p1 = __expf(fmaf(svp[1], scale, -mn_lo));
                float p2 = __expf(fmaf(svp[2], scale, -mn_hi));
                float p3 = __expf(fmaf(svp[3], scale, -mn_hi));
                sm_lo += p0 + p1; sm_hi += p2 + p3;
                pk[j16][2 * h]     = packh2(p0, p1);   // A[row g][k pair]
                pk[j16][2 * h + 1] = packh2(p2, p3);   // A[row g+8][k pair]
            }
        }
#pragma unroll
        for (int o = 1; o < 4; o <<= 1) {
            sm_lo += __shfl_xor_sync(0xffffffffu, sm_lo, o);
            sm_hi += __shfl_xor_sync(0xffffffffu, sm_hi, o);
        }
        l_lo = l_lo * al_lo + sm_lo;
        l_hi = l_hi * al_hi + sm_hi;
#pragma unroll
        for (int i = 0; i < 6; i++) {
            o_acc[i][0] *= al_lo; o_acc[i][1] *= al_lo;
            o_acc[i][2] *= al_hi; o_acc[i][3] *= al_hi;
        }

        // ---- PV: registers P x smem V, 16m x 48c, k = 112 keys ----
#pragma unroll
        for (int j16 = 0; j16 < 7; j16++) {
#pragma unroll
            for (int ci = 0; ci < 6; ci++) {
                unsigned bf[2];
                bf[0] = *reinterpret_cast<const unsigned*>(&vts[(ci * 8 + g) * KSTRH + j16 * 16 + 2 * tig]);
                bf[1] = *reinterpret_cast<const unsigned*>(&vts[(ci * 8 + g) * KSTRH + j16 * 16 + 8 + 2 * tig]);
                mma16(o_acc[ci], pk[j16], bf);
            }
        }
        s ^= 1;
    }

    // ---- epilogue: out = acc / l  (fp16), guarded for tail block ----
    float il_lo = 1.f / l_lo;
    float il_hi = 1.f / l_hi;
    bool ok_lo = (m0 + row_lo) < HWSZ;
    bool ok_hi = (m0 + row_hi) < HWSZ;
#pragma unroll
    for (int ci = 0; ci < 6; ci++) {
        int cc = ci * 8 + 2 * tig;
        if (ok_lo) {
            op[(size_t)cc * HWSZ + m0 + row_lo]       = __float2half_rn(o_acc[ci][0] * il_lo);
            op[(size_t)(cc + 1) * HWSZ + m0 + row_lo] = __float2half_rn(o_acc[ci][1] * il_lo);
        }
        if (ok_hi) {
            op[(size_t)cc * HWSZ + m0 + row_hi]       = __float2half_rn(o_acc[ci][2] * il_hi);
            op[(size_t)(cc + 1) * HWSZ + m0 + row_hi] = __float2half_rn(o_acc[ci][3] * il_hi);
        }
    }
}

// ---------------------------------------------------------------------------
extern "C" void kernel_launch(void* const* d_in, const int* in_sizes, int n_in,
                              void* d_out, int out_size)
{
    const float* x   = (const float*)d_in[0];
    const float* Wq  = (const float*)d_in[1];
    const float* bq  = (const float*)d_in[2];
    const float* Wk  = (const float*)d_in[3];
    const float* bk  = (const float*)d_in[4];
    const float* Wv  = (const float*)d_in[5];
    const float* bv  = (const float*)d_in[6];
    const float* Wo  = (const float*)d_in[7];
    const float* bo  = (const float*)d_in[8];
    const float* dww = (const float*)d_in[9];
    const float* dwb = (const float*)d_in[10];
    const float* lng = (const float*)d_in[11];
    const float* lnb = (const float*)d_in[12];
    const float* pww = (const float*)d_in[13];
    float* out = (float*)d_out;

    float *q, *pos;
    __half *xh, *atth, *xsh, *kh, *vh, *wh;
    cudaGetSymbolAddress((void**)&q,    g_q);
    cudaGetSymbolAddress((void**)&pos,  g_pos);
    cudaGetSymbolAddress((void**)&xh,   g_xh);
    cudaGetSymbolAddress((void**)&atth, g_atth);
    cudaGetSymbolAddress((void**)&xsh,  g_xsh);
    cudaGetSymbolAddress((void**)&kh,   g_kh);
    cudaGetSymbolAddress((void**)&vh,   g_vh);
    cudaGetSymbolAddress((void**)&wh,   g_wh);

    __half* whq = wh;
    __half* whk = wh + NCH * NCH;
    __half* whv = wh + 2 * NCH * NCH;
    __half* who = wh + 3 * NCH * NCH;

    cudaFuncSetAttribute(attention_h, cudaFuncAttributeMaxDynamicSharedMemorySize, F_SMEM);

    // 0) fp16 conversions
    to_half4<<<(YSZ / 4 + 255) / 256, 256>>>(x, xh, YSZ / 4);
    w_to_half<<<(4 * WN4) / 256, 256>>>(Wq, Wk, Wv, Wo, wh);

    dim3 gbig((HWSZ + 127) / 128, 3, BATCH);   // 25 x 3 x 8
    dim3 gkv((NKV + 127) / 128, 6, BATCH);     // 7 x 6 x 8 (k + v fused)

    // 1) q = Wq x + bq
    gemm_h<false><<<gbig, 256>>>(whq, nullptr, bq, nullptr, xh, q, nullptr, NCH, HWSZ);
    // 2) offset net -> pos
    offset_net<<<BATCH * NG * HK, 256>>>(q, dww, dwb, lng, lnb, pww,
                                         pos, out + YSZ, out + YSZ + PSZ);
    // 3) grid sample -> xs (fp16)
    grid_sample_k<<<dim3((GC * NKV) / 256, BATCH * NG), 256>>>(x, pos, xsh);
    // 4) k and v in one launch (fp16 out)
    gemm_h<true><<<gkv, 256>>>(whk, whv, bk, bv, xsh, kh, vh, NCH, NKV);
    // 5) flash attention -> atth (fp16)
    attention_h<<<dim3((HWSZ + FTM - 1) / FTM, BATCH * NH), 256, F_SMEM>>>(q, kh, vh, atth);
    // 6) y = Wo att + bo
    gemm_h<false><<<gbig, 256>>>(who, nullptr, bo, nullptr, atth, out, nullptr, NCH, HWSZ);
}

// round 11
// speedup vs baseline: 12.1244x; 1.0125x over previous
#include <cuda_runtime.h>
#include <cuda_fp16.h>
#include <math.h>

// Problem constants
#define BATCH 8
#define NCH   384
#define HH    56
#define WW    56
#define HWSZ  3136      // 56*56
#define NKV   784       // 28*28
#define HK    28
#define NG    4
#define GC    96
#define NH    8
#define HC    48

#define YSZ   (BATCH*NCH*HWSZ)     // 9633792
#define PSZ   (BATCH*NG*NKV*2)     // 50176

// Scratch (allocation-free rule: __device__ globals)
static __device__ __half g_qh  [BATCH*NCH*HWSZ];
static __device__ __half g_xh  [BATCH*NCH*HWSZ];
static __device__ __half g_atth[BATCH*NCH*HWSZ];
static __device__ __half g_xsh [BATCH*NCH*NKV];
static __device__ __half g_kh  [BATCH*NCH*NKV];
static __device__ __half g_vh  [BATCH*NCH*NKV];
static __device__ __half g_wh  [4*NCH*NCH];     // Wq, Wk, Wv, Wo fp16
static __device__ float  g_pos [BATCH*NG*NKV*2];

// ---------------------------------------------------------------------------
// mma / ldmatrix / cp.async helpers
// ---------------------------------------------------------------------------
__device__ __forceinline__ void mma16(float* d, const unsigned* a, const unsigned* b) {
    asm("mma.sync.aligned.m16n8k16.row.col.f32.f16.f16.f32 "
        "{%0,%1,%2,%3}, {%4,%5,%6,%7}, {%8,%9}, {%0,%1,%2,%3};"
        : "+f"(d[0]), "+f"(d[1]), "+f"(d[2]), "+f"(d[3])
        : "r"(a[0]), "r"(a[1]), "r"(a[2]), "r"(a[3]), "r"(b[0]), "r"(b[1]));
}
__device__ __forceinline__ void ldsm4(unsigned* r, const __half* p) {
    unsigned addr = (unsigned)__cvta_generic_to_shared(p);
    asm volatile("ldmatrix.sync.aligned.m8n8.x4.shared.b16 {%0,%1,%2,%3}, [%4];"
                 : "=r"(r[0]), "=r"(r[1]), "=r"(r[2]), "=r"(r[3]) : "r"(addr));
}
__device__ __forceinline__ void ldsm4t(unsigned* r, const __half* p) {
    unsigned addr = (unsigned)__cvta_generic_to_shared(p);
    asm volatile("ldmatrix.sync.aligned.m8n8.x4.trans.shared.b16 {%0,%1,%2,%3}, [%4];"
                 : "=r"(r[0]), "=r"(r[1]), "=r"(r[2]), "=r"(r[3]) : "r"(addr));
}
__device__ __forceinline__ void cpa16(const __half* dst, const __half* src, bool pred) {
    unsigned d = (unsigned)__cvta_generic_to_shared(dst);
    int sz = pred ? 16 : 0;
    asm volatile("cp.async.cg.shared.global [%0], [%1], 16, %2;"
                 :: "r"(d), "l"(src), "r"(sz));
}
#define CPA_COMMIT() asm volatile("cp.async.commit_group;")
#define CPA_WAIT1()  asm volatile("cp.async.wait_group 1;")
#define CPA_WAIT0()  asm volatile("cp.async.wait_group 0;")

__device__ __forceinline__ unsigned packh2(float a, float b) {
    half2 h = __floats2half2_rn(a, b);
    return *reinterpret_cast<unsigned*>(&h);
}

// ---------------------------------------------------------------------------
// fp32 -> fp16 conversions
// ---------------------------------------------------------------------------
__global__ __launch_bounds__(256)
void to_half4(const float* __restrict__ src, __half* __restrict__ dst, int n4)
{
    int i = blockIdx.x * 256 + threadIdx.x;
    if (i < n4) {
        float4 f = reinterpret_cast<const float4*>(src)[i];
        reinterpret_cast<half2*>(dst)[2*i]   = __floats2half2_rn(f.x, f.y);
        reinterpret_cast<half2*>(dst)[2*i+1] = __floats2half2_rn(f.z, f.w);
    }
}

#define WN4 (NCH*NCH/4)   // 36864
__global__ __launch_bounds__(256)
void w_to_half(const float* __restrict__ Wq, const float* __restrict__ Wk,
               const float* __restrict__ Wv, const float* __restrict__ Wo,
               __half* __restrict__ wh)
{
    int i = blockIdx.x * 256 + threadIdx.x;      // < 4*WN4
    int m = i / WN4, r = i - m * WN4;
    const float* src = (m == 0) ? Wq : (m == 1) ? Wk : (m == 2) ? Wv : Wo;
    float4 f = reinterpret_cast<const float4*>(src)[r];
    half2* dst = reinterpret_cast<half2*>(wh + (size_t)m * NCH * NCH);
    dst[2*r]   = __floats2half2_rn(f.x, f.y);
    dst[2*r+1] = __floats2half2_rn(f.z, f.w);
}

// ---------------------------------------------------------------------------
// fp16 GEMM (unchanged)
// ---------------------------------------------------------------------------
#define ASTRH 40
#define BSTRH 136

template<bool OUTH>
__global__ __launch_bounds__(256)
void gemm_h(const __half* __restrict__ A0, const __half* __restrict__ A1,
            const float* __restrict__ bias0, const float* __restrict__ bias1,
            const __half* __restrict__ Bsrc,
            void* __restrict__ C0, void* __restrict__ C1,
            int K, int N)
{
    __shared__ __half As[2][128 * ASTRH];
    __shared__ __half Bs[2][32 * BSTRH];

    bool sel = (A1 != nullptr) && (blockIdx.y >= 3);
    const __half* A    = sel ? A1 : A0;
    const float*  bias = sel ? bias1 : bias0;
    void*         Cv   = sel ? C1 : C0;

    const __half* Bp = Bsrc + (size_t)blockIdx.z * K * N;
    int m0 = (blockIdx.y % 3) * 128, n0 = blockIdx.x * 128;
    int tid = threadIdx.x;
    int wid = tid >> 5, lane = tid & 31;
    int g = lane >> 2, tig = lane & 3;
    int wm = (wid & 1) * 64;
    int wn = (wid >> 1) * 32;
    int l16 = lane & 15, lh = (lane >> 4) * 8;

    int ar = tid >> 1, ac = (tid & 1) * 16;
    int br = tid >> 3, bc = (tid & 7) * 16;

    float acc[4][4][4];
#pragma unroll
    for (int i = 0; i < 4; i++)
#pragma unroll
        for (int j = 0; j < 4; j++)
#pragma unroll
            for (int r = 0; r < 4; r++) acc[i][j][r] = 0.f;

    auto issue = [&](int s, int k0) {
        const __half* asrc = A + (size_t)(m0 + ar) * K + k0 + ac;
        cpa16(&As[s][ar * ASTRH + ac], asrc, true);
        cpa16(&As[s][ar * ASTRH + ac + 8], asrc + 8, true);
        const __half* bsrc = Bp + (size_t)(k0 + br) * N + n0 + bc;
        cpa16(&Bs[s][br * BSTRH + bc], bsrc, n0 + bc < N);
        cpa16(&Bs[s][br * BSTRH + bc + 8], bsrc + 8, n0 + bc + 8 < N);
    };

    issue(0, 0);
    CPA_COMMIT();

    int s = 0;
    for (int k0 = 0; k0 < K; k0 += 32, s ^= 1) {
        if (k0 + 32 < K) issue(s ^ 1, k0 + 32);
        CPA_COMMIT();
        CPA_WAIT1();
        __syncthreads();
#pragma unroll
        for (int kk = 0; kk < 32; kk += 16) {
            unsigned af[4][4], bf[4][2];
#pragma unroll
            for (int mf = 0; mf < 4; mf++)
                ldsm4(af[mf], &As[s][(wm + mf * 16 + l16) * ASTRH + kk + lh]);
#pragma unroll
            for (int nf = 0; nf < 4; nf += 2) {
                unsigned t4[4];
                ldsm4t(t4, &Bs[s][(kk + l16) * BSTRH + wn + nf * 8 + lh]);
                bf[nf][0] = t4[0]; bf[nf][1] = t4[1];
                bf[nf+1][0] = t4[2]; bf[nf+1][1] = t4[3];
            }
#pragma unroll
            for (int mf = 0; mf < 4; mf++)
#pragma unroll
                for (int nf = 0; nf < 4; nf++)
                    mma16(acc[mf][nf], af[mf], bf[nf]);
        }
        __syncthreads();
    }

#pragma unroll
    for (int mf = 0; mf < 4; mf++) {
        int r0 = m0 + wm + mf * 16 + g;
        int r1 = r0 + 8;
        float bv0 = bias[r0], bv1 = bias[r1];
#pragma unroll
        for (int nf = 0; nf < 4; nf++) {
            int cn = n0 + wn + nf * 8 + 2 * tig;
            if (cn < N) {
                if (OUTH) {
                    __half* Ch = (__half*)Cv + (size_t)blockIdx.z * 384 * N;
                    *reinterpret_cast<half2*>(&Ch[(size_t)r0 * N + cn]) =
                        __floats2half2_rn(acc[mf][nf][0] + bv0, acc[mf][nf][1] + bv0);
                    *reinterpret_cast<half2*>(&Ch[(size_t)r1 * N + cn]) =
                        __floats2half2_rn(acc[mf][nf][2] + bv1, acc[mf][nf][3] + bv1);
                } else {
                    float* Cf = (float*)Cv + (size_t)blockIdx.z * 384 * N;
                    *reinterpret_cast<float2*>(&Cf[(size_t)r0 * N + cn]) =
                        make_float2(acc[mf][nf][0] + bv0, acc[mf][nf][1] + bv0);
                    *reinterpret_cast<float2*>(&Cf[(size_t)r1 * N + cn]) =
                        make_float2(acc[mf][nf][2] + bv1, acc[mf][nf][3] + bv1);
                }
            }
        }
    }
}

// ---------------------------------------------------------------------------
// Offset network v4: same structure as R9/R10 but reads fp16 q (halves DRAM).
// ---------------------------------------------------------------------------
#define HSTR 100

__device__ __forceinline__ float wsum(float v) {
#pragma unroll
    for (int o = 16; o > 0; o >>= 1) v += __shfl_xor_sync(0xffffffffu, v, o);
    return v;
}

__global__ __launch_bounds__(256)
void offset_net(const __half* __restrict__ q,
                const float* __restrict__ dw_w, const float* __restrict__ dw_b,
                const float* __restrict__ ln_g, const float* __restrict__ ln_b,
                const float* __restrict__ pw_w,
                float* __restrict__ pos, float* __restrict__ pos_out,
                float* __restrict__ ref_out)
{
    __shared__ float sh[HK * HSTR];     // [j][c]

    int blk = blockIdx.x;               // bg*28 + i
    int bg = blk / HK;
    int i  = blk - bg * HK;
    int b = bg >> 2, gg = bg & 3;
    int tid = threadIdx.x;

    int y0 = 2 * i - 1;
    for (int it = tid; it < GC * HK; it += 256) {
        int c = it / HK, j = it - c * HK;
        const __half* qc = q + ((size_t)(b * NCH + gg * GC + c)) * HWSZ;
        const float* w = dw_w + c * 9;
        float acc = dw_b[c];
        int x0 = 2 * j - 1;
#pragma unroll
        for (int ky = 0; ky < 3; ky++) {
            int y = y0 + ky;
            if (y < 0 || y >= HH) continue;
#pragma unroll
            for (int kx = 0; kx < 3; kx++) {
                int x = x0 + kx;
                if (x < 0 || x >= WW) continue;
                acc += w[ky * 3 + kx] * __half2float(qc[y * WW + x]);
            }
        }
        sh[j * HSTR + c] = acc;
    }
    __syncthreads();

    int warp = tid >> 5, lane = tid & 31;
    for (int j = warp; j < HK; j += 8) {
        const float* hr = &sh[j * HSTR];
        float h0 = hr[lane * 3], h1 = hr[lane * 3 + 1], h2 = hr[lane * 3 + 2];
        float mu = wsum(h0 + h1 + h2) * (1.f / GC);
        float d0 = h0 - mu, d1 = h1 - mu, d2 = h2 - mu;
        float var = wsum(d0 * d0 + d1 * d1 + d2 * d2) * (1.f / GC);
        float inv = rsqrtf(var + 1e-5f);

        float py_p = 0.f, px_p = 0.f;
        float hn[3] = {d0 * inv, d1 * inv, d2 * inv};
#pragma unroll
        for (int e = 0; e < 3; e++) {
            int c = lane * 3 + e;
            float v = hn[e] * ln_g[c] + ln_b[c];
            v = 0.5f * v * (1.f + erff(v * 0.70710678118654752f));
            py_p += pw_w[c] * v;
            px_p += pw_w[GC + c] * v;
        }
        float offy = wsum(py_p);
        float offx = wsum(px_p);

        if (lane == 0) {
            float ry = (0.5f + (float)i) * (1.f / 27.f) * 2.f - 1.f;
            float rx = (0.5f + (float)j) * (1.f / 27.f) * 2.f - 1.f;
            float py = tanhf(offy) * (1.f / 27.f) + ry;
            float px = tanhf(offx) * (1.f / 27.f) + rx;
            size_t o = ((size_t)bg * NKV + i * HK + j) * 2;
            pos[o] = py;     pos[o + 1] = px;
            pos_out[o] = py; pos_out[o + 1] = px;
            ref_out[o] = ry; ref_out[o + 1] = rx;
        }
    }
}

// ---------------------------------------------------------------------------
// Bilinear grid sample -> fp16 xs (unchanged)
// ---------------------------------------------------------------------------
__global__ __launch_bounds__(256)
void grid_sample_k(const float* __restrict__ x, const float* __restrict__ pos,
                   __half* __restrict__ xs)
{
    int bg = blockIdx.y;
    int b = bg >> 2, g = bg & 3;
    int idx = blockIdx.x * 256 + threadIdx.x;
    int c = idx / NKV, p = idx - c * NKV;

    float py = pos[((size_t)bg * NKV + p) * 2];
    float px = pos[((size_t)bg * NKV + p) * 2 + 1];
    float gx = (px + 1.f) * 0.5f * (WW - 1);
    float gy = (py + 1.f) * 0.5f * (HH - 1);
    float x0f = floorf(gx), y0f = floorf(gy);
    int x0 = (int)x0f, y0 = (int)y0f;
    float wx1 = gx - x0f, wx0 = 1.f - wx1;
    float wy1 = gy - y0f, wy0 = 1.f - wy1;

    const float* img = x + ((size_t)(b * NCH + g * GC + c)) * HWSZ;

    float v00 = 0.f, v01 = 0.f, v10 = 0.f, v11 = 0.f;
    bool xv0 = (x0 >= 0) && (x0 < WW);
    bool xv1 = (x0 + 1 >= 0) && (x0 + 1 < WW);
    bool yv0 = (y0 >= 0) && (y0 < HH);
    bool yv1 = (y0 + 1 >= 0) && (y0 + 1 < HH);
    if (xv0 && yv0) v00 = img[y0 * WW + x0];
    if (xv1 && yv0) v01 = img[y0 * WW + x0 + 1];
    if (xv0 && yv1) v10 = img[(y0 + 1) * WW + x0];
    if (xv1 && yv1) v11 = img[(y0 + 1) * WW + x0 + 1];

    float acc = v00 * wx0 * wy0 + v01 * wx1 * wy0 + v10 * wx0 * wy1 + v11 * wx1 * wy1;
    xs[((size_t)(b * NCH + g * GC + c)) * NKV + p] = __float2half_rn(acc);
}

// ---------------------------------------------------------------------------
// Flash attention v3 (register P), fp16 Q input.
// ---------------------------------------------------------------------------
#define FTM 128
#define FTN 112
#define QSTRH 56     // 48 + 8 pad
#define KSTRH 120    // 112 + 8 pad
#define F_SMEM (30208 * 2)

__global__ __launch_bounds__(256)
void attention_h(const __half* __restrict__ q, const __half* __restrict__ k,
                 const __half* __restrict__ v, __half* __restrict__ out)
{
    extern __shared__ char smraw[];
    __half* qs = (__half*)smraw;                    // [m][c]    128 x QSTRH
    __half* kt = qs + FTM * QSTRH;                  // [2][c][n] 48 x KSTRH
    __half* vt = kt + 2 * HC * KSTRH;

    int head = blockIdx.y;
    int b = head >> 3, hh = head & 7;
    const __half* qp = q + ((size_t)(b * NCH + hh * HC)) * HWSZ;
    const __half* kp = k + ((size_t)(b * NCH + hh * HC)) * NKV;
    const __half* vp = v + ((size_t)(b * NCH + hh * HC)) * NKV;
    __half*       op = out + ((size_t)(b * NCH + hh * HC)) * HWSZ;
    int m0 = blockIdx.x * FTM;
    int tid = threadIdx.x;
    int wid = tid >> 5, lane = tid & 31;
    int g = lane >> 2, tig = lane & 3;
    int l16 = lane & 15, lh = (lane >> 4) * 8;
    int wm = wid * 16;
    const float scale = 0.14433756729740643f;       // 1/sqrt(48)

    int row_lo = wm + g, row_hi = wm + g + 8;

    // stage Q (fp16 direct), guarded for tail block
    for (int idx = tid; idx < HC * FTM; idx += 256) {
        int c = idx >> 7, m = idx & 127;
        qs[m * QSTRH + c] = (m0 + m < HWSZ) ? qp[(size_t)c * HWSZ + m0 + m] : __half(0.f);
    }

    auto stage_kv = [&](int s, int n0) {
        __half* kd = kt + s * HC * KSTRH;
        __half* vd = vt + s * HC * KSTRH;
        for (int it = tid; it < 1344; it += 256) {
            int tsel = it / 672;
            int rid = it - tsel * 672;
            int c = rid / 14, gc = (rid - c * 14) * 8;
            const __half* src = (tsel ? vp : kp) + (size_t)c * NKV + n0 + gc;
            cpa16((tsel ? vd : kd) + c * KSTRH + gc, src, true);
        }
    };

    stage_kv(0, 0);
    CPA_COMMIT();

    float m_lo = -1e30f, m_hi = -1e30f, l_lo = 0.f, l_hi = 0.f;
    float o_acc[6][4];
#pragma unroll
    for (int i = 0; i < 6; i++)
#pragma unroll
        for (int r = 0; r < 4; r++) o_acc[i][r] = 0.f;

    int s = 0;
    for (int t = 0; t < 7; t++) {
        CPA_WAIT0();
        __syncthreads();
        const __half* kts = kt + s * HC * KSTRH;
        const __half* vts = vt + s * HC * KSTRH;

        // ---- S = Q^T K : warp tile 16 x 112 ----
        float sv[14][4];
#pragma unroll
        for (int j = 0; j < 14; j++)
#pragma unroll
            for (int r = 0; r < 4; r++) sv[j][r] = 0.f;
#pragma unroll
        for (int kk = 0; kk < HC; kk += 16) {
            unsigned af[4];
            ldsm4(af, &qs[(wm + l16) * QSTRH + kk + lh]);
#pragma unroll
            for (int j16 = 0; j16 < 7; j16++) {
                unsigned t4[4];
                ldsm4t(t4, &kts[(kk + l16) * KSTRH + j16 * 16 + lh]);
                mma16(sv[2 * j16],     af, t4);
                mma16(sv[2 * j16 + 1], af, t4 + 2);
            }
        }

        // prefetch next K/V tile
        if (t < 6) stage_kv(s ^ 1, (t + 1) * FTN);
        CPA_COMMIT();

        // ---- row max ----
        float mx_lo = -1e30f, mx_hi = -1e30f;
#pragma unroll
        for (int j = 0; j < 14; j++) {
            mx_lo = fmaxf(mx_lo, fmaxf(sv[j][0], sv[j][1]));
            mx_hi = fmaxf(mx_hi, fmaxf(sv[j][2], sv[j][3]));
        }
#pragma unroll
        for (int o = 1; o < 4; o <<= 1) {
            mx_lo = fmaxf(mx_lo, __shfl_xor_sync(0xffffffffu, mx_lo, o));
            mx_hi = fmaxf(mx_hi, __shfl_xor_sync(0xffffffffu, mx_hi, o));
        }
        float mn_lo = fmaxf(m_lo, mx_lo * scale);
        float mn_hi = fmaxf(m_hi, mx_hi * scale);
        float al_lo = __expf(m_lo - mn_lo);
        float al_hi = __expf(m_hi - mn_hi);
        m_lo = mn_lo; m_hi = mn_hi;

        // ---- p = exp(scale*s - m) -> packed A fragments (registers only) ----
        unsigned pk[7][4];
        float sm_lo = 0.f, sm_hi = 0.f;
#pragma unroll
        for (int j16 = 0; j16 < 7; j16++) {
#pragma unroll
            for (int h = 0; h < 2; h++) {
                float* svp = sv[2 * j16 + h];
                float p0 = __expf(fmaf(svp[0], scale, -mn_lo));
                float p1 = __expf(fmaf(svp[1], scale, -mn_lo));
                float p2 = __expf(fmaf(svp[2], scale, -mn_hi));
                float p3 = __expf(fmaf(svp[3], scale, -mn_hi));
                sm_lo += p0 + p1; sm_hi += p2 + p3;
                pk[j16][2 * h]     = packh2(p0, p1);
                pk[j16][2 * h + 1] = packh2(p2, p3);
            }
        }
#pragma unroll
        for (int o = 1; o < 4; o <<= 1) {
            sm_lo += __shfl_xor_sync(0xffffffffu, sm_lo, o);
            sm_hi += __shfl_xor_sync(0xffffffffu, sm_hi, o);
        }
        l_lo = l_lo * al_lo + sm_lo;
        l_hi = l_hi * al_hi + sm_hi;
#pragma unroll
        for (int i = 0; i < 6; i++) {
            o_acc[i][0] *= al_lo; o_acc[i][1] *= al_lo;
            o_acc[i][2] *= al_hi; o_acc[i][3] *= al_hi;
        }

        // ---- PV: registers P x smem V, 16m x 48c ----
#pragma unroll
        for (int j16 = 0; j16 < 7; j16++) {
#pragma unroll
            for (int ci = 0; ci < 6; ci++) {
                unsigned bf[2];
                bf[0] = *reinterpret_cast<const unsigned*>(&vts[(ci * 8 + g) * KSTRH + j16 * 16 + 2 * tig]);
                bf[1] = *reinterpret_cast<const unsigned*>(&vts[(ci * 8 + g) * KSTRH + j16 * 16 + 8 + 2 * tig]);
                mma16(o_acc[ci], pk[j16], bf);
            }
        }
        s ^= 1;
    }

    // ---- epilogue ----
    float il_lo = 1.f / l_lo;
    float il_hi = 1.f / l_hi;
    bool ok_lo = (m0 + row_lo) < HWSZ;
    bool ok_hi = (m0 + row_hi) < HWSZ;
#pragma unroll
    for (int ci = 0; ci < 6; ci++) {
        int cc = ci * 8 + 2 * tig;
        if (ok_lo) {
            op[(size_t)cc * HWSZ + m0 + row_lo]       = __float2half_rn(o_acc[ci][0] * il_lo);
            op[(size_t)(cc + 1) * HWSZ + m0 + row_lo] = __float2half_rn(o_acc[ci][1] * il_lo);
        }
        if (ok_hi) {
            op[(size_t)cc * HWSZ + m0 + row_hi]       = __float2half_rn(o_acc[ci][2] * il_hi);
            op[(size_t)(cc + 1) * HWSZ + m0 + row_hi] = __float2half_rn(o_acc[ci][3] * il_hi);
        }
    }
}

// ---------------------------------------------------------------------------
extern "C" void kernel_launch(void* const* d_in, const int* in_sizes, int n_in,
                              void* d_out, int out_size)
{
    const float* x   = (const float*)d_in[0];
    const float* Wq  = (const float*)d_in[1];
    const float* bq  = (const float*)d_in[2];
    const float* Wk  = (const float*)d_in[3];
    const float* bk  = (const float*)d_in[4];
    const float* Wv  = (const float*)d_in[5];
    const float* bv  = (const float*)d_in[6];
    const float* Wo  = (const float*)d_in[7];
    const float* bo  = (const float*)d_in[8];
    const float* dww = (const float*)d_in[9];
    const float* dwb = (const float*)d_in[10];
    const float* lng = (const float*)d_in[11];
    const float* lnb = (const float*)d_in[12];
    const float* pww = (const float*)d_in[13];
    float* out = (float*)d_out;

    float *pos;
    __half *qh, *xh, *atth, *xsh, *kh, *vh, *wh;
    cudaGetSymbolAddress((void**)&pos,  g_pos);
    cudaGetSymbolAddress((void**)&qh,   g_qh);
    cudaGetSymbolAddress((void**)&xh,   g_xh);
    cudaGetSymbolAddress((void**)&atth, g_atth);
    cudaGetSymbolAddress((void**)&xsh,  g_xsh);
    cudaGetSymbolAddress((void**)&kh,   g_kh);
    cudaGetSymbolAddress((void**)&vh,   g_vh);
    cudaGetSymbolAddress((void**)&wh,   g_wh);

    __half* whq = wh;
    __half* whk = wh + NCH * NCH;
    __half* whv = wh + 2 * NCH * NCH;
    __half* who = wh + 3 * NCH * NCH;

    cudaFuncSetAttribute(attention_h, cudaFuncAttributeMaxDynamicSharedMemorySize, F_SMEM);

    // 0) fp16 conversions
    to_half4<<<(YSZ / 4 + 255) / 256, 256>>>(x, xh, YSZ / 4);
    w_to_half<<<(4 * WN4) / 256, 256>>>(Wq, Wk, Wv, Wo, wh);

    dim3 gbig((HWSZ + 127) / 128, 3, BATCH);   // 25 x 3 x 8
    dim3 gkv((NKV + 127) / 128, 6, BATCH);     // 7 x 6 x 8 (k + v fused)

    // 1) q = Wq x + bq  (fp16 out — consumed by offset_net + attention)
    gemm_h<true><<<gbig, 256>>>(whq, nullptr, bq, nullptr, xh, qh, nullptr, NCH, HWSZ);
    // 2) offset net -> pos (fp16 q input)
    offset_net<<<BATCH * NG * HK, 256>>>(qh, dww, dwb, lng, lnb, pww,
                                         pos, out + YSZ, out + YSZ + PSZ);
    // 3) grid sample -> xs (fp16)
    grid_sample_k<<<dim3((GC * NKV) / 256, BATCH * NG), 256>>>(x, pos, xsh);
    // 4) k and v in one launch (fp16 out)
    gemm_h<true><<<gkv, 256>>>(whk, whv, bk, bv, xsh, kh, vh, NCH, NKV);
    // 5) flash attention -> atth (fp16)
    attention_h<<<dim3((HWSZ + FTM - 1) / FTM, BATCH * NH), 256, F_SMEM>>>(qh, kh, vh, atth);
    // 6) y = Wo att + bo
    gemm_h<false><<<gbig, 256>>>(who, nullptr, bo, nullptr, atth, out, nullptr, NCH, HWSZ);
}

// round 12
// speedup vs baseline: 13.1486x; 1.0845x over previous
#include <cuda_runtime.h>
#include <cuda_fp16.h>
#include <math.h>

// Problem constants
#define BATCH 8
#define NCH   384
#define HH    56
#define WW    56
#define HWSZ  3136      // 56*56
#define NKV   784       // 28*28
#define HK    28
#define NG    4
#define GC    96
#define NH    8
#define HC    48

#define YSZ   (BATCH*NCH*HWSZ)     // 9633792
#define PSZ   (BATCH*NG*NKV*2)     // 50176

// Scratch (allocation-free rule: __device__ globals)
static __device__ __half g_qh  [BATCH*NCH*HWSZ];
static __device__ __half g_xh  [BATCH*NCH*HWSZ];
static __device__ __half g_atth[BATCH*NCH*HWSZ];
static __device__ __half g_xsh [BATCH*NCH*NKV];
static __device__ __half g_kh  [BATCH*NCH*NKV];
static __device__ __half g_vh  [BATCH*NCH*NKV];
static __device__ __half g_wh  [4*NCH*NCH];     // Wq, Wk, Wv, Wo fp16
static __device__ float  g_pos [BATCH*NG*NKV*2];

// ---------------------------------------------------------------------------
// mma / ldmatrix / cp.async helpers
// ---------------------------------------------------------------------------
__device__ __forceinline__ void mma16(float* d, const unsigned* a, const unsigned* b) {
    asm("mma.sync.aligned.m16n8k16.row.col.f32.f16.f16.f32 "
        "{%0,%1,%2,%3}, {%4,%5,%6,%7}, {%8,%9}, {%0,%1,%2,%3};"
        : "+f"(d[0]), "+f"(d[1]), "+f"(d[2]), "+f"(d[3])
        : "r"(a[0]), "r"(a[1]), "r"(a[2]), "r"(a[3]), "r"(b[0]), "r"(b[1]));
}
__device__ __forceinline__ void ldsm4(unsigned* r, const __half* p) {
    unsigned addr = (unsigned)__cvta_generic_to_shared(p);
    asm volatile("ldmatrix.sync.aligned.m8n8.x4.shared.b16 {%0,%1,%2,%3}, [%4];"
                 : "=r"(r[0]), "=r"(r[1]), "=r"(r[2]), "=r"(r[3]) : "r"(addr));
}
__device__ __forceinline__ void ldsm4t(unsigned* r, const __half* p) {
    unsigned addr = (unsigned)__cvta_generic_to_shared(p);
    asm volatile("ldmatrix.sync.aligned.m8n8.x4.trans.shared.b16 {%0,%1,%2,%3}, [%4];"
                 : "=r"(r[0]), "=r"(r[1]), "=r"(r[2]), "=r"(r[3]) : "r"(addr));
}
__device__ __forceinline__ void cpa16(const __half* dst, const __half* src, bool pred) {
    unsigned d = (unsigned)__cvta_generic_to_shared(dst);
    int sz = pred ? 16 : 0;
    asm volatile("cp.async.cg.shared.global [%0], [%1], 16, %2;"
                 :: "r"(d), "l"(src), "r"(sz));
}
#define CPA_COMMIT() asm volatile("cp.async.commit_group;")
#define CPA_WAIT1()  asm volatile("cp.async.wait_group 1;")
#define CPA_WAIT0()  asm volatile("cp.async.wait_group 0;")

__device__ __forceinline__ unsigned packh2(float a, float b) {
    half2 h = __floats2half2_rn(a, b);
    return *reinterpret_cast<unsigned*>(&h);
}
__device__ __forceinline__ float ex2(float x) {
    float r; asm("ex2.approx.ftz.f32 %0, %1;" : "=f"(r) : "f"(x)); return r;
}

// ---------------------------------------------------------------------------
// fp32 -> fp16 conversions
// ---------------------------------------------------------------------------
__global__ __launch_bounds__(256)
void to_half4(const float* __restrict__ src, __half* __restrict__ dst, int n4)
{
    int i = blockIdx.x * 256 + threadIdx.x;
    if (i < n4) {
        float4 f = reinterpret_cast<const float4*>(src)[i];
        reinterpret_cast<half2*>(dst)[2*i]   = __floats2half2_rn(f.x, f.y);
        reinterpret_cast<half2*>(dst)[2*i+1] = __floats2half2_rn(f.z, f.w);
    }
}

#define WN4 (NCH*NCH/4)   // 36864
__global__ __launch_bounds__(256)
void w_to_half(const float* __restrict__ Wq, const float* __restrict__ Wk,
               const float* __restrict__ Wv, const float* __restrict__ Wo,
               __half* __restrict__ wh)
{
    int i = blockIdx.x * 256 + threadIdx.x;      // < 4*WN4
    int m = i / WN4, r = i - m * WN4;
    const float* src = (m == 0) ? Wq : (m == 1) ? Wk : (m == 2) ? Wv : Wo;
    float4 f = reinterpret_cast<const float4*>(src)[r];
    half2* dst = reinterpret_cast<half2*>(wh + (size_t)m * NCH * NCH);
    dst[2*r]   = __floats2half2_rn(f.x, f.y);
    dst[2*r+1] = __floats2half2_rn(f.z, f.w);
}

// ---------------------------------------------------------------------------
// fp16 GEMM (unchanged)
// ---------------------------------------------------------------------------
#define ASTRH 40
#define BSTRH 136

template<bool OUTH>
__global__ __launch_bounds__(256)
void gemm_h(const __half* __restrict__ A0, const __half* __restrict__ A1,
            const float* __restrict__ bias0, const float* __restrict__ bias1,
            const __half* __restrict__ Bsrc,
            void* __restrict__ C0, void* __restrict__ C1,
            int K, int N)
{
    __shared__ __half As[2][128 * ASTRH];
    __shared__ __half Bs[2][32 * BSTRH];

    bool sel = (A1 != nullptr) && (blockIdx.y >= 3);
    const __half* A    = sel ? A1 : A0;
    const float*  bias = sel ? bias1 : bias0;
    void*         Cv   = sel ? C1 : C0;

    const __half* Bp = Bsrc + (size_t)blockIdx.z * K * N;
    int m0 = (blockIdx.y % 3) * 128, n0 = blockIdx.x * 128;
    int tid = threadIdx.x;
    int wid = tid >> 5, lane = tid & 31;
    int g = lane >> 2, tig = lane & 3;
    int wm = (wid & 1) * 64;
    int wn = (wid >> 1) * 32;
    int l16 = lane & 15, lh = (lane >> 4) * 8;

    int ar = tid >> 1, ac = (tid & 1) * 16;
    int br = tid >> 3, bc = (tid & 7) * 16;

    float acc[4][4][4];
#pragma unroll
    for (int i = 0; i < 4; i++)
#pragma unroll
        for (int j = 0; j < 4; j++)
#pragma unroll
            for (int r = 0; r < 4; r++) acc[i][j][r] = 0.f;

    auto issue = [&](int s, int k0) {
        const __half* asrc = A + (size_t)(m0 + ar) * K + k0 + ac;
        cpa16(&As[s][ar * ASTRH + ac], asrc, true);
        cpa16(&As[s][ar * ASTRH + ac + 8], asrc + 8, true);
        const __half* bsrc = Bp + (size_t)(k0 + br) * N + n0 + bc;
        cpa16(&Bs[s][br * BSTRH + bc], bsrc, n0 + bc < N);
        cpa16(&Bs[s][br * BSTRH + bc + 8], bsrc + 8, n0 + bc + 8 < N);
    };

    issue(0, 0);
    CPA_COMMIT();

    int s = 0;
    for (int k0 = 0; k0 < K; k0 += 32, s ^= 1) {
        if (k0 + 32 < K) issue(s ^ 1, k0 + 32);
        CPA_COMMIT();
        CPA_WAIT1();
        __syncthreads();
#pragma unroll
        for (int kk = 0; kk < 32; kk += 16) {
            unsigned af[4][4], bf[4][2];
#pragma unroll
            for (int mf = 0; mf < 4; mf++)
                ldsm4(af[mf], &As[s][(wm + mf * 16 + l16) * ASTRH + kk + lh]);
#pragma unroll
            for (int nf = 0; nf < 4; nf += 2) {
                unsigned t4[4];
                ldsm4t(t4, &Bs[s][(kk + l16) * BSTRH + wn + nf * 8 + lh]);
                bf[nf][0] = t4[0]; bf[nf][1] = t4[1];
                bf[nf+1][0] = t4[2]; bf[nf+1][1] = t4[3];
            }
#pragma unroll
            for (int mf = 0; mf < 4; mf++)
#pragma unroll
                for (int nf = 0; nf < 4; nf++)
                    mma16(acc[mf][nf], af[mf], bf[nf]);
        }
        __syncthreads();
    }

#pragma unroll
    for (int mf = 0; mf < 4; mf++) {
        int r0 = m0 + wm + mf * 16 + g;
        int r1 = r0 + 8;
        float bv0 = bias[r0], bv1 = bias[r1];
#pragma unroll
        for (int nf = 0; nf < 4; nf++) {
            int cn = n0 + wn + nf * 8 + 2 * tig;
            if (cn < N) {
                if (OUTH) {
                    __half* Ch = (__half*)Cv + (size_t)blockIdx.z * 384 * N;
                    *reinterpret_cast<half2*>(&Ch[(size_t)r0 * N + cn]) =
                        __floats2half2_rn(acc[mf][nf][0] + bv0, acc[mf][nf][1] + bv0);
                    *reinterpret_cast<half2*>(&Ch[(size_t)r1 * N + cn]) =
                        __floats2half2_rn(acc[mf][nf][2] + bv1, acc[mf][nf][3] + bv1);
                } else {
                    float* Cf = (float*)Cv + (size_t)blockIdx.z * 384 * N;
                    *reinterpret_cast<float2*>(&Cf[(size_t)r0 * N + cn]) =
                        make_float2(acc[mf][nf][0] + bv0, acc[mf][nf][1] + bv0);
                    *reinterpret_cast<float2*>(&Cf[(size_t)r1 * N + cn]) =
                        make_float2(acc[mf][nf][2] + bv1, acc[mf][nf][3] + bv1);
                }
            }
        }
    }
}

// ---------------------------------------------------------------------------
// Offset network v5: branch-free 9-tap conv (clamped addresses, zeroed
// weights — only i==0 / j==0 clip), then warp-shuffle LN/GELU/1x1.
// ---------------------------------------------------------------------------
#define HSTR 100

__device__ __forceinline__ float wsum(float v) {
#pragma unroll
    for (int o = 16; o > 0; o >>= 1) v += __shfl_xor_sync(0xffffffffu, v, o);
    return v;
}

__global__ __launch_bounds__(256)
void offset_net(const __half* __restrict__ q,
                const float* __restrict__ dw_w, const float* __restrict__ dw_b,
                const float* __restrict__ ln_g, const float* __restrict__ ln_b,
                const float* __restrict__ pw_w,
                float* __restrict__ pos, float* __restrict__ pos_out,
                float* __restrict__ ref_out)
{
    __shared__ float sh[HK * HSTR];     // [j][c]

    int blk = blockIdx.x;               // bg*28 + i
    int bg = blk / HK;
    int i  = blk - bg * HK;
    int b = bg >> 2, gg = bg & 3;
    int tid = threadIdx.x;

    // ---- Phase A: branch-free depthwise 3x3 stride-2 conv ----
    int ya = (i == 0) ? 0 : (2 * i - 1);    // clamped (weight zeroed when i==0)
    int yb = 2 * i, yc = 2 * i + 1;         // always in [0,55]
    for (int it = tid; it < GC * HK; it += 256) {
        int c = it / HK, j = it - c * HK;
        const __half* qc = q + ((size_t)(b * NCH + gg * GC + c)) * HWSZ;
        const float* w = dw_w + c * 9;
        float w0 = w[0], w1 = w[1], w2 = w[2];
        float w3 = w[3], w4 = w[4], w5 = w[5];
        float w6 = w[6], w7 = w[7], w8 = w[8];
        if (i == 0) { w0 = 0.f; w1 = 0.f; w2 = 0.f; }
        if (j == 0) { w0 = 0.f; w3 = 0.f; w6 = 0.f; }
        int xa = (j == 0) ? 0 : (2 * j - 1);
        int xb = 2 * j, xc = 2 * j + 1;
        const __half* r0 = qc + ya * WW;
        const __half* r1 = qc + yb * WW;
        const __half* r2 = qc + yc * WW;
        float acc = dw_b[c];
        acc = fmaf(w0, __half2float(r0[xa]), acc);
        acc = fmaf(w1, __half2float(r0[xb]), acc);
        acc = fmaf(w2, __half2float(r0[xc]), acc);
        acc = fmaf(w3, __half2float(r1[xa]), acc);
        acc = fmaf(w4, __half2float(r1[xb]), acc);
        acc = fmaf(w5, __half2float(r1[xc]), acc);
        acc = fmaf(w6, __half2float(r2[xa]), acc);
        acc = fmaf(w7, __half2float(r2[xb]), acc);
        acc = fmaf(w8, __half2float(r2[xc]), acc);
        sh[j * HSTR + c] = acc;
    }
    __syncthreads();

    // ---- Phase B: per-position LN + GELU + 1x1 + tanh (warp shuffles) ----
    int warp = tid >> 5, lane = tid & 31;
    for (int j = warp; j < HK; j += 8) {
        const float* hr = &sh[j * HSTR];
        float h0 = hr[lane * 3], h1 = hr[lane * 3 + 1], h2 = hr[lane * 3 + 2];
        float mu = wsum(h0 + h1 + h2) * (1.f / GC);
        float d0 = h0 - mu, d1 = h1 - mu, d2 = h2 - mu;
        float var = wsum(d0 * d0 + d1 * d1 + d2 * d2) * (1.f / GC);
        float inv = rsqrtf(var + 1e-5f);

        float py_p = 0.f, px_p = 0.f;
        float hn[3] = {d0 * inv, d1 * inv, d2 * inv};
#pragma unroll
        for (int e = 0; e < 3; e++) {
            int c = lane * 3 + e;
            float v = hn[e] * ln_g[c] + ln_b[c];
            v = 0.5f * v * (1.f + erff(v * 0.70710678118654752f));
            py_p += pw_w[c] * v;
            px_p += pw_w[GC + c] * v;
        }
        float offy = wsum(py_p);
        float offx = wsum(px_p);

        if (lane == 0) {
            float ry = (0.5f + (float)i) * (1.f / 27.f) * 2.f - 1.f;
            float rx = (0.5f + (float)j) * (1.f / 27.f) * 2.f - 1.f;
            float py = tanhf(offy) * (1.f / 27.f) + ry;
            float px = tanhf(offx) * (1.f / 27.f) + rx;
            size_t o = ((size_t)bg * NKV + i * HK + j) * 2;
            pos[o] = py;     pos[o + 1] = px;
            pos_out[o] = py; pos_out[o + 1] = px;
            ref_out[o] = ry; ref_out[o + 1] = rx;
        }
    }
}

// ---------------------------------------------------------------------------
// Bilinear grid sample from fp16 x -> fp16 xs
// ---------------------------------------------------------------------------
__global__ __launch_bounds__(256)
void grid_sample_k(const __half* __restrict__ x, const float* __restrict__ pos,
                   __half* __restrict__ xs)
{
    int bg = blockIdx.y;
    int b = bg >> 2, g = bg & 3;
    int idx = blockIdx.x * 256 + threadIdx.x;
    int c = idx / NKV, p = idx - c * NKV;

    float py = pos[((size_t)bg * NKV + p) * 2];
    float px = pos[((size_t)bg * NKV + p) * 2 + 1];
    float gx = (px + 1.f) * 0.5f * (WW - 1);
    float gy = (py + 1.f) * 0.5f * (HH - 1);
    float x0f = floorf(gx), y0f = floorf(gy);
    int x0 = (int)x0f, y0 = (int)y0f;
    float wx1 = gx - x0f, wx0 = 1.f - wx1;
    float wy1 = gy - y0f, wy0 = 1.f - wy1;

    const __half* img = x + ((size_t)(b * NCH + g * GC + c)) * HWSZ;

    float v00 = 0.f, v01 = 0.f, v10 = 0.f, v11 = 0.f;
    bool xv0 = (x0 >= 0) && (x0 < WW);
    bool xv1 = (x0 + 1 >= 0) && (x0 + 1 < WW);
    bool yv0 = (y0 >= 0) && (y0 < HH);
    bool yv1 = (y0 + 1 >= 0) && (y0 + 1 < HH);
    if (xv0 && yv0) v00 = __half2float(img[y0 * WW + x0]);
    if (xv1 && yv0) v01 = __half2float(img[y0 * WW + x0 + 1]);
    if (xv0 && yv1) v10 = __half2float(img[(y0 + 1) * WW + x0]);
    if (xv1 && yv1) v11 = __half2float(img[(y0 + 1) * WW + x0 + 1]);

    float acc = v00 * wx0 * wy0 + v01 * wx1 * wy0 + v10 * wx0 * wy1 + v11 * wx1 * wy1;
    xs[((size_t)(b * NCH + g * GC + c)) * NKV + p] = __float2half_rn(acc);
}

// ---------------------------------------------------------------------------
// Flash attention v4: register P, log2-domain softmax (ex2.approx).
// ---------------------------------------------------------------------------
#define FTM 128
#define FTN 112
#define QSTRH 56     // 48 + 8 pad
#define KSTRH 120    // 112 + 8 pad
#define F_SMEM (30208 * 2)

__global__ __launch_bounds__(256)
void attention_h(const __half* __restrict__ q, const __half* __restrict__ k,
                 const __half* __restrict__ v, __half* __restrict__ out)
{
    extern __shared__ char smraw[];
    __half* qs = (__half*)smraw;                    // [m][c]    128 x QSTRH
    __half* kt = qs + FTM * QSTRH;                  // [2][c][n] 48 x KSTRH
    __half* vt = kt + 2 * HC * KSTRH;

    int head = blockIdx.y;
    int b = head >> 3, hh = head & 7;
    const __half* qp = q + ((size_t)(b * NCH + hh * HC)) * HWSZ;
    const __half* kp = k + ((size_t)(b * NCH + hh * HC)) * NKV;
    const __half* vp = v + ((size_t)(b * NCH + hh * HC)) * NKV;
    __half*       op = out + ((size_t)(b * NCH + hh * HC)) * HWSZ;
    int m0 = blockIdx.x * FTM;
    int tid = threadIdx.x;
    int wid = tid >> 5, lane = tid & 31;
    int g = lane >> 2, tig = lane & 3;
    int l16 = lane & 15, lh = (lane >> 4) * 8;
    int wm = wid * 16;
    // scale * log2(e): softmax kept in log2 domain
    const float scale2 = 0.14433756729740643f * 1.4426950408889634f;

    int row_lo = wm + g, row_hi = wm + g + 8;

    // stage Q (fp16 direct), guarded for tail block
    for (int idx = tid; idx < HC * FTM; idx += 256) {
        int c = idx >> 7, m = idx & 127;
        qs[m * QSTRH + c] = (m0 + m < HWSZ) ? qp[(size_t)c * HWSZ + m0 + m] : __half(0.f);
    }

    auto stage_kv = [&](int s, int n0) {
        __half* kd = kt + s * HC * KSTRH;
        __half* vd = vt + s * HC * KSTRH;
        for (int it = tid; it < 1344; it += 256) {
            int tsel = it / 672;
            int rid = it - tsel * 672;
            int c = rid / 14, gc = (rid - c * 14) * 8;
            const __half* src = (tsel ? vp : kp) + (size_t)c * NKV + n0 + gc;
            cpa16((tsel ? vd : kd) + c * KSTRH + gc, src, true);
        }
    };

    stage_kv(0, 0);
    CPA_COMMIT();

    float m_lo = -1e30f, m_hi = -1e30f, l_lo = 0.f, l_hi = 0.f;
    float o_acc[6][4];
#pragma unroll
    for (int i = 0; i < 6; i++)
#pragma unroll
        for (int r = 0; r < 4; r++) o_acc[i][r] = 0.f;

    int s = 0;
    for (int t = 0; t < 7; t++) {
        CPA_WAIT0();
        __syncthreads();
        const __half* kts = kt + s * HC * KSTRH;
        const __half* vts = vt + s * HC * KSTRH;

        // ---- S = Q^T K : warp tile 16 x 112 ----
        float sv[14][4];
#pragma unroll
        for (int j = 0; j < 14; j++)
#pragma unroll
            for (int r = 0; r < 4; r++) sv[j][r] = 0.f;
#pragma unroll
        for (int kk = 0; kk < HC; kk += 16) {
            unsigned af[4];
            ldsm4(af, &qs[(wm + l16) * QSTRH + kk + lh]);
#pragma unroll
            for (int j16 = 0; j16 < 7; j16++) {
                unsigned t4[4];
                ldsm4t(t4, &kts[(kk + l16) * KSTRH + j16 * 16 + lh]);
                mma16(sv[2 * j16],     af, t4);
                mma16(sv[2 * j16 + 1], af, t4 + 2);
            }
        }

        // prefetch next K/V tile
        if (t < 6) stage_kv(s ^ 1, (t + 1) * FTN);
        CPA_COMMIT();

        // ---- row max ----
        float mx_lo = -1e30f, mx_hi = -1e30f;
#pragma unroll
        for (int j = 0; j < 14; j++) {
            mx_lo = fmaxf(mx_lo, fmaxf(sv[j][0], sv[j][1]));
            mx_hi = fmaxf(mx_hi, fmaxf(sv[j][2], sv[j][3]));
        }
#pragma unroll
        for (int o = 1; o < 4; o <<= 1) {
            mx_lo = fmaxf(mx_lo, __shfl_xor_sync(0xffffffffu, mx_lo, o));
            mx_hi = fmaxf(mx_hi, __shfl_xor_sync(0xffffffffu, mx_hi, o));
        }
        float mn_lo = fmaxf(m_lo, mx_lo * scale2);   // log2 units
        float mn_hi = fmaxf(m_hi, mx_hi * scale2);
        float al_lo = ex2(m_lo - mn_lo);
        float al_hi = ex2(m_hi - mn_hi);
        m_lo = mn_lo; m_hi = mn_hi;

        // ---- p = 2^(scale2*s - m) -> packed A fragments ----
        unsigned pk[7][4];
        float sm_lo = 0.f, sm_hi = 0.f;
#pragma unroll
        for (int j16 = 0; j16 < 7; j16++) {
#pragma unroll
            for (int h = 0; h < 2; h++) {
                float* svp = sv[2 * j16 + h];
                float p0 = ex2(fmaf(svp[0], scale2, -mn_lo));
                float p1 = ex2(fmaf(svp[1], scale2, -mn_lo));
                float p2 = ex2(fmaf(svp[2], scale2, -mn_hi));
                float p3 = ex2(fmaf(svp[3], scale2, -mn_hi));
                sm_lo += p0 + p1; sm_hi += p2 + p3;
                pk[j16][2 * h]     = packh2(p0, p1);
                pk[j16][2 * h + 1] = packh2(p2, p3);
            }
        }
#pragma unroll
        for (int o = 1; o < 4; o <<= 1) {
            sm_lo += __shfl_xor_sync(0xffffffffu, sm_lo, o);
            sm_hi += __shfl_xor_sync(0xffffffffu, sm_hi, o);
        }
        l_lo = l_lo * al_lo + sm_lo;
        l_hi = l_hi * al_hi + sm_hi;
#pragma unroll
        for (int i = 0; i < 6; i++) {
            o_acc[i][0] *= al_lo; o_acc[i][1] *= al_lo;
            o_acc[i][2] *= al_hi; o_acc[i][3] *= al_hi;
        }

        // ---- PV: registers P x smem V, 16m x 48c ----
#pragma unroll
        for (int j16 = 0; j16 < 7; j16++) {
#pragma unroll
            for (int ci = 0; ci < 6; ci++) {
                unsigned bf[2];
                bf[0] = *reinterpret_cast<const unsigned*>(&vts[(ci * 8 + g) * KSTRH + j16 * 16 + 2 * tig]);
                bf[1] = *reinterpret_cast<const unsigned*>(&vts[(ci * 8 + g) * KSTRH + j16 * 16 + 8 + 2 * tig]);
                mma16(o_acc[ci], pk[j16], bf);
            }
        }
        s ^= 1;
    }

    // ---- epilogue ----
    float il_lo = 1.f / l_lo;
    float il_hi = 1.f / l_hi;
    bool ok_lo = (m0 + row_lo) < HWSZ;
    bool ok_hi = (m0 + row_hi) < HWSZ;
#pragma unroll
    for (int ci = 0; ci < 6; ci++) {
        int cc = ci * 8 + 2 * tig;
        if (ok_lo) {
            op[(size_t)cc * HWSZ + m0 + row_lo]       = __float2half_rn(o_acc[ci][0] * il_lo);
            op[(size_t)(cc + 1) * HWSZ + m0 + row_lo] = __float2half_rn(o_acc[ci][1] * il_lo);
        }
        if (ok_hi) {
            op[(size_t)cc * HWSZ + m0 + row_hi]       = __float2half_rn(o_acc[ci][2] * il_hi);
            op[(size_t)(cc + 1) * HWSZ + m0 + row_hi] = __float2half_rn(o_acc[ci][3] * il_hi);
        }
    }
}

// ---------------------------------------------------------------------------
extern "C" void kernel_launch(void* const* d_in, const int* in_sizes, int n_in,
                              void* d_out, int out_size)
{
    const float* x   = (const float*)d_in[0];
    const float* Wq  = (const float*)d_in[1];
    const float* bq  = (const float*)d_in[2];
    const float* Wk  = (const float*)d_in[3];
    const float* bk  = (const float*)d_in[4];
    const float* Wv  = (const float*)d_in[5];
    const float* bv  = (const float*)d_in[6];
    const float* Wo  = (const float*)d_in[7];
    const float* bo  = (const float*)d_in[8];
    const float* dww = (const float*)d_in[9];
    const float* dwb = (const float*)d_in[10];
    const float* lng = (const float*)d_in[11];
    const float* lnb = (const float*)d_in[12];
    const float* pww = (const float*)d_in[13];
    float* out = (float*)d_out;

    float *pos;
    __half *qh, *xh, *atth, *xsh, *kh, *vh, *wh;
    cudaGetSymbolAddress((void**)&pos,  g_pos);
    cudaGetSymbolAddress((void**)&qh,   g_qh);
    cudaGetSymbolAddress((void**)&xh,   g_xh);
    cudaGetSymbolAddress((void**)&atth, g_atth);
    cudaGetSymbolAddress((void**)&xsh,  g_xsh);
    cudaGetSymbolAddress((void**)&kh,   g_kh);
    cudaGetSymbolAddress((void**)&vh,   g_vh);
    cudaGetSymbolAddress((void**)&wh,   g_wh);

    __half* whq = wh;
    __half* whk = wh + NCH * NCH;
    __half* whv = wh + 2 * NCH * NCH;
    __half* who = wh + 3 * NCH * NCH;

    cudaFuncSetAttribute(attention_h, cudaFuncAttributeMaxDynamicSharedMemorySize, F_SMEM);

    // 0) fp16 conversions
    to_half4<<<(YSZ / 4 + 255) / 256, 256>>>(x, xh, YSZ / 4);
    w_to_half<<<(4 * WN4) / 256, 256>>>(Wq, Wk, Wv, Wo, wh);

    dim3 gbig((HWSZ + 127) / 128, 3, BATCH);   // 25 x 3 x 8
    dim3 gkv((NKV + 127) / 128, 6, BATCH);     // 7 x 6 x 8 (k + v fused)

    // 1) q = Wq x + bq  (fp16 out)
    gemm_h<true><<<gbig, 256>>>(whq, nullptr, bq, nullptr, xh, qh, nullptr, NCH, HWSZ);
    // 2) offset net -> pos
    offset_net<<<BATCH * NG * HK, 256>>>(qh, dww, dwb, lng, lnb, pww,
                                         pos, out + YSZ, out + YSZ + PSZ);
    // 3) grid sample (fp16 in/out)
    grid_sample_k<<<dim3((GC * NKV) / 256, BATCH * NG), 256>>>(xh, pos, xsh);
    // 4) k and v in one launch (fp16 out)
    gemm_h<true><<<gkv, 256>>>(whk, whv, bk, bv, xsh, kh, vh, NCH, NKV);
    // 5) flash attention -> atth (fp16)
    attention_h<<<dim3((HWSZ + FTM - 1) / FTM, BATCH * NH), 256, F_SMEM>>>(qh, kh, vh, atth);
    // 6) y = Wo att + bo
    gemm_h<false><<<gbig, 256>>>(who, nullptr, bo, nullptr, atth, out, nullptr, NCH, HWSZ);
}